// round 1
// baseline (speedup 1.0000x reference)
#include <cuda_runtime.h>

#define B_   128
#define C_   512
#define H_   7
#define W_   34
#define PIX  238            // 7*34
#define NCH  529
#define KTOT (NCH*PIX)      // 125902
#define KSPLIT 32
#define KSP  3936           // per-split K (multiple of 16, 32*3936 >= KTOT)

// ---------------- scratch (device globals; no allocations allowed) ----------
__device__ float g_X[B_ * NCH * PIX];        // dense-concat activation buffer (64.5 MB)
__device__ float g_part[KSPLIT * B_ * 512];  // fc1 K-split partials (8.4 MB)
__device__ float g_fc1[B_ * 512];
__device__ float g_h[2 * B_ * 256];          // l1 / r1 outputs
__device__ float g_ang[2 * B_];

typedef unsigned long long ull;

__device__ __forceinline__ float leaky(float x) { return x >= 0.f ? x : 0.1f * x; }

__device__ __forceinline__ ull fpack(float lo, float hi) {
    ull r; asm("mov.b64 %0, {%1, %2};" : "=l"(r) : "f"(lo), "f"(hi)); return r;
}
__device__ __forceinline__ ull fdup(float v) { return fpack(v, v); }
__device__ __forceinline__ void funpack(ull p, float& lo, float& hi) {
    asm("mov.b64 {%0, %1}, %2;" : "=f"(lo), "=f"(hi) : "l"(p));
}
// packed dual fp32 FMA: d = a*b + d (elementwise on 2 lanes)
__device__ __forceinline__ void fma2(ull& d, ull a, ull b) {
    asm("fma.rn.f32x2 %0, %1, %2, %3;" : "=l"(d) : "l"(a), "l"(b), "l"(d));
}

// ============================================================================
// corr81 + leaky -> X channels [448, 529)
// block = one batch image; threads (x-group 9, dy 9, y 7) = 567 active of 576
// ============================================================================
__global__ __launch_bounds__(576) void corr_k(const float* __restrict__ L,
                                              const float* __restrict__ R) {
    int b = blockIdx.x;
    __shared__ __align__(16) float Ls[8][7][36];   // cols 34,35 unused
    __shared__ __align__(16) float Rs[8][7][44];   // x padded by 4 each side (+2 slack)
    int t = threadIdx.x;
    int g  = t % 9;
    int dy = (t / 9) % 9;
    int y  = t / 81;          // y < 7 valid
    int x0 = g * 4;

    // zero smem once: Rs pads persist, Ls tail cols persist as zero
    for (int i = t; i < 8 * 7 * 44; i += 576) ((float*)Rs)[i] = 0.f;
    for (int i = t; i < 8 * 7 * 36; i += 576) ((float*)Ls)[i] = 0.f;
    __syncthreads();

    float acc[9][4];
#pragma unroll
    for (int dx = 0; dx < 9; dx++)
#pragma unroll
        for (int i = 0; i < 4; i++) acc[dx][i] = 0.f;

    int ry = y + dy - 4;
    bool valid = (y < 7) && (ry >= 0) && (ry < 7);
    const float* Lb = L + (size_t)b * C_ * PIX;
    const float* Rb = R + (size_t)b * C_ * PIX;

    for (int c0 = 0; c0 < C_; c0 += 8) {
        for (int i = t; i < 8 * PIX; i += 576) {
            int c = i / PIX, p = i % PIX;
            float lv = Lb[(size_t)(c0 + c) * PIX + p];
            float rv = Rb[(size_t)(c0 + c) * PIX + p];
            Ls[c][p / 34][p % 34]       = lv;
            Rs[c][p / 34][(p % 34) + 4] = rv;
        }
        __syncthreads();
        if (valid) {
#pragma unroll
            for (int c = 0; c < 8; c++) {
                float4 l4 = *(const float4*)&Ls[c][y][x0];
                float4 r0 = *(const float4*)&Rs[c][ry][x0];
                float4 r1 = *(const float4*)&Rs[c][ry][x0 + 4];
                float4 r2 = *(const float4*)&Rs[c][ry][x0 + 8];
                float lv[4]  = {l4.x, l4.y, l4.z, l4.w};
                float rv[12] = {r0.x, r0.y, r0.z, r0.w,
                                r1.x, r1.y, r1.z, r1.w,
                                r2.x, r2.y, r2.z, r2.w};
#pragma unroll
                for (int dx = 0; dx < 9; dx++)
#pragma unroll
                    for (int i = 0; i < 4; i++)
                        acc[dx][i] = fmaf(lv[i], rv[i + dx], acc[dx][i]);
            }
        }
        __syncthreads();
    }

    if (y < 7) {
#pragma unroll
        for (int dx = 0; dx < 9; dx++) {
            int ch = 448 + dy * 9 + dx;
            float* op = &g_X[((size_t)(b * NCH + ch) * 7 + y) * 34];
#pragma unroll
            for (int i = 0; i < 4; i++) {
                int x = x0 + i;
                if (x < 34) op[x] = leaky(acc[dx][i] * (1.f / 512.f));
            }
        }
    }
}

// ============================================================================
// 3x3 SAME conv + bias + leaky, dense-concat layout inside g_X
// grid (B, OC/32); block 256: thread = (pos-group pg<63 covering 4 x, og -> 8 oc)
// ============================================================================
__global__ __launch_bounds__(256, 2) void conv_k(const float* __restrict__ Wt,
                                                 const float* __restrict__ Bi,
                                                 int IC, int IN_OFF, int OUT_OFF) {
    int b = blockIdx.x;
    int oc_base = blockIdx.y * 32;
    __shared__ __align__(16) float Xs[16][9][36];    // padded input chunk
    __shared__ __align__(16) float Wsm[16][9][34];   // [ic][k][oc] (pad 34: 8B-aligned pairs)
    int t = threadIdx.x;
    int og = t & 3, pg = t >> 2;
    int r = pg / 9, xg = pg % 9, x0 = xg * 4;

    ull acc[4][4] = {};
    const float* Xin = g_X + ((size_t)b * NCH + IN_OFF) * PIX;

    for (int c0 = 0; c0 < IC; c0 += 16) {
        int cc = min(16, IC - c0);
        // input chunk (zero-padded spatially and for c >= cc)
        for (int i = t; i < 16 * 324; i += 256) {
            int c = i / 324, rem = i % 324, ryy = rem / 36, xx = rem % 36;
            float v = 0.f;
            if (c < cc && ryy >= 1 && ryy <= 7 && xx >= 1 && xx <= 34)
                v = Xin[(size_t)(c0 + c) * PIX + (ryy - 1) * 34 + (xx - 1)];
            Xs[c][ryy][xx] = v;
        }
        // weights, coalesced per-oc runs, transposed to [ic][k][oc]
        for (int i = t; i < 32 * 144; i += 256) {
            int oc = i / 144, rem = i % 144, ic = rem / 9, k = rem % 9;
            float v = 0.f;
            if (ic < cc) v = Wt[((size_t)(oc_base + oc) * IC + c0 + ic) * 9 + k];
            Wsm[ic][k][oc] = v;
        }
        __syncthreads();

        if (pg < 63) {
            for (int ic = 0; ic < 16; ic++) {
                ull vd[3][6];
#pragma unroll
                for (int ky = 0; ky < 3; ky++) {
                    float4 a4 = *(const float4*)&Xs[ic][r + ky][x0];
                    float2 b2 = *(const float2*)&Xs[ic][r + ky][x0 + 4];
                    vd[ky][0] = fdup(a4.x); vd[ky][1] = fdup(a4.y);
                    vd[ky][2] = fdup(a4.z); vd[ky][3] = fdup(a4.w);
                    vd[ky][4] = fdup(b2.x); vd[ky][5] = fdup(b2.y);
                }
#pragma unroll
                for (int ocp = 0; ocp < 4; ocp++) {
                    int oci = og * 8 + ocp * 2;
#pragma unroll
                    for (int ky = 0; ky < 3; ky++)
#pragma unroll
                        for (int kx = 0; kx < 3; kx++) {
                            ull w2 = *(const ull*)&Wsm[ic][ky * 3 + kx][oci];
#pragma unroll
                            for (int i = 0; i < 4; i++)
                                fma2(acc[ocp][i], w2, vd[ky][kx + i]);
                        }
                }
            }
        }
        __syncthreads();
    }

    if (pg < 63) {
#pragma unroll
        for (int ocp = 0; ocp < 4; ocp++) {
            int oc = oc_base + og * 8 + ocp * 2;
            float b0v = Bi[oc], b1v = Bi[oc + 1];
            float* op0 = &g_X[((size_t)(b * NCH + OUT_OFF + oc)) * PIX + r * 34];
            float* op1 = op0 + PIX;
#pragma unroll
            for (int i = 0; i < 4; i++) {
                int x = x0 + i;
                if (x < 34) {
                    float lo, hi; funpack(acc[ocp][i], lo, hi);
                    op0[x] = leaky(lo + b0v);
                    op1[x] = leaky(hi + b1v);
                }
            }
        }
    }
}

// ============================================================================
// fc1: (128 x 125902) @ (512 x 125902)^T, 32-way K-split -> partials
// grid (4 ntiles, 32 ksplits); block 256; thread tile 8b x 8n (f32x2 pairs)
// ============================================================================
__global__ __launch_bounds__(256, 2) void fc1_k(const float* __restrict__ Wf) {
    int ntile = blockIdx.x, ks = blockIdx.y;
    int nb = ntile * 128;
    int k0 = ks * KSP, kend = min(KTOT, k0 + KSP);
    __shared__ __align__(16) float Xs[16][132];
    __shared__ __align__(16) float Ws[16][132];
    int t = threadIdx.x, tn = t & 15, tb = t >> 4, b0 = tb * 8, n0 = tn * 8;
    ull acc[8][4] = {};

    for (int kk0 = k0; kk0 < kend; kk0 += 16) {
        int cc = min(16, kend - kk0);
        for (int i = t; i < 2048; i += 256) {
            int k = i & 15, row = i >> 4;
            float xv = 0.f, wv = 0.f;
            if (k < cc) {
                xv = g_X[(size_t)row * KTOT + kk0 + k];
                wv = Wf[(size_t)(nb + row) * KTOT + kk0 + k];
            }
            Xs[k][row] = xv;
            Ws[k][row] = wv;
        }
        __syncthreads();
#pragma unroll 4
        for (int kk = 0; kk < 16; kk++) {
            float4 xa = *(const float4*)&Xs[kk][b0];
            float4 xb = *(const float4*)&Xs[kk][b0 + 4];
            float4 wa = *(const float4*)&Ws[kk][n0];
            float4 wb = *(const float4*)&Ws[kk][n0 + 4];
            ull xd[8] = {fdup(xa.x), fdup(xa.y), fdup(xa.z), fdup(xa.w),
                         fdup(xb.x), fdup(xb.y), fdup(xb.z), fdup(xb.w)};
            ull w2[4] = {fpack(wa.x, wa.y), fpack(wa.z, wa.w),
                         fpack(wb.x, wb.y), fpack(wb.z, wb.w)};
#pragma unroll
            for (int i = 0; i < 8; i++)
#pragma unroll
                for (int j = 0; j < 4; j++)
                    fma2(acc[i][j], w2[j], xd[i]);
        }
        __syncthreads();
    }

#pragma unroll
    for (int i = 0; i < 8; i++)
#pragma unroll
        for (int j = 0; j < 4; j++) {
            float lo, hi; funpack(acc[i][j], lo, hi);
            float* p = &g_part[((size_t)(ks * 128) + b0 + i) * 512 + nb + n0 + 2 * j];
            p[0] = lo; p[1] = hi;
        }
}

__global__ void fc1red_k(const float* __restrict__ bias) {
    int i = blockIdx.x * 256 + threadIdx.x;   // 65536 = 128*512
    float a = 0.f;
#pragma unroll 8
    for (int ks = 0; ks < KSPLIT; ks++) a += g_part[(size_t)ks * 65536 + i];
    g_fc1[i] = leaky(a + bias[i & 511]);
}

// ============================================================================
// l1 / r1: (128 x 512) @ (256 x 512)^T + bias + leaky -> g_h
// grid (2 sides, 2 ntiles); same tiling as fc1, K = 512
// ============================================================================
__global__ __launch_bounds__(256, 2) void l1r1_k(const float* __restrict__ wl1,
                                                 const float* __restrict__ bl1,
                                                 const float* __restrict__ wr1,
                                                 const float* __restrict__ br1) {
    int side = blockIdx.x, ntile = blockIdx.y;
    int nb = ntile * 128;
    const float* Wp = side ? wr1 : wl1;
    const float* Bp = side ? br1 : bl1;
    __shared__ __align__(16) float Xs[16][132];
    __shared__ __align__(16) float Ws[16][132];
    int t = threadIdx.x, tn = t & 15, tb = t >> 4, b0 = tb * 8, n0 = tn * 8;
    ull acc[8][4] = {};

    for (int kk0 = 0; kk0 < 512; kk0 += 16) {
        for (int i = t; i < 2048; i += 256) {
            int k = i & 15, row = i >> 4;
            Xs[k][row] = g_fc1[(size_t)row * 512 + kk0 + k];
            Ws[k][row] = Wp[(size_t)(nb + row) * 512 + kk0 + k];
        }
        __syncthreads();
#pragma unroll 4
        for (int kk = 0; kk < 16; kk++) {
            float4 xa = *(const float4*)&Xs[kk][b0];
            float4 xb = *(const float4*)&Xs[kk][b0 + 4];
            float4 wa = *(const float4*)&Ws[kk][n0];
            float4 wb = *(const float4*)&Ws[kk][n0 + 4];
            ull xd[8] = {fdup(xa.x), fdup(xa.y), fdup(xa.z), fdup(xa.w),
                         fdup(xb.x), fdup(xb.y), fdup(xb.z), fdup(xb.w)};
            ull w2[4] = {fpack(wa.x, wa.y), fpack(wa.z, wa.w),
                         fpack(wb.x, wb.y), fpack(wb.z, wb.w)};
#pragma unroll
            for (int i = 0; i < 8; i++)
#pragma unroll
                for (int j = 0; j < 4; j++)
                    fma2(acc[i][j], w2[j], xd[i]);
        }
        __syncthreads();
    }

#pragma unroll
    for (int i = 0; i < 8; i++)
#pragma unroll
        for (int j = 0; j < 4; j++) {
            float lo, hi; funpack(acc[i][j], lo, hi);
            int n = nb + n0 + 2 * j;
            float* p = &g_h[(size_t)side * (B_ * 256) + (size_t)(b0 + i) * 256 + n];
            p[0] = leaky(lo + Bp[n]);
            p[1] = leaky(hi + Bp[n + 1]);
        }
}

// ============================================================================
// heads: l2/r2 (4x256), normalize, quat_dist per batch
// ============================================================================
__global__ void heads2_k(const float* __restrict__ wl2, const float* __restrict__ bl2,
                         const float* __restrict__ wr2, const float* __restrict__ br2,
                         const float* __restrict__ lt,  const float* __restrict__ rt) {
    int b = blockIdx.x, t = threadIdx.x;
    __shared__ float hl[256], hr[256], q[8];
    hl[t] = g_h[(size_t)b * 256 + t];
    hr[t] = g_h[(size_t)(B_ * 256) + (size_t)b * 256 + t];
    __syncthreads();

    int wrp = t >> 5, lane = t & 31;
    const float* w   = (wrp < 4) ? wl2 : wr2;
    const float* src = (wrp < 4) ? hl : hr;
    int i = wrp & 3;
    float s = 0.f;
    for (int j = lane; j < 256; j += 32) s += w[i * 256 + j] * src[j];
#pragma unroll
    for (int off = 16; off > 0; off >>= 1) s += __shfl_down_sync(0xffffffffu, s, off);
    if (lane == 0) q[wrp] = s + ((wrp < 4) ? bl2[i] : br2[i]);
    __syncthreads();

    if (t == 0) {
#pragma unroll
        for (int side = 0; side < 2; side++) {
            float qw = q[side * 4 + 0], qx = q[side * 4 + 1];
            float qy = q[side * 4 + 2], qz = q[side * 4 + 3];
            float nn = sqrtf(qw * qw + qx * qx + qy * qy + qz * qz);
            nn = fmaxf(nn, 1e-12f);
            qw /= nn; qx /= nn; qy /= nn; qz /= nn;
            const float* tgt = (side == 0 ? lt : rt) + (size_t)b * 4;
            float rw = tgt[0], rx = -tgt[1], ry = -tgt[2], rz = -tgt[3];
            float tw = qw * rw - qx * rx - qy * ry - qz * rz;
            float tx = qw * rx + qx * rw + qy * rz - qz * ry;
            float ty = qw * ry - qx * rz + qy * rw + qz * rx;
            float tz = qw * rz + qx * ry - qy * rx + qz * rw;
            float ang = 2.f * atan2f(sqrtf(tx * tx + ty * ty + tz * tz + 1e-12f), fabsf(tw));
            g_ang[side * B_ + b] = ang;
        }
    }
}

__global__ void mean_k(float* __restrict__ out) {
    __shared__ float sl[128], sr[128];
    int t = threadIdx.x;
    sl[t] = g_ang[t];
    sr[t] = g_ang[128 + t];
    __syncthreads();
    for (int s = 64; s > 0; s >>= 1) {
        if (t < s) { sl[t] += sl[t + s]; sr[t] += sr[t + s]; }
        __syncthreads();
    }
    if (t == 0) { out[0] = sl[0] * (1.f / 128.f); out[1] = sr[0] * (1.f / 128.f); }
}

// ============================================================================
extern "C" void kernel_launch(void* const* d_in, const int* in_sizes, int n_in,
                              void* d_out, int out_size) {
    (void)in_sizes; (void)n_in; (void)out_size;
    const float* left  = (const float*)d_in[0];
    const float* right = (const float*)d_in[1];
    const float* lt    = (const float*)d_in[2];
    const float* rt    = (const float*)d_in[3];
    const float* w6[5] = {(const float*)d_in[4],  (const float*)d_in[6],
                          (const float*)d_in[8],  (const float*)d_in[10],
                          (const float*)d_in[12]};
    const float* b6[5] = {(const float*)d_in[5],  (const float*)d_in[7],
                          (const float*)d_in[9],  (const float*)d_in[11],
                          (const float*)d_in[13]};
    const float* wfc1 = (const float*)d_in[14];
    const float* bfc1 = (const float*)d_in[15];
    const float* wl1  = (const float*)d_in[16];
    const float* bl1  = (const float*)d_in[17];
    const float* wr1  = (const float*)d_in[18];
    const float* br1  = (const float*)d_in[19];
    const float* wl2  = (const float*)d_in[20];
    const float* bl2  = (const float*)d_in[21];
    const float* wr2  = (const float*)d_in[22];
    const float* br2  = (const float*)d_in[23];
    float* out = (float*)d_out;

    corr_k<<<B_, 576>>>(left, right);

    const int IC[5]   = {81, 209, 337, 433, 497};
    const int INO[5]  = {448, 320, 192, 96, 32};
    const int OUTO[5] = {320, 192, 96, 32, 0};
    const int OCB[5]  = {4, 4, 3, 2, 1};   // OC/32
    for (int l = 0; l < 5; l++)
        conv_k<<<dim3(B_, OCB[l]), 256>>>(w6[l], b6[l], IC[l], INO[l], OUTO[l]);

    fc1_k<<<dim3(4, KSPLIT), 256>>>(wfc1);
    fc1red_k<<<256, 256>>>(bfc1);
    l1r1_k<<<dim3(2, 2), 256>>>(wl1, bl1, wr1, br1);
    heads2_k<<<B_, 256>>>(wl2, bl2, wr2, br2, lt, rt);
    mean_k<<<1, 128>>>(out);
}

// round 2
// speedup vs baseline: 1.3135x; 1.3135x over previous
#include <cuda_runtime.h>
#include <cstdint>

#define B_   128
#define C_   512
#define H_   7
#define W_   34
#define PIX  238            // 7*34
#define NCH  529
#define KTOT (NCH*PIX)      // 125902
#define KSPLIT 32
#define KSP  3936           // per-split K (multiple of 16, 32*3936 >= KTOT)
#define PPIX 324            // padded 9*36

// ---------------- scratch (device globals; no allocations allowed) ----------
__device__ float g_X [B_ * NCH * PIX];       // dense-concat activations (fc1 reads this)
__device__ float g_Xp[B_ * NCH * PPIX];      // padded activations (convs read this; halos stay 0)
__device__ float g_part[KSPLIT * B_ * 512];  // fc1 K-split partials
__device__ float g_fc1[B_ * 512];
__device__ float g_h[2 * B_ * 256];          // l1 / r1 outputs
__device__ float g_ang[2 * B_];

typedef unsigned long long ull;

__device__ __forceinline__ float leaky(float x) { return x >= 0.f ? x : 0.1f * x; }

__device__ __forceinline__ ull fpack(float lo, float hi) {
    ull r; asm("mov.b64 %0, {%1, %2};" : "=l"(r) : "f"(lo), "f"(hi)); return r;
}
__device__ __forceinline__ ull fdup(float v) { return fpack(v, v); }
__device__ __forceinline__ void funpack(ull p, float& lo, float& hi) {
    asm("mov.b64 {%0, %1}, %2;" : "=f"(lo), "=f"(hi) : "l"(p));
}
__device__ __forceinline__ void fma2(ull& d, ull a, ull b) {
    asm("fma.rn.f32x2 %0, %1, %2, %3;" : "=l"(d) : "l"(a), "l"(b), "l"(d));
}
__device__ __forceinline__ uint32_t to_tf32(float f) {
    uint32_t r; asm("cvt.rna.tf32.f32 %0, %1;" : "=r"(r) : "f"(f)); return r;
}
__device__ __forceinline__ void mma_tf32(float* c,
                                         uint32_t a0, uint32_t a1, uint32_t a2, uint32_t a3,
                                         uint32_t b0, uint32_t b1) {
    asm volatile("mma.sync.aligned.m16n8k8.row.col.f32.tf32.tf32.f32 "
                 "{%0,%1,%2,%3}, {%4,%5,%6,%7}, {%8,%9}, {%0,%1,%2,%3};"
                 : "+f"(c[0]), "+f"(c[1]), "+f"(c[2]), "+f"(c[3])
                 : "r"(a0), "r"(a1), "r"(a2), "r"(a3), "r"(b0), "r"(b1));
}

// ============================================================================
// corr81 + leaky -> channels [448, 529): dual-store dense g_X + padded g_Xp
// ============================================================================
__global__ __launch_bounds__(576) void corr_k(const float* __restrict__ L,
                                              const float* __restrict__ R) {
    int b = blockIdx.x;
    __shared__ __align__(16) float Ls[8][7][36];
    __shared__ __align__(16) float Rs[8][7][44];
    int t = threadIdx.x;
    int g  = t % 9;
    int dy = (t / 9) % 9;
    int y  = t / 81;
    int x0 = g * 4;

    for (int i = t; i < 8 * 7 * 44; i += 576) ((float*)Rs)[i] = 0.f;
    for (int i = t; i < 8 * 7 * 36; i += 576) ((float*)Ls)[i] = 0.f;
    __syncthreads();

    float acc[9][4];
#pragma unroll
    for (int dx = 0; dx < 9; dx++)
#pragma unroll
        for (int i = 0; i < 4; i++) acc[dx][i] = 0.f;

    int ry = y + dy - 4;
    bool valid = (y < 7) && (ry >= 0) && (ry < 7);
    const float* Lb = L + (size_t)b * C_ * PIX;
    const float* Rb = R + (size_t)b * C_ * PIX;

    for (int c0 = 0; c0 < C_; c0 += 8) {
        for (int i = t; i < 8 * PIX; i += 576) {
            int c = i / PIX, p = i % PIX;
            float lv = Lb[(size_t)(c0 + c) * PIX + p];
            float rv = Rb[(size_t)(c0 + c) * PIX + p];
            Ls[c][p / 34][p % 34]       = lv;
            Rs[c][p / 34][(p % 34) + 4] = rv;
        }
        __syncthreads();
        if (valid) {
#pragma unroll
            for (int c = 0; c < 8; c++) {
                float4 l4 = *(const float4*)&Ls[c][y][x0];
                float4 r0 = *(const float4*)&Rs[c][ry][x0];
                float4 r1 = *(const float4*)&Rs[c][ry][x0 + 4];
                float4 r2 = *(const float4*)&Rs[c][ry][x0 + 8];
                float lv[4]  = {l4.x, l4.y, l4.z, l4.w};
                float rv[12] = {r0.x, r0.y, r0.z, r0.w,
                                r1.x, r1.y, r1.z, r1.w,
                                r2.x, r2.y, r2.z, r2.w};
#pragma unroll
                for (int dx = 0; dx < 9; dx++)
#pragma unroll
                    for (int i = 0; i < 4; i++)
                        acc[dx][i] = fmaf(lv[i], rv[i + dx], acc[dx][i]);
            }
        }
        __syncthreads();
    }

    if (y < 7) {
#pragma unroll
        for (int dx = 0; dx < 9; dx++) {
            int ch = 448 + dy * 9 + dx;
            float* opd = &g_X [((size_t)(b * NCH + ch)) * PIX  + y * 34];
            float* opp = &g_Xp[((size_t)(b * NCH + ch)) * PPIX + (y + 1) * 36 + 1];
#pragma unroll
            for (int i = 0; i < 4; i++) {
                int x = x0 + i;
                if (x < 34) {
                    float v = leaky(acc[dx][i] * (1.f / 512.f));
                    opd[x] = v;
                    opp[x] = v;
                }
            }
        }
    }
}

// ============================================================================
// 3x3 SAME conv + bias + leaky via implicit-GEMM tf32 mma.sync.m16n8k8
// grid (B, OC/32); 256 threads = 8 warps: (mw 0..1) x (nw 0..3)
// warp tile: 16 oc x 64 positions; K = IC*9 in chunks of (8 ic x 9 taps)
// ============================================================================
__global__ __launch_bounds__(256) void convT_k(const float* __restrict__ Wt,
                                               const float* __restrict__ Bi,
                                               int IC, int IN_OFF, int OUT_OFF) {
    int b   = blockIdx.x;
    int ocb = blockIdx.y;
    __shared__ uint32_t Xs[8][328];        // tf32 bits, padded stride (conflict-free)
    __shared__ uint32_t Ws[9][8][40];      // [tap][ic][oc], padded

    int t = threadIdx.x;
    int wid = t >> 5, lane = t & 31;
    int mw = wid & 1, nw = wid >> 1;
    int gid = lane >> 2, tig = lane & 3;   // groupID / threadID-in-group

    float acc[8][4] = {};                  // [n8-block j][c0..c3]

    // per-j base offsets into the padded 9x36 plane (position n = lane/4)
    int offp[8];
#pragma unroll
    for (int j = 0; j < 8; j++) {
        int p = nw * 64 + j * 8 + gid;
        if (p > 237) p = 237;              // clamp: garbage computed, never stored
        offp[j] = (p / 34) * 36 + (p % 34);
    }

    const float* Xin = g_Xp + ((size_t)b * NCH + IN_OFF) * PPIX;

    for (int c0 = 0; c0 < IC; c0 += 8) {
        int cc = min(8, IC - c0);
        // ---- fill Xs: 8 ic x 324 floats (vectorized, tf32-converted) ----
        for (int i = t; i < 8 * 81; i += 256) {
            int c = i / 81, q = (i % 81) * 4;
            float4 v = make_float4(0.f, 0.f, 0.f, 0.f);
            if (c < cc) v = *(const float4*)(Xin + (size_t)(c0 + c) * PPIX + q);
            uint32_t* dst = &Xs[c][q];
            dst[0] = to_tf32(v.x); dst[1] = to_tf32(v.y);
            dst[2] = to_tf32(v.z); dst[3] = to_tf32(v.w);
        }
        // ---- fill Ws: 32 oc x 8 ic x 9 taps ----
        for (int i = t; i < 32 * 72; i += 256) {
            int oc = i / 72, rem = i % 72, ic = rem / 9, kk = rem % 9;
            float v = 0.f;
            if (ic < cc) v = Wt[((size_t)(ocb * 32 + oc) * IC + c0 + ic) * 9 + kk];
            Ws[kk][ic][oc] = to_tf32(v);
        }
        __syncthreads();

#pragma unroll
        for (int ky = 0; ky < 3; ky++)
#pragma unroll
            for (int kx = 0; kx < 3; kx++) {
                int kk  = ky * 3 + kx;
                int kof = ky * 36 + kx;
                uint32_t a0 = Ws[kk][tig    ][mw * 16 + gid];
                uint32_t a1 = Ws[kk][tig    ][mw * 16 + gid + 8];
                uint32_t a2 = Ws[kk][tig + 4][mw * 16 + gid];
                uint32_t a3 = Ws[kk][tig + 4][mw * 16 + gid + 8];
#pragma unroll
                for (int j = 0; j < 8; j++) {
                    uint32_t b0 = Xs[tig    ][offp[j] + kof];
                    uint32_t b1 = Xs[tig + 4][offp[j] + kof];
                    mma_tf32(acc[j], a0, a1, a2, a3, b0, b1);
                }
            }
        __syncthreads();
    }

    // ---- epilogue: bias + leaky, dual store (dense + padded) ----
    int oc0 = ocb * 32 + mw * 16 + gid;    // layer-local oc
    int oc1 = oc0 + 8;
    float bi0 = Bi[oc0], bi1 = Bi[oc1];
    float* o0d = g_X  + ((size_t)b * NCH + OUT_OFF + oc0) * PIX;
    float* o1d = g_X  + ((size_t)b * NCH + OUT_OFF + oc1) * PIX;
    float* o0p = g_Xp + ((size_t)b * NCH + OUT_OFF + oc0) * PPIX;
    float* o1p = g_Xp + ((size_t)b * NCH + OUT_OFF + oc1) * PPIX;
#pragma unroll
    for (int j = 0; j < 8; j++) {
        int p = nw * 64 + j * 8 + tig * 2;     // always even -> p+1 <= 237 when p < 238
        if (p < 238) {
            int off0 = (p / 34 + 1) * 36 + (p % 34 + 1);
            int p1 = p + 1;
            int off1 = (p1 / 34 + 1) * 36 + (p1 % 34 + 1);
            float v00 = leaky(acc[j][0] + bi0);
            float v01 = leaky(acc[j][1] + bi0);
            float v10 = leaky(acc[j][2] + bi1);
            float v11 = leaky(acc[j][3] + bi1);
            o0d[p] = v00;  o0d[p1] = v01;
            o1d[p] = v10;  o1d[p1] = v11;
            o0p[off0] = v00; o0p[off1] = v01;
            o1p[off0] = v10; o1p[off1] = v11;
        }
    }
}

// ============================================================================
// fc1: (128 x 125902) @ (512 x 125902)^T, 32-way K-split -> partials (FFMA2)
// ============================================================================
__global__ __launch_bounds__(256, 2) void fc1_k(const float* __restrict__ Wf) {
    int ntile = blockIdx.x, ks = blockIdx.y;
    int nb = ntile * 128;
    int k0 = ks * KSP, kend = min(KTOT, k0 + KSP);
    __shared__ __align__(16) float Xs[16][132];
    __shared__ __align__(16) float Ws[16][132];
    int t = threadIdx.x, tn = t & 15, tb = t >> 4, b0 = tb * 8, n0 = tn * 8;
    ull acc[8][4] = {};

    for (int kk0 = k0; kk0 < kend; kk0 += 16) {
        int cc = min(16, kend - kk0);
        for (int i = t; i < 2048; i += 256) {
            int k = i & 15, row = i >> 4;
            float xv = 0.f, wv = 0.f;
            if (k < cc) {
                xv = g_X[(size_t)row * KTOT + kk0 + k];
                wv = Wf[(size_t)(nb + row) * KTOT + kk0 + k];
            }
            Xs[k][row] = xv;
            Ws[k][row] = wv;
        }
        __syncthreads();
#pragma unroll 4
        for (int kk = 0; kk < 16; kk++) {
            float4 xa = *(const float4*)&Xs[kk][b0];
            float4 xb = *(const float4*)&Xs[kk][b0 + 4];
            float4 wa = *(const float4*)&Ws[kk][n0];
            float4 wb = *(const float4*)&Ws[kk][n0 + 4];
            ull xd[8] = {fdup(xa.x), fdup(xa.y), fdup(xa.z), fdup(xa.w),
                         fdup(xb.x), fdup(xb.y), fdup(xb.z), fdup(xb.w)};
            ull w2[4] = {fpack(wa.x, wa.y), fpack(wa.z, wa.w),
                         fpack(wb.x, wb.y), fpack(wb.z, wb.w)};
#pragma unroll
            for (int i = 0; i < 8; i++)
#pragma unroll
                for (int j = 0; j < 4; j++)
                    fma2(acc[i][j], w2[j], xd[i]);
        }
        __syncthreads();
    }

#pragma unroll
    for (int i = 0; i < 8; i++)
#pragma unroll
        for (int j = 0; j < 4; j++) {
            float lo, hi; funpack(acc[i][j], lo, hi);
            float* p = &g_part[((size_t)(ks * 128) + b0 + i) * 512 + nb + n0 + 2 * j];
            p[0] = lo; p[1] = hi;
        }
}

__global__ void fc1red_k(const float* __restrict__ bias) {
    int i = blockIdx.x * 256 + threadIdx.x;
    float a = 0.f;
#pragma unroll 8
    for (int ks = 0; ks < KSPLIT; ks++) a += g_part[(size_t)ks * 65536 + i];
    g_fc1[i] = leaky(a + bias[i & 511]);
}

// ============================================================================
// l1 / r1: (128 x 512) @ (256 x 512)^T + bias + leaky -> g_h
// ============================================================================
__global__ __launch_bounds__(256, 2) void l1r1_k(const float* __restrict__ wl1,
                                                 const float* __restrict__ bl1,
                                                 const float* __restrict__ wr1,
                                                 const float* __restrict__ br1) {
    int side = blockIdx.x, ntile = blockIdx.y;
    int nb = ntile * 128;
    const float* Wp = side ? wr1 : wl1;
    const float* Bp = side ? br1 : bl1;
    __shared__ __align__(16) float Xs[16][132];
    __shared__ __align__(16) float Ws[16][132];
    int t = threadIdx.x, tn = t & 15, tb = t >> 4, b0 = tb * 8, n0 = tn * 8;
    ull acc[8][4] = {};

    for (int kk0 = 0; kk0 < 512; kk0 += 16) {
        for (int i = t; i < 2048; i += 256) {
            int k = i & 15, row = i >> 4;
            Xs[k][row] = g_fc1[(size_t)row * 512 + kk0 + k];
            Ws[k][row] = Wp[(size_t)(nb + row) * 512 + kk0 + k];
        }
        __syncthreads();
#pragma unroll 4
        for (int kk = 0; kk < 16; kk++) {
            float4 xa = *(const float4*)&Xs[kk][b0];
            float4 xb = *(const float4*)&Xs[kk][b0 + 4];
            float4 wa = *(const float4*)&Ws[kk][n0];
            float4 wb = *(const float4*)&Ws[kk][n0 + 4];
            ull xd[8] = {fdup(xa.x), fdup(xa.y), fdup(xa.z), fdup(xa.w),
                         fdup(xb.x), fdup(xb.y), fdup(xb.z), fdup(xb.w)};
            ull w2[4] = {fpack(wa.x, wa.y), fpack(wa.z, wa.w),
                         fpack(wb.x, wb.y), fpack(wb.z, wb.w)};
#pragma unroll
            for (int i = 0; i < 8; i++)
#pragma unroll
                for (int j = 0; j < 4; j++)
                    fma2(acc[i][j], w2[j], xd[i]);
        }
        __syncthreads();
    }

#pragma unroll
    for (int i = 0; i < 8; i++)
#pragma unroll
        for (int j = 0; j < 4; j++) {
            float lo, hi; funpack(acc[i][j], lo, hi);
            int n = nb + n0 + 2 * j;
            float* p = &g_h[(size_t)side * (B_ * 256) + (size_t)(b0 + i) * 256 + n];
            p[0] = leaky(lo + Bp[n]);
            p[1] = leaky(hi + Bp[n + 1]);
        }
}

// ============================================================================
// heads + quat distance + mean
// ============================================================================
__global__ void heads2_k(const float* __restrict__ wl2, const float* __restrict__ bl2,
                         const float* __restrict__ wr2, const float* __restrict__ br2,
                         const float* __restrict__ lt,  const float* __restrict__ rt) {
    int b = blockIdx.x, t = threadIdx.x;
    __shared__ float hl[256], hr[256], q[8];
    hl[t] = g_h[(size_t)b * 256 + t];
    hr[t] = g_h[(size_t)(B_ * 256) + (size_t)b * 256 + t];
    __syncthreads();

    int wrp = t >> 5, lane = t & 31;
    const float* w   = (wrp < 4) ? wl2 : wr2;
    const float* src = (wrp < 4) ? hl : hr;
    int i = wrp & 3;
    float s = 0.f;
    for (int j = lane; j < 256; j += 32) s += w[i * 256 + j] * src[j];
#pragma unroll
    for (int off = 16; off > 0; off >>= 1) s += __shfl_down_sync(0xffffffffu, s, off);
    if (lane == 0) q[wrp] = s + ((wrp < 4) ? bl2[i] : br2[i]);
    __syncthreads();

    if (t == 0) {
#pragma unroll
        for (int side = 0; side < 2; side++) {
            float qw = q[side * 4 + 0], qx = q[side * 4 + 1];
            float qy = q[side * 4 + 2], qz = q[side * 4 + 3];
            float nn = sqrtf(qw * qw + qx * qx + qy * qy + qz * qz);
            nn = fmaxf(nn, 1e-12f);
            qw /= nn; qx /= nn; qy /= nn; qz /= nn;
            const float* tgt = (side == 0 ? lt : rt) + (size_t)b * 4;
            float rw = tgt[0], rx = -tgt[1], ry = -tgt[2], rz = -tgt[3];
            float tw = qw * rw - qx * rx - qy * ry - qz * rz;
            float tx = qw * rx + qx * rw + qy * rz - qz * ry;
            float ty = qw * ry - qx * rz + qy * rw + qz * rx;
            float tz = qw * rz + qx * ry - qy * rx + qz * rw;
            float ang = 2.f * atan2f(sqrtf(tx * tx + ty * ty + tz * tz + 1e-12f), fabsf(tw));
            g_ang[side * B_ + b] = ang;
        }
    }
}

__global__ void mean_k(float* __restrict__ out) {
    __shared__ float sl[128], sr[128];
    int t = threadIdx.x;
    sl[t] = g_ang[t];
    sr[t] = g_ang[128 + t];
    __syncthreads();
    for (int s = 64; s > 0; s >>= 1) {
        if (t < s) { sl[t] += sl[t + s]; sr[t] += sr[t + s]; }
        __syncthreads();
    }
    if (t == 0) { out[0] = sl[0] * (1.f / 128.f); out[1] = sr[0] * (1.f / 128.f); }
}

// ============================================================================
extern "C" void kernel_launch(void* const* d_in, const int* in_sizes, int n_in,
                              void* d_out, int out_size) {
    (void)in_sizes; (void)n_in; (void)out_size;
    const float* left  = (const float*)d_in[0];
    const float* right = (const float*)d_in[1];
    const float* lt    = (const float*)d_in[2];
    const float* rt    = (const float*)d_in[3];
    const float* w6[5] = {(const float*)d_in[4],  (const float*)d_in[6],
                          (const float*)d_in[8],  (const float*)d_in[10],
                          (const float*)d_in[12]};
    const float* b6[5] = {(const float*)d_in[5],  (const float*)d_in[7],
                          (const float*)d_in[9],  (const float*)d_in[11],
                          (const float*)d_in[13]};
    const float* wfc1 = (const float*)d_in[14];
    const float* bfc1 = (const float*)d_in[15];
    const float* wl1  = (const float*)d_in[16];
    const float* bl1  = (const float*)d_in[17];
    const float* wr1  = (const float*)d_in[18];
    const float* br1  = (const float*)d_in[19];
    const float* wl2  = (const float*)d_in[20];
    const float* bl2  = (const float*)d_in[21];
    const float* wr2  = (const float*)d_in[22];
    const float* br2  = (const float*)d_in[23];
    float* out = (float*)d_out;

    corr_k<<<B_, 576>>>(left, right);

    const int IC[5]   = {81, 209, 337, 433, 497};
    const int INO[5]  = {448, 320, 192, 96, 32};
    const int OUTO[5] = {320, 192, 96, 32, 0};
    const int OCB[5]  = {4, 4, 3, 2, 1};   // OC/32
    for (int l = 0; l < 5; l++)
        convT_k<<<dim3(B_, OCB[l]), 256>>>(w6[l], b6[l], IC[l], INO[l], OUTO[l]);

    fc1_k<<<dim3(4, KSPLIT), 256>>>(wfc1);
    fc1red_k<<<256, 256>>>(bfc1);
    l1r1_k<<<dim3(2, 2), 256>>>(wl1, bl1, wr1, br1);
    heads2_k<<<B_, 256>>>(wl2, bl2, wr2, br2, lt, rt);
    mean_k<<<1, 128>>>(out);
}

// round 3
// speedup vs baseline: 1.5395x; 1.1720x over previous
#include <cuda_runtime.h>
#include <cstdint>

#define B_   128
#define C_   512
#define H_   7
#define W_   34
#define PIX  238            // 7*34
#define NCH  529
#define KTOT (NCH*PIX)      // 125902
#define KSPLIT 32
#define KSP  3936           // per-split K (123 chunks of 32)
#define PPIX 324            // padded 9*36
#define WTILE 5760          // 9 taps * 16 ic * 40 oc-padded words per (ocb,chunk)

// ---------------- scratch (device globals; no allocations allowed) ----------
__device__ uint32_t g_Xdt[B_ * NCH * PIX];   // dense activations, tf32 bits (fc1 reads)
__device__ uint32_t g_Xpt[B_ * NCH * PPIX];  // padded activations, tf32 bits (convs read; halos stay 0)
__device__ uint32_t g_Wc[234 * WTILE];       // pre-transformed conv weights (tf32 bits)
__device__ float g_part[KSPLIT * B_ * 512];  // fc1 K-split partials
__device__ float g_fc1[B_ * 512];
__device__ float g_h[2 * B_ * 256];
__device__ float g_ang[2 * B_];

typedef unsigned long long ull;

__device__ __forceinline__ float leaky(float x) { return x >= 0.f ? x : 0.1f * x; }

__device__ __forceinline__ ull fpack(float lo, float hi) {
    ull r; asm("mov.b64 %0, {%1, %2};" : "=l"(r) : "f"(lo), "f"(hi)); return r;
}
__device__ __forceinline__ ull fdup(float v) { return fpack(v, v); }
__device__ __forceinline__ void funpack(ull p, float& lo, float& hi) {
    asm("mov.b64 {%0, %1}, %2;" : "=f"(lo), "=f"(hi) : "l"(p));
}
__device__ __forceinline__ void fma2(ull& d, ull a, ull b) {
    asm("fma.rn.f32x2 %0, %1, %2, %3;" : "=l"(d) : "l"(a), "l"(b), "l"(d));
}
__device__ __forceinline__ uint32_t to_tf32(float f) {
    uint32_t r; asm("cvt.rna.tf32.f32 %0, %1;" : "=r"(r) : "f"(f)); return r;
}
__device__ __forceinline__ void mma_tf32(float* c,
                                         uint32_t a0, uint32_t a1, uint32_t a2, uint32_t a3,
                                         uint32_t b0, uint32_t b1) {
    asm volatile("mma.sync.aligned.m16n8k8.row.col.f32.tf32.tf32.f32 "
                 "{%0,%1,%2,%3}, {%4,%5,%6,%7}, {%8,%9}, {%0,%1,%2,%3};"
                 : "+f"(c[0]), "+f"(c[1]), "+f"(c[2]), "+f"(c[3])
                 : "r"(a0), "r"(a1), "r"(a2), "r"(a3), "r"(b0), "r"(b1));
}

// ============================================================================
// weight prep: [OC,IC,3,3] fp32 -> tf32 tiles [ocb][chunk][tap][ic16][40]
// ============================================================================
__global__ void wprep_k(const float* __restrict__ Wt, int IC, int wbase) {
    int ocb = blockIdx.x, ch = blockIdx.y, chunks = gridDim.y;
    uint32_t* out = g_Wc + wbase + (size_t)(ocb * chunks + ch) * WTILE;
    int c0 = ch * 16;
    for (int i = threadIdx.x; i < WTILE; i += 256) {
        int tap = i / 640, rem = i % 640, ic = rem / 40, oc = rem % 40;
        float v = 0.f;
        if (oc < 32 && c0 + ic < IC)
            v = Wt[((size_t)(ocb * 32 + oc) * IC + c0 + ic) * 9 + tap];
        out[i] = to_tf32(v);
    }
}

// ============================================================================
// corr81 + leaky -> channels [448,529): stores tf32 bits (dense + padded)
// ============================================================================
__global__ __launch_bounds__(576) void corr_k(const float* __restrict__ L,
                                              const float* __restrict__ R) {
    int b = blockIdx.x;
    __shared__ __align__(16) float Ls[8][7][36];
    __shared__ __align__(16) float Rs[8][7][44];
    int t = threadIdx.x;
    int g  = t % 9;
    int dy = (t / 9) % 9;
    int y  = t / 81;
    int x0 = g * 4;

    for (int i = t; i < 8 * 7 * 44; i += 576) ((float*)Rs)[i] = 0.f;
    for (int i = t; i < 8 * 7 * 36; i += 576) ((float*)Ls)[i] = 0.f;
    __syncthreads();

    float acc[9][4];
#pragma unroll
    for (int dx = 0; dx < 9; dx++)
#pragma unroll
        for (int i = 0; i < 4; i++) acc[dx][i] = 0.f;

    int ry = y + dy - 4;
    bool valid = (y < 7) && (ry >= 0) && (ry < 7);
    const float* Lb = L + (size_t)b * C_ * PIX;
    const float* Rb = R + (size_t)b * C_ * PIX;

    for (int c0 = 0; c0 < C_; c0 += 8) {
        for (int i = t; i < 8 * PIX; i += 576) {
            int c = i / PIX, p = i % PIX;
            Ls[c][p / 34][p % 34]       = Lb[(size_t)(c0 + c) * PIX + p];
            Rs[c][p / 34][(p % 34) + 4] = Rb[(size_t)(c0 + c) * PIX + p];
        }
        __syncthreads();
        if (valid) {
#pragma unroll
            for (int c = 0; c < 8; c++) {
                float4 l4 = *(const float4*)&Ls[c][y][x0];
                float4 r0 = *(const float4*)&Rs[c][ry][x0];
                float4 r1 = *(const float4*)&Rs[c][ry][x0 + 4];
                float4 r2 = *(const float4*)&Rs[c][ry][x0 + 8];
                float lv[4]  = {l4.x, l4.y, l4.z, l4.w};
                float rv[12] = {r0.x, r0.y, r0.z, r0.w,
                                r1.x, r1.y, r1.z, r1.w,
                                r2.x, r2.y, r2.z, r2.w};
#pragma unroll
                for (int dx = 0; dx < 9; dx++)
#pragma unroll
                    for (int i = 0; i < 4; i++)
                        acc[dx][i] = fmaf(lv[i], rv[i + dx], acc[dx][i]);
            }
        }
        __syncthreads();
    }

    if (y < 7) {
#pragma unroll
        for (int dx = 0; dx < 9; dx++) {
            int ch = 448 + dy * 9 + dx;
            uint32_t* opd = &g_Xdt[((size_t)(b * NCH + ch)) * PIX  + y * 34];
            uint32_t* opp = &g_Xpt[((size_t)(b * NCH + ch)) * PPIX + (y + 1) * 36 + 1];
#pragma unroll
            for (int i = 0; i < 4; i++) {
                int x = x0 + i;
                if (x < 34) {
                    uint32_t v = to_tf32(leaky(acc[dx][i] * (1.f / 512.f)));
                    opd[x] = v;
                    opp[x] = v;
                }
            }
        }
    }
}

// ============================================================================
// 3x3 conv via tf32 mma, prepped weights, 16-ic chunks, copy-only fills
// grid (B, OC/32); 8 warps = 2(oc) x 4(pos); warp: 16 oc x 64 positions
// ============================================================================
__global__ __launch_bounds__(256) void convT_k(const float* __restrict__ Bi,
                                               int IC, int chunks, int wbase,
                                               int IN_OFF, int OUT_OFF) {
    int b   = blockIdx.x;
    int ocb = blockIdx.y;
    __shared__ uint32_t Xs[16][328];
    __shared__ uint32_t Wss[WTILE];

    int t = threadIdx.x;
    int wid = t >> 5, lane = t & 31;
    int mw = wid & 1, nw = wid >> 1;
    int gid = lane >> 2, tig = lane & 3;

    float acc[8][4] = {};

    int offp[8];
#pragma unroll
    for (int j = 0; j < 8; j++) {
        int p = nw * 64 + j * 8 + gid;
        if (p > 237) p = 237;
        offp[j] = (p / 34) * 36 + (p % 34);
    }

    const uint32_t* Xin = g_Xpt + ((size_t)b * NCH + IN_OFF) * PPIX;
    const uint32_t* Wtile = g_Wc + wbase + (size_t)ocb * chunks * WTILE;

    int cfill = t >> 4, jf = t & 15;      // channel / intra-channel copier
    for (int ch = 0; ch < chunks; ch++) {
        int cc = IC - ch * 16; if (cc > 16) cc = 16;
        // Xs: 16 ch x 81 uint4 copies (zeros for c >= cc)
        {
            const uint4* src = (const uint4*)(Xin + (size_t)(ch * 16 + cfill) * PPIX);
            uint4* dst = (uint4*)&Xs[cfill][0];
            if (cfill < cc) {
                for (int q = jf; q < 81; q += 16) dst[q] = src[q];
            } else {
                uint4 z = {0, 0, 0, 0};
                for (int q = jf; q < 81; q += 16) dst[q] = z;
            }
        }
        // Ws: flat uint4 copy of the prepped tile
        {
            const uint4* src = (const uint4*)(Wtile + (size_t)ch * WTILE);
            uint4* dst = (uint4*)Wss;
            for (int i = t; i < WTILE / 4; i += 256) dst[i] = src[i];
        }
        __syncthreads();

#pragma unroll
        for (int kg = 0; kg < 2; kg++) {
#pragma unroll
            for (int ky = 0; ky < 3; ky++)
#pragma unroll
                for (int kx = 0; kx < 3; kx++) {
                    int kk  = ky * 3 + kx;
                    int kof = ky * 36 + kx;
                    int icb = kg * 8;
                    uint32_t a0 = Wss[kk * 640 + (icb + tig    ) * 40 + mw * 16 + gid];
                    uint32_t a1 = Wss[kk * 640 + (icb + tig    ) * 40 + mw * 16 + gid + 8];
                    uint32_t a2 = Wss[kk * 640 + (icb + tig + 4) * 40 + mw * 16 + gid];
                    uint32_t a3 = Wss[kk * 640 + (icb + tig + 4) * 40 + mw * 16 + gid + 8];
#pragma unroll
                    for (int j = 0; j < 8; j++) {
                        uint32_t b0 = Xs[icb + tig    ][offp[j] + kof];
                        uint32_t b1 = Xs[icb + tig + 4][offp[j] + kof];
                        mma_tf32(acc[j], a0, a1, a2, a3, b0, b1);
                    }
                }
        }
        __syncthreads();
    }

    // epilogue: bias + leaky, tf32 dual store
    int oc0 = ocb * 32 + mw * 16 + gid;
    int oc1 = oc0 + 8;
    float bi0 = Bi[oc0], bi1 = Bi[oc1];
    uint32_t* o0d = g_Xdt + ((size_t)b * NCH + OUT_OFF + oc0) * PIX;
    uint32_t* o1d = g_Xdt + ((size_t)b * NCH + OUT_OFF + oc1) * PIX;
    uint32_t* o0p = g_Xpt + ((size_t)b * NCH + OUT_OFF + oc0) * PPIX;
    uint32_t* o1p = g_Xpt + ((size_t)b * NCH + OUT_OFF + oc1) * PPIX;
#pragma unroll
    for (int j = 0; j < 8; j++) {
        int p = nw * 64 + j * 8 + tig * 2;
        if (p < 238) {
            int p1 = p + 1;
            int off0 = (p / 34 + 1) * 36 + (p % 34 + 1);
            int off1 = (p1 / 34 + 1) * 36 + (p1 % 34 + 1);
            uint32_t v00 = to_tf32(leaky(acc[j][0] + bi0));
            uint32_t v01 = to_tf32(leaky(acc[j][1] + bi0));
            uint32_t v10 = to_tf32(leaky(acc[j][2] + bi1));
            uint32_t v11 = to_tf32(leaky(acc[j][3] + bi1));
            o0d[p] = v00;  o0d[p1] = v01;
            o1d[p] = v10;  o1d[p1] = v11;
            o0p[off0] = v00; o0p[off1] = v01;
            o1p[off0] = v10; o1p[off1] = v11;
        }
    }
}

// ============================================================================
// fc1 via tf32 mma: C[128 x 512] = X[128 x K] * W^T, 32-way K-split
// grid (8 ntiles of 64, 32 ksplits); 8 warps = 4(M32) x 2(N32)
// ============================================================================
__global__ __launch_bounds__(256, 2) void fc1T_k(const float* __restrict__ Wf) {
    int ntile = blockIdx.x, ks = blockIdx.y;
    int nb = ntile * 64;
    int k0 = ks * KSP, kend = min(KTOT, k0 + KSP);
    __shared__ uint32_t Xs[128][36];
    __shared__ uint32_t Ws[64][36];

    int t = threadIdx.x;
    int wid = t >> 5, lane = t & 31;
    int gid = lane >> 2, tig = lane & 3;
    int mwarp = wid & 3, nwarp = wid >> 2;
    int m0 = mwarp * 32, n0 = nwarp * 32;

    float acc[2][4][4] = {};

    for (int kk0 = k0; kk0 < kend; kk0 += 32) {
        // Xs: 128 rows x 32 k (uint2 from tf32 dense buffer)
        for (int i = t; i < 2048; i += 256) {
            int row = i >> 4, s = i & 15;
            int k = kk0 + s * 2;
            uint2 v = {0u, 0u};
            if (k + 1 < kend)      v = *(const uint2*)&g_Xdt[(size_t)row * KTOT + k];
            else if (k < kend)     v.x = g_Xdt[(size_t)row * KTOT + k];
            Xs[row][s * 2] = v.x; Xs[row][s * 2 + 1] = v.y;
        }
        // Ws: 64 rows x 32 k (float2 + cvt)
        for (int i = t; i < 1024; i += 256) {
            int row = i >> 4, s = i & 15;
            int k = kk0 + s * 2;
            float2 w = {0.f, 0.f};
            if (k + 1 < kend)      w = *(const float2*)&Wf[(size_t)(nb + row) * KTOT + k];
            else if (k < kend)     w.x = Wf[(size_t)(nb + row) * KTOT + k];
            Ws[row][s * 2] = to_tf32(w.x); Ws[row][s * 2 + 1] = to_tf32(w.y);
        }
        __syncthreads();

#pragma unroll
        for (int k8 = 0; k8 < 4; k8++) {
            int kb = k8 * 8;
            uint32_t a[2][4];
#pragma unroll
            for (int mi = 0; mi < 2; mi++) {
                int m = m0 + mi * 16;
                a[mi][0] = Xs[m + gid    ][kb + tig];
                a[mi][1] = Xs[m + gid + 8][kb + tig];
                a[mi][2] = Xs[m + gid    ][kb + tig + 4];
                a[mi][3] = Xs[m + gid + 8][kb + tig + 4];
            }
#pragma unroll
            for (int nj = 0; nj < 4; nj++) {
                int n = n0 + nj * 8;
                uint32_t b0 = Ws[n + gid][kb + tig];
                uint32_t b1 = Ws[n + gid][kb + tig + 4];
#pragma unroll
                for (int mi = 0; mi < 2; mi++)
                    mma_tf32(acc[mi][nj], a[mi][0], a[mi][1], a[mi][2], a[mi][3], b0, b1);
            }
        }
        __syncthreads();
    }

    float* pp = g_part + (size_t)ks * 65536;
#pragma unroll
    for (int mi = 0; mi < 2; mi++) {
        int m = m0 + mi * 16;
#pragma unroll
        for (int nj = 0; nj < 4; nj++) {
            int col = nb + n0 + nj * 8 + 2 * tig;
            *(float2*)&pp[(size_t)(m + gid    ) * 512 + col] =
                make_float2(acc[mi][nj][0], acc[mi][nj][1]);
            *(float2*)&pp[(size_t)(m + gid + 8) * 512 + col] =
                make_float2(acc[mi][nj][2], acc[mi][nj][3]);
        }
    }
}

__global__ void fc1red_k(const float* __restrict__ bias) {
    int i = blockIdx.x * 256 + threadIdx.x;
    float a = 0.f;
#pragma unroll 8
    for (int ks = 0; ks < KSPLIT; ks++) a += g_part[(size_t)ks * 65536 + i];
    g_fc1[i] = leaky(a + bias[i & 511]);
}

// ============================================================================
// l1 / r1 (FFMA2, small)
// ============================================================================
__global__ __launch_bounds__(256, 2) void l1r1_k(const float* __restrict__ wl1,
                                                 const float* __restrict__ bl1,
                                                 const float* __restrict__ wr1,
                                                 const float* __restrict__ br1) {
    int side = blockIdx.x, ntile = blockIdx.y;
    int nb = ntile * 128;
    const float* Wp = side ? wr1 : wl1;
    const float* Bp = side ? br1 : bl1;
    __shared__ __align__(16) float Xs[16][132];
    __shared__ __align__(16) float Ws[16][132];
    int t = threadIdx.x, tn = t & 15, tb = t >> 4, b0 = tb * 8, n0 = tn * 8;
    ull acc[8][4] = {};

    for (int kk0 = 0; kk0 < 512; kk0 += 16) {
        for (int i = t; i < 2048; i += 256) {
            int k = i & 15, row = i >> 4;
            Xs[k][row] = g_fc1[(size_t)row * 512 + kk0 + k];
            Ws[k][row] = Wp[(size_t)(nb + row) * 512 + kk0 + k];
        }
        __syncthreads();
#pragma unroll 4
        for (int kk = 0; kk < 16; kk++) {
            float4 xa = *(const float4*)&Xs[kk][b0];
            float4 xb = *(const float4*)&Xs[kk][b0 + 4];
            float4 wa = *(const float4*)&Ws[kk][n0];
            float4 wb = *(const float4*)&Ws[kk][n0 + 4];
            ull xd[8] = {fdup(xa.x), fdup(xa.y), fdup(xa.z), fdup(xa.w),
                         fdup(xb.x), fdup(xb.y), fdup(xb.z), fdup(xb.w)};
            ull w2[4] = {fpack(wa.x, wa.y), fpack(wa.z, wa.w),
                         fpack(wb.x, wb.y), fpack(wb.z, wb.w)};
#pragma unroll
            for (int i = 0; i < 8; i++)
#pragma unroll
                for (int j = 0; j < 4; j++)
                    fma2(acc[i][j], w2[j], xd[i]);
        }
        __syncthreads();
    }

#pragma unroll
    for (int i = 0; i < 8; i++)
#pragma unroll
        for (int j = 0; j < 4; j++) {
            float lo, hi; funpack(acc[i][j], lo, hi);
            int n = nb + n0 + 2 * j;
            float* p = &g_h[(size_t)side * (B_ * 256) + (size_t)(b0 + i) * 256 + n];
            p[0] = leaky(lo + Bp[n]);
            p[1] = leaky(hi + Bp[n + 1]);
        }
}

// ============================================================================
// heads + quat distance + mean
// ============================================================================
__global__ void heads2_k(const float* __restrict__ wl2, const float* __restrict__ bl2,
                         const float* __restrict__ wr2, const float* __restrict__ br2,
                         const float* __restrict__ lt,  const float* __restrict__ rt) {
    int b = blockIdx.x, t = threadIdx.x;
    __shared__ float hl[256], hr[256], q[8];
    hl[t] = g_h[(size_t)b * 256 + t];
    hr[t] = g_h[(size_t)(B_ * 256) + (size_t)b * 256 + t];
    __syncthreads();

    int wrp = t >> 5, lane = t & 31;
    const float* w   = (wrp < 4) ? wl2 : wr2;
    const float* src = (wrp < 4) ? hl : hr;
    int i = wrp & 3;
    float s = 0.f;
    for (int j = lane; j < 256; j += 32) s += w[i * 256 + j] * src[j];
#pragma unroll
    for (int off = 16; off > 0; off >>= 1) s += __shfl_down_sync(0xffffffffu, s, off);
    if (lane == 0) q[wrp] = s + ((wrp < 4) ? bl2[i] : br2[i]);
    __syncthreads();

    if (t == 0) {
#pragma unroll
        for (int side = 0; side < 2; side++) {
            float qw = q[side * 4 + 0], qx = q[side * 4 + 1];
            float qy = q[side * 4 + 2], qz = q[side * 4 + 3];
            float nn = sqrtf(qw * qw + qx * qx + qy * qy + qz * qz);
            nn = fmaxf(nn, 1e-12f);
            qw /= nn; qx /= nn; qy /= nn; qz /= nn;
            const float* tgt = (side == 0 ? lt : rt) + (size_t)b * 4;
            float rw = tgt[0], rx = -tgt[1], ry = -tgt[2], rz = -tgt[3];
            float tw = qw * rw - qx * rx - qy * ry - qz * rz;
            float tx = qw * rx + qx * rw + qy * rz - qz * ry;
            float ty = qw * ry - qx * rz + qy * rw + qz * rx;
            float tz = qw * rz + qx * ry - qy * rx + qz * rw;
            float ang = 2.f * atan2f(sqrtf(tx * tx + ty * ty + tz * tz + 1e-12f), fabsf(tw));
            g_ang[side * B_ + b] = ang;
        }
    }
}

__global__ void mean_k(float* __restrict__ out) {
    __shared__ float sl[128], sr[128];
    int t = threadIdx.x;
    sl[t] = g_ang[t];
    sr[t] = g_ang[128 + t];
    __syncthreads();
    for (int s = 64; s > 0; s >>= 1) {
        if (t < s) { sl[t] += sl[t + s]; sr[t] += sr[t + s]; }
        __syncthreads();
    }
    if (t == 0) { out[0] = sl[0] * (1.f / 128.f); out[1] = sr[0] * (1.f / 128.f); }
}

// ============================================================================
extern "C" void kernel_launch(void* const* d_in, const int* in_sizes, int n_in,
                              void* d_out, int out_size) {
    (void)in_sizes; (void)n_in; (void)out_size;
    const float* left  = (const float*)d_in[0];
    const float* right = (const float*)d_in[1];
    const float* lt    = (const float*)d_in[2];
    const float* rt    = (const float*)d_in[3];
    const float* w6[5] = {(const float*)d_in[4],  (const float*)d_in[6],
                          (const float*)d_in[8],  (const float*)d_in[10],
                          (const float*)d_in[12]};
    const float* b6[5] = {(const float*)d_in[5],  (const float*)d_in[7],
                          (const float*)d_in[9],  (const float*)d_in[11],
                          (const float*)d_in[13]};
    const float* wfc1 = (const float*)d_in[14];
    const float* bfc1 = (const float*)d_in[15];
    const float* wl1  = (const float*)d_in[16];
    const float* bl1  = (const float*)d_in[17];
    const float* wr1  = (const float*)d_in[18];
    const float* br1  = (const float*)d_in[19];
    const float* wl2  = (const float*)d_in[20];
    const float* bl2  = (const float*)d_in[21];
    const float* wr2  = (const float*)d_in[22];
    const float* br2  = (const float*)d_in[23];
    float* out = (float*)d_out;

    const int IC[5]     = {81, 209, 337, 433, 497};
    const int INO[5]    = {448, 320, 192, 96, 32};
    const int OUTO[5]   = {320, 192, 96, 32, 0};
    const int OCB[5]    = {4, 4, 3, 2, 1};
    const int CHK[5]    = {6, 14, 22, 28, 32};
    const int WBASE[5]  = {0, 24 * WTILE, 80 * WTILE, 146 * WTILE, 202 * WTILE};

    for (int l = 0; l < 5; l++)
        wprep_k<<<dim3(OCB[l], CHK[l]), 256>>>(w6[l], IC[l], WBASE[l]);

    corr_k<<<B_, 576>>>(left, right);

    for (int l = 0; l < 5; l++)
        convT_k<<<dim3(B_, OCB[l]), 256>>>(b6[l], IC[l], CHK[l], WBASE[l], INO[l], OUTO[l]);

    fc1T_k<<<dim3(8, KSPLIT), 256>>>(wfc1);
    fc1red_k<<<256, 256>>>(bfc1);
    l1r1_k<<<dim3(2, 2), 256>>>(wl1, bl1, wr1, br1);
    heads2_k<<<B_, 256>>>(wl2, bl2, wr2, br2, lt, rt);
    mean_k<<<1, 128>>>(out);
}

// round 4
// speedup vs baseline: 2.5315x; 1.6444x over previous
#include <cuda_runtime.h>
#include <cstdint>

#define B_   128
#define C_   512
#define PIX  238            // 7*34
#define NCH  529
#define KTOT (NCH*PIX)      // 125902
#define KPAD 125952         // padded dense row stride = 32*3936 (16B-aligned rows)
#define KSPLIT 32
#define KSP  3936
#define NCHUNK 123          // KSP/32
#define PPIX 324            // padded 9*36
#define WTILE 5760          // 9 taps * 16 ic * 40 oc-padded words

// ---------------- scratch (device globals; no allocations allowed) ----------
__device__ uint32_t g_Xdt[B_ * KPAD];        // dense activations, tf32 bits (pad cols stay 0)
__device__ uint32_t g_Xpt[B_ * NCH * PPIX];  // padded activations, tf32 bits (halos stay 0)
__device__ uint32_t g_Wc[234 * WTILE];       // pre-transformed conv weights (tf32 bits)
__device__ float g_part[KSPLIT * B_ * 512];
__device__ float g_fc1[B_ * 512];
__device__ float g_h[2 * B_ * 256];
__device__ float g_ang[2 * B_];

typedef unsigned long long ull;

__device__ __forceinline__ float leaky(float x) { return x >= 0.f ? x : 0.1f * x; }

__device__ __forceinline__ ull fpack(float lo, float hi) {
    ull r; asm("mov.b64 %0, {%1, %2};" : "=l"(r) : "f"(lo), "f"(hi)); return r;
}
__device__ __forceinline__ ull fdup(float v) { return fpack(v, v); }
__device__ __forceinline__ void funpack(ull p, float& lo, float& hi) {
    asm("mov.b64 {%0, %1}, %2;" : "=f"(lo), "=f"(hi) : "l"(p));
}
__device__ __forceinline__ void fma2(ull& d, ull a, ull b) {
    asm("fma.rn.f32x2 %0, %1, %2, %3;" : "=l"(d) : "l"(a), "l"(b), "l"(d));
}
__device__ __forceinline__ uint32_t to_tf32(float f) {
    uint32_t r; asm("cvt.rna.tf32.f32 %0, %1;" : "=r"(r) : "f"(f)); return r;
}
__device__ __forceinline__ void mma_tf32(float* c,
                                         uint32_t a0, uint32_t a1, uint32_t a2, uint32_t a3,
                                         uint32_t b0, uint32_t b1) {
    asm volatile("mma.sync.aligned.m16n8k8.row.col.f32.tf32.tf32.f32 "
                 "{%0,%1,%2,%3}, {%4,%5,%6,%7}, {%8,%9}, {%0,%1,%2,%3};"
                 : "+f"(c[0]), "+f"(c[1]), "+f"(c[2]), "+f"(c[3])
                 : "r"(a0), "r"(a1), "r"(a2), "r"(a3), "r"(b0), "r"(b1));
}
__device__ __forceinline__ uint32_t sptr(const void* p) {
    return (uint32_t)__cvta_generic_to_shared(p);
}
#define CPA16(dst, src)  asm volatile("cp.async.ca.shared.global [%0], [%1], 16;"    :: "r"(dst), "l"(src))
#define CPA16Z(dst, src) asm volatile("cp.async.ca.shared.global [%0], [%1], 16, 0;" :: "r"(dst), "l"(src))
#define CPA8(dst, src)   asm volatile("cp.async.ca.shared.global [%0], [%1], 8;"     :: "r"(dst), "l"(src))
#define CPCOMMIT()       asm volatile("cp.async.commit_group;")
#define CPWAIT1()        asm volatile("cp.async.wait_group 1;" ::: "memory")

// ============================================================================
// weight prep: all 5 layers in one launch (234 tiles)
// ============================================================================
__global__ void wprep_all(const float* __restrict__ w0, const float* __restrict__ w1,
                          const float* __restrict__ w2, const float* __restrict__ w3,
                          const float* __restrict__ w4) {
    int tile = blockIdx.x;
    const float* W; int IC, chunks, tbase;
    if      (tile <  24) { W = w0; IC =  81; chunks =  6; tbase =   0; }
    else if (tile <  80) { W = w1; IC = 209; chunks = 14; tbase =  24; }
    else if (tile < 146) { W = w2; IC = 337; chunks = 22; tbase =  80; }
    else if (tile < 202) { W = w3; IC = 433; chunks = 28; tbase = 146; }
    else                 { W = w4; IC = 497; chunks = 32; tbase = 202; }
    int rel = tile - tbase, ocb = rel / chunks, ch = rel % chunks;
    int c0 = ch * 16;
    uint32_t* out = g_Wc + (size_t)tile * WTILE;
    for (int i = threadIdx.x; i < WTILE; i += 256) {
        int tap = i / 640, rem = i % 640, ic = rem / 40, oc = rem % 40;
        float v = 0.f;
        if (oc < 32 && c0 + ic < IC)
            v = W[((size_t)(ocb * 32 + oc) * IC + c0 + ic) * 9 + tap];
        out[i] = to_tf32(v);
    }
}

// ============================================================================
// corr81 + leaky -> channels [448,529): tf32 bits (dense KPAD + padded)
// ============================================================================
__global__ __launch_bounds__(576) void corr_k(const float* __restrict__ L,
                                              const float* __restrict__ R) {
    int b = blockIdx.x;
    __shared__ __align__(16) float Ls[8][7][36];
    __shared__ __align__(16) float Rs[8][7][44];
    int t = threadIdx.x;
    int g  = t % 9;
    int dy = (t / 9) % 9;
    int y  = t / 81;
    int x0 = g * 4;

    for (int i = t; i < 8 * 7 * 44; i += 576) ((float*)Rs)[i] = 0.f;
    for (int i = t; i < 8 * 7 * 36; i += 576) ((float*)Ls)[i] = 0.f;
    __syncthreads();

    ull acc2[9][2] = {};

    int ry = y + dy - 4;
    bool valid = (y < 7) && (ry >= 0) && (ry < 7);
    const float* Lb = L + (size_t)b * C_ * PIX;
    const float* Rb = R + (size_t)b * C_ * PIX;

    for (int c0 = 0; c0 < C_; c0 += 8) {
        for (int i = t; i < 8 * PIX; i += 576) {
            int c = i / PIX, p = i % PIX;
            Ls[c][p / 34][p % 34]       = Lb[(size_t)(c0 + c) * PIX + p];
            Rs[c][p / 34][(p % 34) + 4] = Rb[(size_t)(c0 + c) * PIX + p];
        }
        __syncthreads();
        if (valid) {
#pragma unroll
            for (int c = 0; c < 8; c++) {
                float4 l4 = *(const float4*)&Ls[c][y][x0];
                float4 r0 = *(const float4*)&Rs[c][ry][x0];
                float4 r1 = *(const float4*)&Rs[c][ry][x0 + 4];
                float4 r2 = *(const float4*)&Rs[c][ry][x0 + 8];
                ull lp0 = fpack(l4.x, l4.y), lp1 = fpack(l4.z, l4.w);
                float rv[12] = {r0.x, r0.y, r0.z, r0.w,
                                r1.x, r1.y, r1.z, r1.w,
                                r2.x, r2.y, r2.z, r2.w};
#pragma unroll
                for (int dx = 0; dx < 9; dx++) {
                    fma2(acc2[dx][0], lp0, fpack(rv[dx],     rv[dx + 1]));
                    fma2(acc2[dx][1], lp1, fpack(rv[dx + 2], rv[dx + 3]));
                }
            }
        }
        __syncthreads();
    }

    if (y < 7) {
#pragma unroll
        for (int dx = 0; dx < 9; dx++) {
            int ch = 448 + dy * 9 + dx;
            float av[4];
            funpack(acc2[dx][0], av[0], av[1]);
            funpack(acc2[dx][1], av[2], av[3]);
            uint32_t* opd = &g_Xdt[(size_t)b * KPAD + ch * PIX + y * 34];
            uint32_t* opp = &g_Xpt[((size_t)(b * NCH + ch)) * PPIX + (y + 1) * 36 + 1];
#pragma unroll
            for (int i = 0; i < 4; i++) {
                int x = x0 + i;
                if (x < 34) {
                    uint32_t v = to_tf32(leaky(av[i] * (1.f / 512.f)));
                    opd[x] = v;
                    opp[x] = v;
                }
            }
        }
    }
}

// ============================================================================
// 3x3 conv via tf32 mma; cp.async 2-stage double-buffered fills
// dyn smem: Xs[2][16][328] then Ws[2][5760]  (88064 bytes)
// ============================================================================
__device__ __forceinline__ void conv_fill(const uint32_t* Xin, const uint32_t* Wtile,
                                          uint32_t* Xs_s, uint32_t* Ws_s,
                                          int ch, int IC, int t) {
    int c = t >> 4, q0 = t & 15;
    int cc = IC - ch * 16;
    const uint32_t* src = Xin + (size_t)(ch * 16 + c) * PPIX;
    uint32_t xd = sptr(Xs_s + c * 328);
    if (c < cc) { for (int q = q0; q < 81; q += 16) CPA16(xd + q * 16, src + q * 4); }
    else        { for (int q = q0; q < 81; q += 16) CPA16Z(xd + q * 16, src); }
    const uint32_t* wsrc = Wtile + (size_t)ch * WTILE;
    uint32_t wd = sptr(Ws_s);
    for (int i = t; i < 1440; i += 256) CPA16(wd + i * 16, wsrc + i * 4);
}

__global__ __launch_bounds__(256) void convT_k(const float* __restrict__ Bi,
                                               int IC, int chunks, int wbase,
                                               int IN_OFF, int OUT_OFF) {
    int b   = blockIdx.x;
    int ocb = blockIdx.y;
    extern __shared__ uint32_t dyn[];
    uint32_t* Xsb = dyn;             // 2 * 5248
    uint32_t* Wsb = dyn + 10496;     // 2 * 5760

    int t = threadIdx.x;
    int wid = t >> 5, lane = t & 31;
    int mw = wid & 1, nw = wid >> 1;
    int gid = lane >> 2, tig = lane & 3;

    float acc[8][4] = {};

    int offp[8];
#pragma unroll
    for (int j = 0; j < 8; j++) {
        int p = nw * 64 + j * 8 + gid;
        if (p > 237) p = 237;
        offp[j] = (p / 34) * 36 + (p % 34);
    }

    const uint32_t* Xin = g_Xpt + ((size_t)b * NCH + IN_OFF) * PPIX;
    const uint32_t* Wtile = g_Wc + (size_t)(wbase + ocb * chunks) * WTILE;

    conv_fill(Xin, Wtile, Xsb, Wsb, 0, IC, t);
    CPCOMMIT();

    int buf = 0;
    for (int ch = 0; ch < chunks; ch++) {
        if (ch + 1 < chunks)
            conv_fill(Xin, Wtile, Xsb + (buf ^ 1) * 5248, Wsb + (buf ^ 1) * 5760,
                      ch + 1, IC, t);
        CPCOMMIT();
        CPWAIT1();
        __syncthreads();

        const uint32_t* Xs = Xsb + buf * 5248;
        const uint32_t* Ws = Wsb + buf * 5760;
#pragma unroll
        for (int kg = 0; kg < 2; kg++) {
            int icb = kg * 8;
#pragma unroll
            for (int ky = 0; ky < 3; ky++)
#pragma unroll
                for (int kx = 0; kx < 3; kx++) {
                    int kk  = ky * 3 + kx;
                    int kof = ky * 36 + kx;
                    uint32_t a0 = Ws[kk * 640 + (icb + tig    ) * 40 + mw * 16 + gid];
                    uint32_t a1 = Ws[kk * 640 + (icb + tig    ) * 40 + mw * 16 + gid + 8];
                    uint32_t a2 = Ws[kk * 640 + (icb + tig + 4) * 40 + mw * 16 + gid];
                    uint32_t a3 = Ws[kk * 640 + (icb + tig + 4) * 40 + mw * 16 + gid + 8];
#pragma unroll
                    for (int j = 0; j < 8; j++) {
                        uint32_t b0 = Xs[(icb + tig    ) * 328 + offp[j] + kof];
                        uint32_t b1 = Xs[(icb + tig + 4) * 328 + offp[j] + kof];
                        mma_tf32(acc[j], a0, a1, a2, a3, b0, b1);
                    }
                }
        }
        __syncthreads();
        buf ^= 1;
    }

    // epilogue: bias + leaky, tf32 dual store
    int oc0 = ocb * 32 + mw * 16 + gid;
    int oc1 = oc0 + 8;
    float bi0 = Bi[oc0], bi1 = Bi[oc1];
    uint32_t* o0d = g_Xdt + (size_t)b * KPAD + (OUT_OFF + oc0) * PIX;
    uint32_t* o1d = g_Xdt + (size_t)b * KPAD + (OUT_OFF + oc1) * PIX;
    uint32_t* o0p = g_Xpt + ((size_t)b * NCH + OUT_OFF + oc0) * PPIX;
    uint32_t* o1p = g_Xpt + ((size_t)b * NCH + OUT_OFF + oc1) * PPIX;
#pragma unroll
    for (int j = 0; j < 8; j++) {
        int p = nw * 64 + j * 8 + tig * 2;
        if (p < 238) {
            int p1 = p + 1;
            int off0 = (p / 34 + 1) * 36 + (p % 34 + 1);
            int off1 = (p1 / 34 + 1) * 36 + (p1 % 34 + 1);
            uint32_t v00 = to_tf32(leaky(acc[j][0] + bi0));
            uint32_t v01 = to_tf32(leaky(acc[j][1] + bi0));
            uint32_t v10 = to_tf32(leaky(acc[j][2] + bi1));
            uint32_t v11 = to_tf32(leaky(acc[j][3] + bi1));
            o0d[p] = v00;  o0d[p1] = v01;
            o1d[p] = v10;  o1d[p1] = v11;
            o0p[off0] = v00; o0p[off1] = v01;
            o1p[off0] = v10; o1p[off1] = v11;
        }
    }
}

// ============================================================================
// fc1 via tf32 mma, cp.async double-buffered, raw-fp32 W (HW tf32 truncation)
// dyn smem: Xs[2][128][36] then Ws[2][64][36]  (55296 bytes)
// ============================================================================
__device__ __forceinline__ void fc1_fill(const float* __restrict__ Wf,
                                         uint32_t* Xs_s, uint32_t* Ws_s,
                                         int nb, int kk0, int t) {
    // X: 128 rows x 32 k, 16B ops
    for (int i = t; i < 1024; i += 256) {
        int row = i >> 3, s = i & 7;
        CPA16(sptr(Xs_s + row * 36 + s * 4), g_Xdt + (size_t)row * KPAD + kk0 + s * 4);
    }
    // W: 64 rows x 32 k, 8B ops (KTOT rows only 8B-aligned); clamp last-row overrun
    for (int i = t; i < 1024; i += 256) {
        int row = i >> 4, s = i & 15;
        size_t off = (size_t)(nb + row) * KTOT + kk0 + s * 2;
        if (off + 2 > (size_t)512 * KTOT) off = 0;   // pad region: X=0 anyway
        CPA8(sptr(Ws_s + row * 36 + s * 2), Wf + off);
    }
}

__global__ __launch_bounds__(256) void fc1T_k(const float* __restrict__ Wf) {
    int ntile = blockIdx.x, ks = blockIdx.y;
    int nb = ntile * 64;
    int k0 = ks * KSP;
    extern __shared__ uint32_t dyn[];
    uint32_t* Xsb = dyn;             // 2 * 4608
    uint32_t* Wsb = dyn + 9216;      // 2 * 2304

    int t = threadIdx.x;
    int wid = t >> 5, lane = t & 31;
    int gid = lane >> 2, tig = lane & 3;
    int mwarp = wid & 3, nwarp = wid >> 2;
    int m0 = mwarp * 32, n0 = nwarp * 32;

    float acc[2][4][4] = {};

    fc1_fill(Wf, Xsb, Wsb, nb, k0, t);
    CPCOMMIT();

    int buf = 0;
    for (int ch = 0; ch < NCHUNK; ch++) {
        if (ch + 1 < NCHUNK)
            fc1_fill(Wf, Xsb + (buf ^ 1) * 4608, Wsb + (buf ^ 1) * 2304,
                     nb, k0 + (ch + 1) * 32, t);
        CPCOMMIT();
        CPWAIT1();
        __syncthreads();

        const uint32_t* Xs = Xsb + buf * 4608;
        const uint32_t* Ws = Wsb + buf * 2304;
#pragma unroll
        for (int k8 = 0; k8 < 4; k8++) {
            int kb = k8 * 8;
            uint32_t a[2][4];
#pragma unroll
            for (int mi = 0; mi < 2; mi++) {
                int m = m0 + mi * 16;
                a[mi][0] = Xs[(m + gid    ) * 36 + kb + tig];
                a[mi][1] = Xs[(m + gid + 8) * 36 + kb + tig];
                a[mi][2] = Xs[(m + gid    ) * 36 + kb + tig + 4];
                a[mi][3] = Xs[(m + gid + 8) * 36 + kb + tig + 4];
            }
#pragma unroll
            for (int nj = 0; nj < 4; nj++) {
                int n = n0 + nj * 8;
                uint32_t b0 = Ws[(n + gid) * 36 + kb + tig];
                uint32_t b1 = Ws[(n + gid) * 36 + kb + tig + 4];
#pragma unroll
                for (int mi = 0; mi < 2; mi++)
                    mma_tf32(acc[mi][nj], a[mi][0], a[mi][1], a[mi][2], a[mi][3], b0, b1);
            }
        }
        __syncthreads();
        buf ^= 1;
    }

    float* pp = g_part + (size_t)ks * 65536;
#pragma unroll
    for (int mi = 0; mi < 2; mi++) {
        int m = m0 + mi * 16;
#pragma unroll
        for (int nj = 0; nj < 4; nj++) {
            int col = nb + n0 + nj * 8 + 2 * tig;
            *(float2*)&pp[(size_t)(m + gid    ) * 512 + col] =
                make_float2(acc[mi][nj][0], acc[mi][nj][1]);
            *(float2*)&pp[(size_t)(m + gid + 8) * 512 + col] =
                make_float2(acc[mi][nj][2], acc[mi][nj][3]);
        }
    }
}

__global__ void fc1red_k(const float* __restrict__ bias) {
    int i = blockIdx.x * 256 + threadIdx.x;
    float a = 0.f;
#pragma unroll 8
    for (int ks = 0; ks < KSPLIT; ks++) a += g_part[(size_t)ks * 65536 + i];
    g_fc1[i] = leaky(a + bias[i & 511]);
}

// ============================================================================
// l1 / r1 (FFMA2, small)
// ============================================================================
__global__ __launch_bounds__(256, 2) void l1r1_k(const float* __restrict__ wl1,
                                                 const float* __restrict__ bl1,
                                                 const float* __restrict__ wr1,
                                                 const float* __restrict__ br1) {
    int side = blockIdx.x, ntile = blockIdx.y;
    int nb = ntile * 128;
    const float* Wp = side ? wr1 : wl1;
    const float* Bp = side ? br1 : bl1;
    __shared__ __align__(16) float Xs[16][132];
    __shared__ __align__(16) float Ws[16][132];
    int t = threadIdx.x, tn = t & 15, tb = t >> 4, b0 = tb * 8, n0 = tn * 8;
    ull acc[8][4] = {};

    for (int kk0 = 0; kk0 < 512; kk0 += 16) {
        for (int i = t; i < 2048; i += 256) {
            int k = i & 15, row = i >> 4;
            Xs[k][row] = g_fc1[(size_t)row * 512 + kk0 + k];
            Ws[k][row] = Wp[(size_t)(nb + row) * 512 + kk0 + k];
        }
        __syncthreads();
#pragma unroll 4
        for (int kk = 0; kk < 16; kk++) {
            float4 xa = *(const float4*)&Xs[kk][b0];
            float4 xb = *(const float4*)&Xs[kk][b0 + 4];
            float4 wa = *(const float4*)&Ws[kk][n0];
            float4 wb = *(const float4*)&Ws[kk][n0 + 4];
            ull xd[8] = {fdup(xa.x), fdup(xa.y), fdup(xa.z), fdup(xa.w),
                         fdup(xb.x), fdup(xb.y), fdup(xb.z), fdup(xb.w)};
            ull w2[4] = {fpack(wa.x, wa.y), fpack(wa.z, wa.w),
                         fpack(wb.x, wb.y), fpack(wb.z, wb.w)};
#pragma unroll
            for (int i = 0; i < 8; i++)
#pragma unroll
                for (int j = 0; j < 4; j++)
                    fma2(acc[i][j], w2[j], xd[i]);
        }
        __syncthreads();
    }

#pragma unroll
    for (int i = 0; i < 8; i++)
#pragma unroll
        for (int j = 0; j < 4; j++) {
            float lo, hi; funpack(acc[i][j], lo, hi);
            int n = nb + n0 + 2 * j;
            float* p = &g_h[(size_t)side * (B_ * 256) + (size_t)(b0 + i) * 256 + n];
            p[0] = leaky(lo + Bp[n]);
            p[1] = leaky(hi + Bp[n + 1]);
        }
}

// ============================================================================
// heads + quat distance + mean
// ============================================================================
__global__ void heads2_k(const float* __restrict__ wl2, const float* __restrict__ bl2,
                         const float* __restrict__ wr2, const float* __restrict__ br2,
                         const float* __restrict__ lt,  const float* __restrict__ rt) {
    int b = blockIdx.x, t = threadIdx.x;
    __shared__ float hl[256], hr[256], q[8];
    hl[t] = g_h[(size_t)b * 256 + t];
    hr[t] = g_h[(size_t)(B_ * 256) + (size_t)b * 256 + t];
    __syncthreads();

    int wrp = t >> 5, lane = t & 31;
    const float* w   = (wrp < 4) ? wl2 : wr2;
    const float* src = (wrp < 4) ? hl : hr;
    int i = wrp & 3;
    float s = 0.f;
    for (int j = lane; j < 256; j += 32) s += w[i * 256 + j] * src[j];
#pragma unroll
    for (int off = 16; off > 0; off >>= 1) s += __shfl_down_sync(0xffffffffu, s, off);
    if (lane == 0) q[wrp] = s + ((wrp < 4) ? bl2[i] : br2[i]);
    __syncthreads();

    if (t == 0) {
#pragma unroll
        for (int side = 0; side < 2; side++) {
            float qw = q[side * 4 + 0], qx = q[side * 4 + 1];
            float qy = q[side * 4 + 2], qz = q[side * 4 + 3];
            float nn = sqrtf(qw * qw + qx * qx + qy * qy + qz * qz);
            nn = fmaxf(nn, 1e-12f);
            qw /= nn; qx /= nn; qy /= nn; qz /= nn;
            const float* tgt = (side == 0 ? lt : rt) + (size_t)b * 4;
            float rw = tgt[0], rx = -tgt[1], ry = -tgt[2], rz = -tgt[3];
            float tw = qw * rw - qx * rx - qy * ry - qz * rz;
            float tx = qw * rx + qx * rw + qy * rz - qz * ry;
            float ty = qw * ry - qx * rz + qy * rw + qz * rx;
            float tz = qw * rz + qx * ry - qy * rx + qz * rw;
            float ang = 2.f * atan2f(sqrtf(tx * tx + ty * ty + tz * tz + 1e-12f), fabsf(tw));
            g_ang[side * B_ + b] = ang;
        }
    }
}

__global__ void mean_k(float* __restrict__ out) {
    __shared__ float sl[128], sr[128];
    int t = threadIdx.x;
    sl[t] = g_ang[t];
    sr[t] = g_ang[128 + t];
    __syncthreads();
    for (int s = 64; s > 0; s >>= 1) {
        if (t < s) { sl[t] += sl[t + s]; sr[t] += sr[t + s]; }
        __syncthreads();
    }
    if (t == 0) { out[0] = sl[0] * (1.f / 128.f); out[1] = sr[0] * (1.f / 128.f); }
}

// ============================================================================
extern "C" void kernel_launch(void* const* d_in, const int* in_sizes, int n_in,
                              void* d_out, int out_size) {
    (void)in_sizes; (void)n_in; (void)out_size;
    const float* left  = (const float*)d_in[0];
    const float* right = (const float*)d_in[1];
    const float* lt    = (const float*)d_in[2];
    const float* rt    = (const float*)d_in[3];
    const float* w6[5] = {(const float*)d_in[4],  (const float*)d_in[6],
                          (const float*)d_in[8],  (const float*)d_in[10],
                          (const float*)d_in[12]};
    const float* b6[5] = {(const float*)d_in[5],  (const float*)d_in[7],
                          (const float*)d_in[9],  (const float*)d_in[11],
                          (const float*)d_in[13]};
    const float* wfc1 = (const float*)d_in[14];
    const float* bfc1 = (const float*)d_in[15];
    const float* wl1  = (const float*)d_in[16];
    const float* bl1  = (const float*)d_in[17];
    const float* wr1  = (const float*)d_in[18];
    const float* br1  = (const float*)d_in[19];
    const float* wl2  = (const float*)d_in[20];
    const float* bl2  = (const float*)d_in[21];
    const float* wr2  = (const float*)d_in[22];
    const float* br2  = (const float*)d_in[23];
    float* out = (float*)d_out;

    static bool attr_done = false;
    if (!attr_done) {
        cudaFuncSetAttribute(convT_k, cudaFuncAttributeMaxDynamicSharedMemorySize, 88064);
        cudaFuncSetAttribute(fc1T_k,  cudaFuncAttributeMaxDynamicSharedMemorySize, 55296);
        attr_done = true;
    }

    const int IC[5]    = {81, 209, 337, 433, 497};
    const int INO[5]   = {448, 320, 192, 96, 32};
    const int OUTO[5]  = {320, 192, 96, 32, 0};
    const int OCB[5]   = {4, 4, 3, 2, 1};
    const int CHK[5]   = {6, 14, 22, 28, 32};
    const int WBASE[5] = {0, 24, 80, 146, 202};   // tile offsets

    wprep_all<<<234, 256>>>(w6[0], w6[1], w6[2], w6[3], w6[4]);
    corr_k<<<B_, 576>>>(left, right);

    for (int l = 0; l < 5; l++)
        convT_k<<<dim3(B_, OCB[l]), 256, 88064>>>(b6[l], IC[l], CHK[l], WBASE[l],
                                                  INO[l], OUTO[l]);

    fc1T_k<<<dim3(8, KSPLIT), 256, 55296>>>(wfc1);
    fc1red_k<<<256, 256>>>(bfc1);
    l1r1_k<<<dim3(2, 2), 256>>>(wl1, bl1, wr1, br1);
    heads2_k<<<B_, 256>>>(wl2, bl2, wr2, br2, lt, rt);
    mean_k<<<1, 128>>>(out);
}

// round 5
// speedup vs baseline: 3.3912x; 1.3396x over previous
#include <cuda_runtime.h>
#include <cstdint>

#define B_   128
#define C_   512
#define PIX  238            // 7*34
#define NCH  529
#define KTOT (NCH*PIX)      // 125902
#define KPAD 125952         // padded dense row stride (16B-aligned rows)
#define KSPLIT 32
#define KSP  3936
#define NCHUNK 123          // KSP/32
#define NPLANE 324          // padded 9*36 plane positions
#define NCHK 34             // global 16-channel chunks covering 529 (+15 zero)
#define XP2_CH (NPLANE * 8) // 2592 words per (b,chunk) plane
#define WCT 2304            // 9 taps * 32 oc * 8 kpair words per tile

// ---------------- scratch (device globals; no allocations allowed) ----------
__device__ uint32_t g_Xdt[B_ * KPAD];            // dense activations, tf32 bits (fc1)
__device__ uint32_t g_Xp2[B_ * NCHK * XP2_CH];   // padded bf16 pair-interleaved (convs)
__device__ uint32_t g_Wc2[234 * WCT];            // prepped conv weights, bf16 pairs
__device__ float g_part[KSPLIT * B_ * 512];
__device__ float g_fc1[B_ * 512];
__device__ float g_h[2 * B_ * 256];
__device__ float g_ang[2 * B_];

typedef unsigned long long ull;

__device__ __forceinline__ float leaky(float x) { return x >= 0.f ? x : 0.1f * x; }

__device__ __forceinline__ ull fpack(float lo, float hi) {
    ull r; asm("mov.b64 %0, {%1, %2};" : "=l"(r) : "f"(lo), "f"(hi)); return r;
}
__device__ __forceinline__ ull fdup(float v) { return fpack(v, v); }
__device__ __forceinline__ void funpack(ull p, float& lo, float& hi) {
    asm("mov.b64 {%0, %1}, %2;" : "=f"(lo), "=f"(hi) : "l"(p));
}
__device__ __forceinline__ void fma2(ull& d, ull a, ull b) {
    asm("fma.rn.f32x2 %0, %1, %2, %3;" : "=l"(d) : "l"(a), "l"(b), "l"(d));
}
__device__ __forceinline__ uint32_t to_tf32(float f) {
    uint32_t r; asm("cvt.rna.tf32.f32 %0, %1;" : "=r"(r) : "f"(f)); return r;
}
__device__ __forceinline__ uint16_t f2bf(float f) {           // round-to-nearest-even
    uint32_t u = __float_as_uint(f);
    return (uint16_t)((u + 0x7fffu + ((u >> 16) & 1u)) >> 16);
}
__device__ __forceinline__ uint32_t f2bf2(float lo, float hi) {
    return (uint32_t)f2bf(lo) | ((uint32_t)f2bf(hi) << 16);
}
__device__ __forceinline__ void mma_tf32(float* c,
                                         uint32_t a0, uint32_t a1, uint32_t a2, uint32_t a3,
                                         uint32_t b0, uint32_t b1) {
    asm volatile("mma.sync.aligned.m16n8k8.row.col.f32.tf32.tf32.f32 "
                 "{%0,%1,%2,%3}, {%4,%5,%6,%7}, {%8,%9}, {%0,%1,%2,%3};"
                 : "+f"(c[0]), "+f"(c[1]), "+f"(c[2]), "+f"(c[3])
                 : "r"(a0), "r"(a1), "r"(a2), "r"(a3), "r"(b0), "r"(b1));
}
__device__ __forceinline__ void mma_bf16(float* c,
                                         uint32_t a0, uint32_t a1, uint32_t a2, uint32_t a3,
                                         uint32_t b0, uint32_t b1) {
    asm volatile("mma.sync.aligned.m16n8k16.row.col.f32.bf16.bf16.f32 "
                 "{%0,%1,%2,%3}, {%4,%5,%6,%7}, {%8,%9}, {%0,%1,%2,%3};"
                 : "+f"(c[0]), "+f"(c[1]), "+f"(c[2]), "+f"(c[3])
                 : "r"(a0), "r"(a1), "r"(a2), "r"(a3), "r"(b0), "r"(b1));
}
__device__ __forceinline__ uint32_t sptr(const void* p) {
    return (uint32_t)__cvta_generic_to_shared(p);
}
#define CPA16(dst, src)  asm volatile("cp.async.ca.shared.global [%0], [%1], 16;"    :: "r"(dst), "l"(src))
#define CPA8(dst, src)   asm volatile("cp.async.ca.shared.global [%0], [%1], 8;"     :: "r"(dst), "l"(src))
#define CPCOMMIT()       asm volatile("cp.async.commit_group;")
#define CPWAIT1()        asm volatile("cp.async.wait_group 1;" ::: "memory")

// ============================================================================
// weight prep: all 5 layers -> pair-packed bf16 tiles [tap][oc][kpair]
// ============================================================================
__global__ void wprep_all(const float* __restrict__ w0, const float* __restrict__ w1,
                          const float* __restrict__ w2, const float* __restrict__ w3,
                          const float* __restrict__ w4) {
    int tile = blockIdx.x;
    const float* W; int IC, chunks, tbase;
    if      (tile <  24) { W = w0; IC =  81; chunks =  6; tbase =   0; }
    else if (tile <  80) { W = w1; IC = 209; chunks = 14; tbase =  24; }
    else if (tile < 146) { W = w2; IC = 337; chunks = 22; tbase =  80; }
    else if (tile < 202) { W = w3; IC = 433; chunks = 28; tbase = 146; }
    else                 { W = w4; IC = 497; chunks = 32; tbase = 202; }
    int rel = tile - tbase, ocb = rel / chunks, ch = rel % chunks;
    uint32_t* out = g_Wc2 + (size_t)tile * WCT;
    for (int i = threadIdx.x; i < WCT; i += 256) {
        int tap = i >> 8, rem = i & 255, oc = rem >> 3, kp = rem & 7;
        int ic0 = ch * 16 + kp * 2;
        float v0 = 0.f, v1 = 0.f;
        const float* wrow = W + ((size_t)(ocb * 32 + oc) * IC) * 9;
        if (ic0     < IC) v0 = wrow[(ic0    ) * 9 + tap];
        if (ic0 + 1 < IC) v1 = wrow[(ic0 + 1) * 9 + tap];
        out[i] = f2bf2(v0, v1);
    }
}

// ============================================================================
// corr81 + leaky -> channels [448,529): tf32 dense + bf16 pair-interleaved
// ============================================================================
__global__ __launch_bounds__(576) void corr_k(const float* __restrict__ L,
                                              const float* __restrict__ R) {
    int b = blockIdx.x;
    __shared__ __align__(16) float Ls[8][7][36];
    __shared__ __align__(16) float Rs[8][7][44];
    int t = threadIdx.x;
    int g  = t % 9;
    int dy = (t / 9) % 9;
    int y  = t / 81;
    int x0 = g * 4;

    for (int i = t; i < 8 * 7 * 44; i += 576) ((float*)Rs)[i] = 0.f;
    for (int i = t; i < 8 * 7 * 36; i += 576) ((float*)Ls)[i] = 0.f;
    __syncthreads();

    ull acc2[9][2] = {};

    int ry = y + dy - 4;
    bool valid = (y < 7) && (ry >= 0) && (ry < 7);
    const float* Lb = L + (size_t)b * C_ * PIX;
    const float* Rb = R + (size_t)b * C_ * PIX;

    for (int c0 = 0; c0 < C_; c0 += 8) {
        for (int i = t; i < 8 * PIX; i += 576) {
            int c = i / PIX, p = i % PIX;
            Ls[c][p / 34][p % 34]       = Lb[(size_t)(c0 + c) * PIX + p];
            Rs[c][p / 34][(p % 34) + 4] = Rb[(size_t)(c0 + c) * PIX + p];
        }
        __syncthreads();
        if (valid) {
#pragma unroll
            for (int c = 0; c < 8; c++) {
                float4 l4 = *(const float4*)&Ls[c][y][x0];
                float4 r0 = *(const float4*)&Rs[c][ry][x0];
                float4 r1 = *(const float4*)&Rs[c][ry][x0 + 4];
                float4 r2 = *(const float4*)&Rs[c][ry][x0 + 8];
                ull lp0 = fpack(l4.x, l4.y), lp1 = fpack(l4.z, l4.w);
                float rv[12] = {r0.x, r0.y, r0.z, r0.w,
                                r1.x, r1.y, r1.z, r1.w,
                                r2.x, r2.y, r2.z, r2.w};
#pragma unroll
                for (int dx = 0; dx < 9; dx++) {
                    fma2(acc2[dx][0], lp0, fpack(rv[dx],     rv[dx + 1]));
                    fma2(acc2[dx][1], lp1, fpack(rv[dx + 2], rv[dx + 3]));
                }
            }
        }
        __syncthreads();
    }

    if (y < 7) {
        uint16_t* Xp16 = (uint16_t*)g_Xp2;
#pragma unroll
        for (int dx = 0; dx < 9; dx++) {
            int ch = 448 + dy * 9 + dx;
            float av[4];
            funpack(acc2[dx][0], av[0], av[1]);
            funpack(acc2[dx][1], av[2], av[3]);
            uint32_t* opd = &g_Xdt[(size_t)b * KPAD + ch * PIX + y * 34];
            size_t pbase = ((size_t)(b * NCHK + (ch >> 4)) * NPLANE) * 8 + ((ch & 15) >> 1);
            int half = ch & 1;
#pragma unroll
            for (int i = 0; i < 4; i++) {
                int x = x0 + i;
                if (x < 34) {
                    float v = leaky(av[i] * (1.f / 512.f));
                    opd[x] = to_tf32(v);
                    int pos = (y + 1) * 36 + (x + 1);
                    Xp16[(pbase + (size_t)pos * 8) * 2 + half] = f2bf(v);
                }
            }
        }
    }
}

// ============================================================================
// 3x3 conv via bf16 mma.m16n8k16; cp.async 2-stage double buffering
// smem per stage: Xs 324*12 words + Ws 9*32*12 words = 7344 w; x2 = 58752 B
// ============================================================================
#define XS_W (NPLANE * 12)   // 3888
#define WS_W (9 * 32 * 12)   // 3456
#define STG_W (XS_W + WS_W)  // 7344

__device__ __forceinline__ void convB_fill(const uint32_t* Xsrc, const uint32_t* Wt,
                                           uint32_t* Xs, uint32_t* Ws, int ch, int t) {
    const uint32_t* xs = Xsrc + (size_t)ch * XP2_CH;
    for (int i = t; i < 648; i += 256) {
        int pos = i >> 1, h = i & 1;
        CPA16(sptr(Xs + pos * 12 + h * 4), xs + pos * 8 + h * 4);
    }
    const uint32_t* ws = Wt + (size_t)ch * WCT;
    for (int i = t; i < 576; i += 256) {
        int to = i >> 1, h = i & 1;
        CPA16(sptr(Ws + to * 12 + h * 4), ws + to * 8 + h * 4);
    }
}

__global__ __launch_bounds__(256) void convB_k(const float* __restrict__ Bi,
                                               int chunks, int wtile0,
                                               int chunk0in, int OUT_OFF) {
    int b   = blockIdx.x;
    int ocb = blockIdx.y;
    extern __shared__ uint32_t dyn[];

    int t = threadIdx.x;
    int wid = t >> 5, lane = t & 31;
    int mw = wid & 1, nw = wid >> 1;
    int gid = lane >> 2, tig = lane & 3;

    float acc[8][4] = {};

    int offp[8];
#pragma unroll
    for (int j = 0; j < 8; j++) {
        int p = nw * 64 + j * 8 + gid;
        if (p > 237) p = 237;
        offp[j] = (p / 34) * 36 + (p % 34);
    }

    const uint32_t* Xsrc = g_Xp2 + (size_t)(b * NCHK + chunk0in) * XP2_CH;
    const uint32_t* Wt   = g_Wc2 + (size_t)(wtile0 + ocb * chunks) * WCT;

    convB_fill(Xsrc, Wt, dyn, dyn + XS_W, 0, t);
    CPCOMMIT();

    int buf = 0;
    for (int ch = 0; ch < chunks; ch++) {
        if (ch + 1 < chunks)
            convB_fill(Xsrc, Wt, dyn + (buf ^ 1) * STG_W, dyn + (buf ^ 1) * STG_W + XS_W,
                       ch + 1, t);
        CPCOMMIT();
        CPWAIT1();
        __syncthreads();

        const uint32_t* Xs = dyn + buf * STG_W;
        const uint32_t* Ws = dyn + buf * STG_W + XS_W;
#pragma unroll
        for (int ky = 0; ky < 3; ky++)
#pragma unroll
            for (int kx = 0; kx < 3; kx++) {
                int kk  = ky * 3 + kx;
                int kof = ky * 36 + kx;
                int wb  = (kk * 32 + mw * 16 + gid) * 12 + tig;
                uint32_t a0 = Ws[wb];
                uint32_t a1 = Ws[wb + 96];        // +8 oc rows * 12
                uint32_t a2 = Ws[wb + 4];         // kpair tig+4
                uint32_t a3 = Ws[wb + 100];
#pragma unroll
                for (int j = 0; j < 8; j++) {
                    int xb = (offp[j] + kof) * 12 + tig;
                    uint32_t b0 = Xs[xb];
                    uint32_t b1 = Xs[xb + 4];
                    mma_bf16(acc[j], a0, a1, a2, a3, b0, b1);
                }
            }
        __syncthreads();
        buf ^= 1;
    }

    // epilogue: bias + leaky; tf32 dense + bf16 pair-interleaved stores
    int oc0 = ocb * 32 + mw * 16 + gid;
    int oc1 = oc0 + 8;
    float bi0 = Bi[oc0], bi1 = Bi[oc1];
    uint32_t* o0d = g_Xdt + (size_t)b * KPAD + (OUT_OFF + oc0) * PIX;
    uint32_t* o1d = g_Xdt + (size_t)b * KPAD + (OUT_OFF + oc1) * PIX;
    uint16_t* Xp16 = (uint16_t*)g_Xp2;
    int chunkOut = (OUT_OFF >> 4) + ocb * 2 + mw;
    size_t pb = ((size_t)(b * NCHK + chunkOut) * NPLANE) * 8;
    int kp0 = gid >> 1, kp1 = kp0 + 4, half = gid & 1;
#pragma unroll
    for (int j = 0; j < 8; j++) {
        int p = nw * 64 + j * 8 + tig * 2;
        if (p < 238) {
            int p1 = p + 1;
            int pos0 = (p / 34 + 1) * 36 + (p % 34 + 1);
            int pos1 = (p1 / 34 + 1) * 36 + (p1 % 34 + 1);
            float v00 = leaky(acc[j][0] + bi0);
            float v01 = leaky(acc[j][1] + bi0);
            float v10 = leaky(acc[j][2] + bi1);
            float v11 = leaky(acc[j][3] + bi1);
            o0d[p] = to_tf32(v00);  o0d[p1] = to_tf32(v01);
            o1d[p] = to_tf32(v10);  o1d[p1] = to_tf32(v11);
            Xp16[(pb + (size_t)pos0 * 8 + kp0) * 2 + half] = f2bf(v00);
            Xp16[(pb + (size_t)pos1 * 8 + kp0) * 2 + half] = f2bf(v01);
            Xp16[(pb + (size_t)pos0 * 8 + kp1) * 2 + half] = f2bf(v10);
            Xp16[(pb + (size_t)pos1 * 8 + kp1) * 2 + half] = f2bf(v11);
        }
    }
}

// ============================================================================
// fc1 via tf32 mma, cp.async double-buffered (unchanged from R4)
// ============================================================================
__device__ __forceinline__ void fc1_fill(const float* __restrict__ Wf,
                                         uint32_t* Xs_s, uint32_t* Ws_s,
                                         int nb, int kk0, int t) {
    for (int i = t; i < 1024; i += 256) {
        int row = i >> 3, s = i & 7;
        CPA16(sptr(Xs_s + row * 36 + s * 4), g_Xdt + (size_t)row * KPAD + kk0 + s * 4);
    }
    for (int i = t; i < 1024; i += 256) {
        int row = i >> 4, s = i & 15;
        size_t off = (size_t)(nb + row) * KTOT + kk0 + s * 2;
        if (off + 2 > (size_t)512 * KTOT) off = 0;
        CPA8(sptr(Ws_s + row * 36 + s * 2), Wf + off);
    }
}

__global__ __launch_bounds__(256) void fc1T_k(const float* __restrict__ Wf) {
    int ntile = blockIdx.x, ks = blockIdx.y;
    int nb = ntile * 64;
    int k0 = ks * KSP;
    extern __shared__ uint32_t dyn[];
    uint32_t* Xsb = dyn;
    uint32_t* Wsb = dyn + 9216;

    int t = threadIdx.x;
    int wid = t >> 5, lane = t & 31;
    int gid = lane >> 2, tig = lane & 3;
    int mwarp = wid & 3, nwarp = wid >> 2;
    int m0 = mwarp * 32, n0 = nwarp * 32;

    float acc[2][4][4] = {};

    fc1_fill(Wf, Xsb, Wsb, nb, k0, t);
    CPCOMMIT();

    int buf = 0;
    for (int ch = 0; ch < NCHUNK; ch++) {
        if (ch + 1 < NCHUNK)
            fc1_fill(Wf, Xsb + (buf ^ 1) * 4608, Wsb + (buf ^ 1) * 2304,
                     nb, k0 + (ch + 1) * 32, t);
        CPCOMMIT();
        CPWAIT1();
        __syncthreads();

        const uint32_t* Xs = Xsb + buf * 4608;
        const uint32_t* Ws = Wsb + buf * 2304;
#pragma unroll
        for (int k8 = 0; k8 < 4; k8++) {
            int kb = k8 * 8;
            uint32_t a[2][4];
#pragma unroll
            for (int mi = 0; mi < 2; mi++) {
                int m = m0 + mi * 16;
                a[mi][0] = Xs[(m + gid    ) * 36 + kb + tig];
                a[mi][1] = Xs[(m + gid + 8) * 36 + kb + tig];
                a[mi][2] = Xs[(m + gid    ) * 36 + kb + tig + 4];
                a[mi][3] = Xs[(m + gid + 8) * 36 + kb + tig + 4];
            }
#pragma unroll
            for (int nj = 0; nj < 4; nj++) {
                int n = n0 + nj * 8;
                uint32_t b0 = Ws[(n + gid) * 36 + kb + tig];
                uint32_t b1 = Ws[(n + gid) * 36 + kb + tig + 4];
#pragma unroll
                for (int mi = 0; mi < 2; mi++)
                    mma_tf32(acc[mi][nj], a[mi][0], a[mi][1], a[mi][2], a[mi][3], b0, b1);
            }
        }
        __syncthreads();
        buf ^= 1;
    }

    float* pp = g_part + (size_t)ks * 65536;
#pragma unroll
    for (int mi = 0; mi < 2; mi++) {
        int m = m0 + mi * 16;
#pragma unroll
        for (int nj = 0; nj < 4; nj++) {
            int col = nb + n0 + nj * 8 + 2 * tig;
            *(float2*)&pp[(size_t)(m + gid    ) * 512 + col] =
                make_float2(acc[mi][nj][0], acc[mi][nj][1]);
            *(float2*)&pp[(size_t)(m + gid + 8) * 512 + col] =
                make_float2(acc[mi][nj][2], acc[mi][nj][3]);
        }
    }
}

__global__ void fc1red_k(const float* __restrict__ bias) {
    int i = blockIdx.x * 256 + threadIdx.x;
    float a = 0.f;
#pragma unroll 8
    for (int ks = 0; ks < KSPLIT; ks++) a += g_part[(size_t)ks * 65536 + i];
    g_fc1[i] = leaky(a + bias[i & 511]);
}

// ============================================================================
// l1 / r1 (FFMA2, small)
// ============================================================================
__global__ __launch_bounds__(256, 2) void l1r1_k(const float* __restrict__ wl1,
                                                 const float* __restrict__ bl1,
                                                 const float* __restrict__ wr1,
                                                 const float* __restrict__ br1) {
    int side = blockIdx.x, ntile = blockIdx.y;
    int nb = ntile * 128;
    const float* Wp = side ? wr1 : wl1;
    const float* Bp = side ? br1 : bl1;
    __shared__ __align__(16) float Xs[16][132];
    __shared__ __align__(16) float Ws[16][132];
    int t = threadIdx.x, tn = t & 15, tb = t >> 4, b0 = tb * 8, n0 = tn * 8;
    ull acc[8][4] = {};

    for (int kk0 = 0; kk0 < 512; kk0 += 16) {
        for (int i = t; i < 2048; i += 256) {
            int k = i & 15, row = i >> 4;
            Xs[k][row] = g_fc1[(size_t)row * 512 + kk0 + k];
            Ws[k][row] = Wp[(size_t)(nb + row) * 512 + kk0 + k];
        }
        __syncthreads();
#pragma unroll 4
        for (int kk = 0; kk < 16; kk++) {
            float4 xa = *(const float4*)&Xs[kk][b0];
            float4 xb = *(const float4*)&Xs[kk][b0 + 4];
            float4 wa = *(const float4*)&Ws[kk][n0];
            float4 wb = *(const float4*)&Ws[kk][n0 + 4];
            ull xd[8] = {fdup(xa.x), fdup(xa.y), fdup(xa.z), fdup(xa.w),
                         fdup(xb.x), fdup(xb.y), fdup(xb.z), fdup(xb.w)};
            ull w2[4] = {fpack(wa.x, wa.y), fpack(wa.z, wa.w),
                         fpack(wb.x, wb.y), fpack(wb.z, wb.w)};
#pragma unroll
            for (int i = 0; i < 8; i++)
#pragma unroll
                for (int j = 0; j < 4; j++)
                    fma2(acc[i][j], w2[j], xd[i]);
        }
        __syncthreads();
    }

#pragma unroll
    for (int i = 0; i < 8; i++)
#pragma unroll
        for (int j = 0; j < 4; j++) {
            float lo, hi; funpack(acc[i][j], lo, hi);
            int n = nb + n0 + 2 * j;
            float* p = &g_h[(size_t)side * (B_ * 256) + (size_t)(b0 + i) * 256 + n];
            p[0] = leaky(lo + Bp[n]);
            p[1] = leaky(hi + Bp[n + 1]);
        }
}

// ============================================================================
// heads + quat distance + mean
// ============================================================================
__global__ void heads2_k(const float* __restrict__ wl2, const float* __restrict__ bl2,
                         const float* __restrict__ wr2, const float* __restrict__ br2,
                         const float* __restrict__ lt,  const float* __restrict__ rt) {
    int b = blockIdx.x, t = threadIdx.x;
    __shared__ float hl[256], hr[256], q[8];
    hl[t] = g_h[(size_t)b * 256 + t];
    hr[t] = g_h[(size_t)(B_ * 256) + (size_t)b * 256 + t];
    __syncthreads();

    int wrp = t >> 5, lane = t & 31;
    const float* w   = (wrp < 4) ? wl2 : wr2;
    const float* src = (wrp < 4) ? hl : hr;
    int i = wrp & 3;
    float s = 0.f;
    for (int j = lane; j < 256; j += 32) s += w[i * 256 + j] * src[j];
#pragma unroll
    for (int off = 16; off > 0; off >>= 1) s += __shfl_down_sync(0xffffffffu, s, off);
    if (lane == 0) q[wrp] = s + ((wrp < 4) ? bl2[i] : br2[i]);
    __syncthreads();

    if (t == 0) {
#pragma unroll
        for (int side = 0; side < 2; side++) {
            float qw = q[side * 4 + 0], qx = q[side * 4 + 1];
            float qy = q[side * 4 + 2], qz = q[side * 4 + 3];
            float nn = sqrtf(qw * qw + qx * qx + qy * qy + qz * qz);
            nn = fmaxf(nn, 1e-12f);
            qw /= nn; qx /= nn; qy /= nn; qz /= nn;
            const float* tgt = (side == 0 ? lt : rt) + (size_t)b * 4;
            float rw = tgt[0], rx = -tgt[1], ry = -tgt[2], rz = -tgt[3];
            float tw = qw * rw - qx * rx - qy * ry - qz * rz;
            float tx = qw * rx + qx * rw + qy * rz - qz * ry;
            float ty = qw * ry - qx * rz + qy * rw + qz * rx;
            float tz = qw * rz + qx * ry - qy * rx + qz * rw;
            float ang = 2.f * atan2f(sqrtf(tx * tx + ty * ty + tz * tz + 1e-12f), fabsf(tw));
            g_ang[side * B_ + b] = ang;
        }
    }
}

__global__ void mean_k(float* __restrict__ out) {
    __shared__ float sl[128], sr[128];
    int t = threadIdx.x;
    sl[t] = g_ang[t];
    sr[t] = g_ang[128 + t];
    __syncthreads();
    for (int s = 64; s > 0; s >>= 1) {
        if (t < s) { sl[t] += sl[t + s]; sr[t] += sr[t + s]; }
        __syncthreads();
    }
    if (t == 0) { out[0] = sl[0] * (1.f / 128.f); out[1] = sr[0] * (1.f / 128.f); }
}

// ============================================================================
extern "C" void kernel_launch(void* const* d_in, const int* in_sizes, int n_in,
                              void* d_out, int out_size) {
    (void)in_sizes; (void)n_in; (void)out_size;
    const float* left  = (const float*)d_in[0];
    const float* right = (const float*)d_in[1];
    const float* lt    = (const float*)d_in[2];
    const float* rt    = (const float*)d_in[3];
    const float* w6[5] = {(const float*)d_in[4],  (const float*)d_in[6],
                          (const float*)d_in[8],  (const float*)d_in[10],
                          (const float*)d_in[12]};
    const float* b6[5] = {(const float*)d_in[5],  (const float*)d_in[7],
                          (const float*)d_in[9],  (const float*)d_in[11],
                          (const float*)d_in[13]};
    const float* wfc1 = (const float*)d_in[14];
    const float* bfc1 = (const float*)d_in[15];
    const float* wl1  = (const float*)d_in[16];
    const float* bl1  = (const float*)d_in[17];
    const float* wr1  = (const float*)d_in[18];
    const float* br1  = (const float*)d_in[19];
    const float* wl2  = (const float*)d_in[20];
    const float* bl2  = (const float*)d_in[21];
    const float* wr2  = (const float*)d_in[22];
    const float* br2  = (const float*)d_in[23];
    float* out = (float*)d_out;

    static bool attr_done = false;
    if (!attr_done) {
        cudaFuncSetAttribute(convB_k, cudaFuncAttributeMaxDynamicSharedMemorySize,
                             2 * STG_W * 4);
        cudaFuncSetAttribute(fc1T_k, cudaFuncAttributeMaxDynamicSharedMemorySize, 55296);
        attr_done = true;
    }

    const int INO[5]   = {448, 320, 192, 96, 32};
    const int OUTO[5]  = {320, 192, 96, 32, 0};
    const int OCB[5]   = {4, 4, 3, 2, 1};
    const int CHK[5]   = {6, 14, 22, 28, 32};
    const int WBASE[5] = {0, 24, 80, 146, 202};

    wprep_all<<<234, 256>>>(w6[0], w6[1], w6[2], w6[3], w6[4]);
    corr_k<<<B_, 576>>>(left, right);

    for (int l = 0; l < 5; l++)
        convB_k<<<dim3(B_, OCB[l]), 256, 2 * STG_W * 4>>>(b6[l], CHK[l], WBASE[l],
                                                          INO[l] >> 4, OUTO[l]);

    fc1T_k<<<dim3(8, KSPLIT), 256, 55296>>>(wfc1);
    fc1red_k<<<256, 256>>>(bfc1);
    l1r1_k<<<dim3(2, 2), 256>>>(wl1, bl1, wr1, br1);
    heads2_k<<<B_, 256>>>(wl2, bl2, wr2, br2, lt, rt);
    mean_k<<<1, 128>>>(out);
}

// round 7
// speedup vs baseline: 3.5844x; 1.0570x over previous
#include <cuda_runtime.h>
#include <cstdint>

#define B_   128
#define C_   512
#define PIX  238            // 7*34
#define NCH  529
#define KTOT (NCH*PIX)      // 125902
#define KPAD 125952         // padded dense row stride (16B-aligned rows)
#define KSPLIT 32
#define KSP  3936
#define NCHUNK 123          // KSP/32
#define NPLANE 324          // padded 9*36 plane positions
#define NCHK 34             // global 16-channel chunks covering 529 (+15 zero)
#define XP2_CH (NPLANE * 8) // 2592 words per (b,chunk) plane
#define WCT 2304            // 9 taps * 32 oc * 8 kpair words per tile

#define XS_W   (NPLANE * 12)   // 3888 words
#define WS64_W (2 * 3456)      // 6912 words (2 oc-halves)
#define STG_W  (XS_W + WS64_W) // 10800 words / 43200 B per stage

// ---------------- scratch (device globals; no allocations allowed) ----------
__device__ uint32_t g_Xdt[B_ * KPAD];            // dense activations, tf32 bits (fc1)
__device__ uint32_t g_Xp2[B_ * NCHK * XP2_CH];   // padded bf16 pair-interleaved (convs)
__device__ uint32_t g_Wc2[234 * WCT];            // prepped conv weights, bf16 pairs
__device__ float g_part[KSPLIT * B_ * 512];
__device__ float g_fc1[B_ * 512];
__device__ float g_h[2 * B_ * 256];
__device__ float g_ang[2 * B_];

typedef unsigned long long ull;

__device__ __forceinline__ float leaky(float x) { return x >= 0.f ? x : 0.1f * x; }

__device__ __forceinline__ ull fpack(float lo, float hi) {
    ull r; asm("mov.b64 %0, {%1, %2};" : "=l"(r) : "f"(lo), "f"(hi)); return r;
}
__device__ __forceinline__ ull fdup(float v) { return fpack(v, v); }
__device__ __forceinline__ void funpack(ull p, float& lo, float& hi) {
    asm("mov.b64 {%0, %1}, %2;" : "=f"(lo), "=f"(hi) : "l"(p));
}
__device__ __forceinline__ void fma2(ull& d, ull a, ull b) {
    asm("fma.rn.f32x2 %0, %1, %2, %3;" : "=l"(d) : "l"(a), "l"(b), "l"(d));
}
__device__ __forceinline__ uint32_t to_tf32(float f) {
    uint32_t r; asm("cvt.rna.tf32.f32 %0, %1;" : "=r"(r) : "f"(f)); return r;
}
__device__ __forceinline__ uint16_t f2bf(float f) {
    uint32_t u = __float_as_uint(f);
    return (uint16_t)((u + 0x7fffu + ((u >> 16) & 1u)) >> 16);
}
__device__ __forceinline__ uint32_t f2bf2(float lo, float hi) {
    return (uint32_t)f2bf(lo) | ((uint32_t)f2bf(hi) << 16);
}
__device__ __forceinline__ void mma_tf32(float* c,
                                         uint32_t a0, uint32_t a1, uint32_t a2, uint32_t a3,
                                         uint32_t b0, uint32_t b1) {
    asm volatile("mma.sync.aligned.m16n8k8.row.col.f32.tf32.tf32.f32 "
                 "{%0,%1,%2,%3}, {%4,%5,%6,%7}, {%8,%9}, {%0,%1,%2,%3};"
                 : "+f"(c[0]), "+f"(c[1]), "+f"(c[2]), "+f"(c[3])
                 : "r"(a0), "r"(a1), "r"(a2), "r"(a3), "r"(b0), "r"(b1));
}
__device__ __forceinline__ void mma_bf16(float* c,
                                         uint32_t a0, uint32_t a1, uint32_t a2, uint32_t a3,
                                         uint32_t b0, uint32_t b1) {
    asm volatile("mma.sync.aligned.m16n8k16.row.col.f32.bf16.bf16.f32 "
                 "{%0,%1,%2,%3}, {%4,%5,%6,%7}, {%8,%9}, {%0,%1,%2,%3};"
                 : "+f"(c[0]), "+f"(c[1]), "+f"(c[2]), "+f"(c[3])
                 : "r"(a0), "r"(a1), "r"(a2), "r"(a3), "r"(b0), "r"(b1));
}
__device__ __forceinline__ uint32_t sptr(const void* p) {
    return (uint32_t)__cvta_generic_to_shared(p);
}
#define CPA16(dst, src)  asm volatile("cp.async.ca.shared.global [%0], [%1], 16;"    :: "r"(dst), "l"(src))
#define CPA8(dst, src)   asm volatile("cp.async.ca.shared.global [%0], [%1], 8;"     :: "r"(dst), "l"(src))
#define CPCOMMIT()       asm volatile("cp.async.commit_group;")
#define CPWAIT1()        asm volatile("cp.async.wait_group 1;" ::: "memory")

// ============================================================================
// weight prep: all 5 layers -> pair-packed bf16 tiles [tap][oc32][kpair]
// ============================================================================
__global__ void wprep_all(const float* __restrict__ w0, const float* __restrict__ w1,
                          const float* __restrict__ w2, const float* __restrict__ w3,
                          const float* __restrict__ w4) {
    int tile = blockIdx.x;
    const float* W; int IC, chunks, tbase;
    if      (tile <  24) { W = w0; IC =  81; chunks =  6; tbase =   0; }
    else if (tile <  80) { W = w1; IC = 209; chunks = 14; tbase =  24; }
    else if (tile < 146) { W = w2; IC = 337; chunks = 22; tbase =  80; }
    else if (tile < 202) { W = w3; IC = 433; chunks = 28; tbase = 146; }
    else                 { W = w4; IC = 497; chunks = 32; tbase = 202; }
    int rel = tile - tbase, ocb = rel / chunks, ch = rel % chunks;
    uint32_t* out = g_Wc2 + (size_t)tile * WCT;
    for (int i = threadIdx.x; i < WCT; i += 256) {
        int tap = i >> 8, rem = i & 255, oc = rem >> 3, kp = rem & 7;
        int ic0 = ch * 16 + kp * 2;
        float v0 = 0.f, v1 = 0.f;
        const float* wrow = W + ((size_t)(ocb * 32 + oc) * IC) * 9;
        if (ic0     < IC) v0 = wrow[(ic0    ) * 9 + tap];
        if (ic0 + 1 < IC) v1 = wrow[(ic0 + 1) * 9 + tap];
        out[i] = f2bf2(v0, v1);
    }
}

// ============================================================================
// corr81 + leaky -> channels [448,529): 16-channel chunks
// ============================================================================
__global__ __launch_bounds__(576) void corr_k(const float* __restrict__ L,
                                              const float* __restrict__ R) {
    int b = blockIdx.x;
    __shared__ __align__(16) float Ls[16][7][36];
    __shared__ __align__(16) float Rs[16][7][44];
    int t = threadIdx.x;
    int g  = t % 9;
    int dy = (t / 9) % 9;
    int y  = t / 81;
    int x0 = g * 4;

    for (int i = t; i < 16 * 7 * 44; i += 576) ((float*)Rs)[i] = 0.f;
    for (int i = t; i < 16 * 7 * 36; i += 576) ((float*)Ls)[i] = 0.f;
    __syncthreads();

    ull acc2[9][2] = {};

    int ry = y + dy - 4;
    bool valid = (y < 7) && (ry >= 0) && (ry < 7);
    const float* Lb = L + (size_t)b * C_ * PIX;
    const float* Rb = R + (size_t)b * C_ * PIX;

    for (int c0 = 0; c0 < C_; c0 += 16) {
        for (int i = t; i < 16 * PIX; i += 576) {
            int c = i / PIX, p = i % PIX;
            Ls[c][p / 34][p % 34]       = Lb[(size_t)(c0 + c) * PIX + p];
            Rs[c][p / 34][(p % 34) + 4] = Rb[(size_t)(c0 + c) * PIX + p];
        }
        __syncthreads();
        if (valid) {
#pragma unroll
            for (int c = 0; c < 16; c++) {
                float4 l4 = *(const float4*)&Ls[c][y][x0];
                float4 r0 = *(const float4*)&Rs[c][ry][x0];
                float4 r1 = *(const float4*)&Rs[c][ry][x0 + 4];
                float4 r2 = *(const float4*)&Rs[c][ry][x0 + 8];
                ull lp0 = fpack(l4.x, l4.y), lp1 = fpack(l4.z, l4.w);
                float rv[12] = {r0.x, r0.y, r0.z, r0.w,
                                r1.x, r1.y, r1.z, r1.w,
                                r2.x, r2.y, r2.z, r2.w};
#pragma unroll
                for (int dx = 0; dx < 9; dx++) {
                    fma2(acc2[dx][0], lp0, fpack(rv[dx],     rv[dx + 1]));
                    fma2(acc2[dx][1], lp1, fpack(rv[dx + 2], rv[dx + 3]));
                }
            }
        }
        __syncthreads();
    }

    if (y < 7) {
        uint16_t* Xp16 = (uint16_t*)g_Xp2;
#pragma unroll
        for (int dx = 0; dx < 9; dx++) {
            int ch = 448 + dy * 9 + dx;
            float av[4];
            funpack(acc2[dx][0], av[0], av[1]);
            funpack(acc2[dx][1], av[2], av[3]);
            uint32_t* opd = &g_Xdt[(size_t)b * KPAD + ch * PIX + y * 34];
            size_t pbase = ((size_t)(b * NCHK + (ch >> 4)) * NPLANE) * 8 + ((ch & 15) >> 1);
            int half = ch & 1;
#pragma unroll
            for (int i = 0; i < 4; i++) {
                int x = x0 + i;
                if (x < 34) {
                    float v = leaky(av[i] * (1.f / 512.f));
                    opd[x] = to_tf32(v);
                    int pos = (y + 1) * 36 + (x + 1);
                    Xp16[(pbase + (size_t)pos * 8) * 2 + half] = f2bf(v);
                }
            }
        }
    }
}

// ============================================================================
// 3x3 conv, bf16 mma.m16n8k16, 64-oc block tile (warp: 32oc x 64pos),
// cp.async double-buffered; partial (32-oc) tiles use exact 16oc/warp mode.
// ============================================================================
__device__ __forceinline__ void conv64_fill(const uint32_t* Xsrc,
                                            const uint32_t* W0, const uint32_t* W1,
                                            int nhalf, uint32_t* stage, int ch, int t) {
    const uint32_t* xs = Xsrc + (size_t)ch * XP2_CH;
    for (int i = t; i < 648; i += 256) {
        int pos = i >> 1, h = i & 1;
        CPA16(sptr(stage + pos * 12 + h * 4), xs + pos * 8 + h * 4);
    }
    uint32_t* Ws = stage + XS_W;
    for (int i = t; i < nhalf * 576; i += 256) {
        int h = (i >= 576), ii = i - h * 576;
        int to = ii >> 1, hw = ii & 1;
        const uint32_t* ws = (h ? W1 : W0) + (size_t)ch * WCT;
        CPA16(sptr(Ws + h * 3456 + to * 12 + hw * 4), ws + to * 8 + hw * 4);
    }
}

__global__ __launch_bounds__(256) void convB64_k(const float* __restrict__ Bi,
                                                 int chunks, int wtile0,
                                                 int chunk0in, int OUT_OFF, int OC) {
    int b    = blockIdx.x;
    int ocb2 = blockIdx.y;
    bool partial = (ocb2 * 64 + 64 > OC);
    int nhalf = partial ? 1 : 2;
    extern __shared__ uint32_t dyn[];

    int t = threadIdx.x;
    int wid = t >> 5, lane = t & 31;
    int mw = wid & 1, nw = wid >> 1;
    int gid = lane >> 2, tig = lane & 3;

    float acc[2][8][4] = {};

    int offp[8];
#pragma unroll
    for (int j = 0; j < 8; j++) {
        int p = nw * 64 + j * 8 + gid;
        if (p > 237) p = 237;
        offp[j] = (p / 34) * 36 + (p % 34);
    }

    const uint32_t* Xsrc = g_Xp2 + (size_t)(b * NCHK + chunk0in) * XP2_CH;
    const uint32_t* W0 = g_Wc2 + (size_t)(wtile0 + (ocb2 * 2    ) * chunks) * WCT;
    const uint32_t* W1 = g_Wc2 + (size_t)(wtile0 + (ocb2 * 2 + nhalf - 1) * chunks) * WCT;

    // A-fragment row bases (without tap offset)
    int aBase0, aBase1;
    if (partial) {
        aBase0 = (mw * 16 + gid) * 12 + tig;          // half 0
        aBase1 = aBase0;                               // unused
    } else {
        aBase0 = mw * 3456 + (gid     ) * 12 + tig;    // frag 0 (oc +0)
        aBase1 = mw * 3456 + (16 + gid) * 12 + tig;    // frag 1 (oc +16)
    }

    conv64_fill(Xsrc, W0, W1, nhalf, dyn, 0, t);
    CPCOMMIT();

    int buf = 0;
    for (int ch = 0; ch < chunks; ch++) {
        if (ch + 1 < chunks)
            conv64_fill(Xsrc, W0, W1, nhalf, dyn + (buf ^ 1) * STG_W, ch + 1, t);
        CPCOMMIT();
        CPWAIT1();
        __syncthreads();

        const uint32_t* Xs = dyn + buf * STG_W;
        const uint32_t* Ws = Xs + XS_W;
        if (!partial) {
#pragma unroll
            for (int ky = 0; ky < 3; ky++)
#pragma unroll
                for (int kx = 0; kx < 3; kx++) {
                    int kk  = ky * 3 + kx;
                    int kof = ky * 36 + kx;
                    int a0b = aBase0 + kk * 384;
                    int a1b = aBase1 + kk * 384;
                    uint32_t p0 = Ws[a0b], p1 = Ws[a0b + 96];
                    uint32_t p2 = Ws[a0b + 4], p3 = Ws[a0b + 100];
                    uint32_t q0 = Ws[a1b], q1 = Ws[a1b + 96];
                    uint32_t q2 = Ws[a1b + 4], q3 = Ws[a1b + 100];
#pragma unroll
                    for (int j = 0; j < 8; j++) {
                        int xb = (offp[j] + kof) * 12 + tig;
                        uint32_t b0 = Xs[xb];
                        uint32_t b1 = Xs[xb + 4];
                        mma_bf16(acc[0][j], p0, p1, p2, p3, b0, b1);
                        mma_bf16(acc[1][j], q0, q1, q2, q3, b0, b1);
                    }
                }
        } else {
#pragma unroll
            for (int ky = 0; ky < 3; ky++)
#pragma unroll
                for (int kx = 0; kx < 3; kx++) {
                    int kk  = ky * 3 + kx;
                    int kof = ky * 36 + kx;
                    int a0b = aBase0 + kk * 384;
                    uint32_t p0 = Ws[a0b], p1 = Ws[a0b + 96];
                    uint32_t p2 = Ws[a0b + 4], p3 = Ws[a0b + 100];
#pragma unroll
                    for (int j = 0; j < 8; j++) {
                        int xb = (offp[j] + kof) * 12 + tig;
                        uint32_t b0 = Xs[xb];
                        uint32_t b1 = Xs[xb + 4];
                        mma_bf16(acc[0][j], p0, p1, p2, p3, b0, b1);
                    }
                }
        }
        __syncthreads();
        buf ^= 1;
    }

    // epilogue: bias + leaky; tf32 dense + bf16 pair-interleaved stores
    uint16_t* Xp16 = (uint16_t*)g_Xp2;
    int fmax = partial ? 1 : 2;
    int kp0 = gid >> 1, kp1 = kp0 + 4, half = gid & 1;
    for (int f = 0; f < fmax; f++) {
        int ocf = ocb2 * 64 + (partial ? mw * 16 : mw * 32 + f * 16);  // frag base (mult of 16)
        int oc0 = ocf + gid;
        int oc1 = oc0 + 8;
        float bi0 = Bi[oc0], bi1 = Bi[oc1];
        uint32_t* o0d = g_Xdt + (size_t)b * KPAD + (OUT_OFF + oc0) * PIX;
        uint32_t* o1d = g_Xdt + (size_t)b * KPAD + (OUT_OFF + oc1) * PIX;
        size_t pb = ((size_t)(b * NCHK + (OUT_OFF >> 4) + (ocf >> 4)) * NPLANE) * 8;
#pragma unroll
        for (int j = 0; j < 8; j++) {
            int p = nw * 64 + j * 8 + tig * 2;
            if (p < 238) {
                int p1 = p + 1;
                int pos0 = (p / 34 + 1) * 36 + (p % 34 + 1);
                int pos1 = (p1 / 34 + 1) * 36 + (p1 % 34 + 1);
                float v00 = leaky(acc[f][j][0] + bi0);
                float v01 = leaky(acc[f][j][1] + bi0);
                float v10 = leaky(acc[f][j][2] + bi1);
                float v11 = leaky(acc[f][j][3] + bi1);
                o0d[p] = to_tf32(v00);  o0d[p1] = to_tf32(v01);
                o1d[p] = to_tf32(v10);  o1d[p1] = to_tf32(v11);
                Xp16[(pb + (size_t)pos0 * 8 + kp0) * 2 + half] = f2bf(v00);
                Xp16[(pb + (size_t)pos1 * 8 + kp0) * 2 + half] = f2bf(v01);
                Xp16[(pb + (size_t)pos0 * 8 + kp1) * 2 + half] = f2bf(v10);
                Xp16[(pb + (size_t)pos1 * 8 + kp1) * 2 + half] = f2bf(v11);
            }
        }
    }
}

// ============================================================================
// fc1 via tf32 mma, cp.async double-buffered (unchanged)
// ============================================================================
__device__ __forceinline__ void fc1_fill(const float* __restrict__ Wf,
                                         uint32_t* Xs_s, uint32_t* Ws_s,
                                         int nb, int kk0, int t) {
    for (int i = t; i < 1024; i += 256) {
        int row = i >> 3, s = i & 7;
        CPA16(sptr(Xs_s + row * 36 + s * 4), g_Xdt + (size_t)row * KPAD + kk0 + s * 4);
    }
    for (int i = t; i < 1024; i += 256) {
        int row = i >> 4, s = i & 15;
        size_t off = (size_t)(nb + row) * KTOT + kk0 + s * 2;
        if (off + 2 > (size_t)512 * KTOT) off = 0;
        CPA8(sptr(Ws_s + row * 36 + s * 2), Wf + off);
    }
}

__global__ __launch_bounds__(256) void fc1T_k(const float* __restrict__ Wf) {
    int ntile = blockIdx.x, ks = blockIdx.y;
    int nb = ntile * 64;
    int k0 = ks * KSP;
    extern __shared__ uint32_t dyn[];
    uint32_t* Xsb = dyn;
    uint32_t* Wsb = dyn + 9216;

    int t = threadIdx.x;
    int wid = t >> 5, lane = t & 31;
    int gid = lane >> 2, tig = lane & 3;
    int mwarp = wid & 3, nwarp = wid >> 2;
    int m0 = mwarp * 32, n0 = nwarp * 32;

    float acc[2][4][4] = {};

    fc1_fill(Wf, Xsb, Wsb, nb, k0, t);
    CPCOMMIT();

    int buf = 0;
    for (int ch = 0; ch < NCHUNK; ch++) {
        if (ch + 1 < NCHUNK)
            fc1_fill(Wf, Xsb + (buf ^ 1) * 4608, Wsb + (buf ^ 1) * 2304,
                     nb, k0 + (ch + 1) * 32, t);
        CPCOMMIT();
        CPWAIT1();
        __syncthreads();

        const uint32_t* Xs = Xsb + buf * 4608;
        const uint32_t* Ws = Wsb + buf * 2304;
#pragma unroll
        for (int k8 = 0; k8 < 4; k8++) {
            int kb = k8 * 8;
            uint32_t a[2][4];
#pragma unroll
            for (int mi = 0; mi < 2; mi++) {
                int m = m0 + mi * 16;
                a[mi][0] = Xs[(m + gid    ) * 36 + kb + tig];
                a[mi][1] = Xs[(m + gid + 8) * 36 + kb + tig];
                a[mi][2] = Xs[(m + gid    ) * 36 + kb + tig + 4];
                a[mi][3] = Xs[(m + gid + 8) * 36 + kb + tig + 4];
            }
#pragma unroll
            for (int nj = 0; nj < 4; nj++) {
                int n = n0 + nj * 8;
                uint32_t b0 = Ws[(n + gid) * 36 + kb + tig];
                uint32_t b1 = Ws[(n + gid) * 36 + kb + tig + 4];
#pragma unroll
                for (int mi = 0; mi < 2; mi++)
                    mma_tf32(acc[mi][nj], a[mi][0], a[mi][1], a[mi][2], a[mi][3], b0, b1);
            }
        }
        __syncthreads();
        buf ^= 1;
    }

    float* pp = g_part + (size_t)ks * 65536;
#pragma unroll
    for (int mi = 0; mi < 2; mi++) {
        int m = m0 + mi * 16;
#pragma unroll
        for (int nj = 0; nj < 4; nj++) {
            int col = nb + n0 + nj * 8 + 2 * tig;
            *(float2*)&pp[(size_t)(m + gid    ) * 512 + col] =
                make_float2(acc[mi][nj][0], acc[mi][nj][1]);
            *(float2*)&pp[(size_t)(m + gid + 8) * 512 + col] =
                make_float2(acc[mi][nj][2], acc[mi][nj][3]);
        }
    }
}

__global__ void fc1red_k(const float* __restrict__ bias) {
    int i = blockIdx.x * 256 + threadIdx.x;
    float a = 0.f;
#pragma unroll 8
    for (int ks = 0; ks < KSPLIT; ks++) a += g_part[(size_t)ks * 65536 + i];
    g_fc1[i] = leaky(a + bias[i & 511]);
}

// ============================================================================
// l1 / r1 (FFMA2, small)
// ============================================================================
__global__ __launch_bounds__(256, 2) void l1r1_k(const float* __restrict__ wl1,
                                                 const float* __restrict__ bl1,
                                                 const float* __restrict__ wr1,
                                                 const float* __restrict__ br1) {
    int side = blockIdx.x, ntile = blockIdx.y;
    int nb = ntile * 128;
    const float* Wp = side ? wr1 : wl1;
    const float* Bp = side ? br1 : bl1;
    __shared__ __align__(16) float Xs[16][132];
    __shared__ __align__(16) float Ws[16][132];
    int t = threadIdx.x, tn = t & 15, tb = t >> 4, b0 = tb * 8, n0 = tn * 8;
    ull acc[8][4] = {};

    for (int kk0 = 0; kk0 < 512; kk0 += 16) {
        for (int i = t; i < 2048; i += 256) {
            int k = i & 15, row = i >> 4;
            Xs[k][row] = g_fc1[(size_t)row * 512 + kk0 + k];
            Ws[k][row] = Wp[(size_t)(nb + row) * 512 + kk0 + k];
        }
        __syncthreads();
#pragma unroll 4
        for (int kk = 0; kk < 16; kk++) {
            float4 xa = *(const float4*)&Xs[kk][b0];
            float4 xb = *(const float4*)&Xs[kk][b0 + 4];
            float4 wa = *(const float4*)&Ws[kk][n0];
            float4 wb = *(const float4*)&Ws[kk][n0 + 4];
            ull xd[8] = {fdup(xa.x), fdup(xa.y), fdup(xa.z), fdup(xa.w),
                         fdup(xb.x), fdup(xb.y), fdup(xb.z), fdup(xb.w)};
            ull w2[4] = {fpack(wa.x, wa.y), fpack(wa.z, wa.w),
                         fpack(wb.x, wb.y), fpack(wb.z, wb.w)};
#pragma unroll
            for (int i = 0; i < 8; i++)
#pragma unroll
                for (int j = 0; j < 4; j++)
                    fma2(acc[i][j], w2[j], xd[i]);
        }
        __syncthreads();
    }

#pragma unroll
    for (int i = 0; i < 8; i++)
#pragma unroll
        for (int j = 0; j < 4; j++) {
            float lo, hi; funpack(acc[i][j], lo, hi);
            int n = nb + n0 + 2 * j;
            float* p = &g_h[(size_t)side * (B_ * 256) + (size_t)(b0 + i) * 256 + n];
            p[0] = leaky(lo + Bp[n]);
            p[1] = leaky(hi + Bp[n + 1]);
        }
}

// ============================================================================
// heads + quat distance + mean
// ============================================================================
__global__ void heads2_k(const float* __restrict__ wl2, const float* __restrict__ bl2,
                         const float* __restrict__ wr2, const float* __restrict__ br2,
                         const float* __restrict__ lt,  const float* __restrict__ rt) {
    int b = blockIdx.x, t = threadIdx.x;
    __shared__ float hl[256], hr[256], q[8];
    hl[t] = g_h[(size_t)b * 256 + t];
    hr[t] = g_h[(size_t)(B_ * 256) + (size_t)b * 256 + t];
    __syncthreads();

    int wrp = t >> 5, lane = t & 31;
    const float* w   = (wrp < 4) ? wl2 : wr2;
    const float* src = (wrp < 4) ? hl : hr;
    int i = wrp & 3;
    float s = 0.f;
    for (int j = lane; j < 256; j += 32) s += w[i * 256 + j] * src[j];
#pragma unroll
    for (int off = 16; off > 0; off >>= 1) s += __shfl_down_sync(0xffffffffu, s, off);
    if (lane == 0) q[wrp] = s + ((wrp < 4) ? bl2[i] : br2[i]);
    __syncthreads();

    if (t == 0) {
#pragma unroll
        for (int side = 0; side < 2; side++) {
            float qw = q[side * 4 + 0], qx = q[side * 4 + 1];
            float qy = q[side * 4 + 2], qz = q[side * 4 + 3];
            float nn = sqrtf(qw * qw + qx * qx + qy * qy + qz * qz);
            nn = fmaxf(nn, 1e-12f);
            qw /= nn; qx /= nn; qy /= nn; qz /= nn;
            const float* tgt = (side == 0 ? lt : rt) + (size_t)b * 4;
            float rw = tgt[0], rx = -tgt[1], ry = -tgt[2], rz = -tgt[3];
            float tw = qw * rw - qx * rx - qy * ry - qz * rz;
            float tx = qw * rx + qx * rw + qy * rz - qz * ry;
            float ty = qw * ry - qx * rz + qy * rw + qz * rx;
            float tz = qw * rz + qx * ry - qy * rx + qz * rw;
            float ang = 2.f * atan2f(sqrtf(tx * tx + ty * ty + tz * tz + 1e-12f), fabsf(tw));
            g_ang[side * B_ + b] = ang;
        }
    }
}

__global__ void mean_k(float* __restrict__ out) {
    __shared__ float sl[128], sr[128];
    int t = threadIdx.x;
    sl[t] = g_ang[t];
    sr[t] = g_ang[128 + t];
    __syncthreads();
    for (int s = 64; s > 0; s >>= 1) {
        if (t < s) { sl[t] += sl[t + s]; sr[t] += sr[t + s]; }
        __syncthreads();
    }
    if (t == 0) { out[0] = sl[0] * (1.f / 128.f); out[1] = sr[0] * (1.f / 128.f); }
}

// ============================================================================
extern "C" void kernel_launch(void* const* d_in, const int* in_sizes, int n_in,
                              void* d_out, int out_size) {
    (void)in_sizes; (void)n_in; (void)out_size;
    const float* left  = (const float*)d_in[0];
    const float* right = (const float*)d_in[1];
    const float* lt    = (const float*)d_in[2];
    const float* rt    = (const float*)d_in[3];
    const float* w6[5] = {(const float*)d_in[4],  (const float*)d_in[6],
                          (const float*)d_in[8],  (const float*)d_in[10],
                          (const float*)d_in[12]};
    const float* b6[5] = {(const float*)d_in[5],  (const float*)d_in[7],
                          (const float*)d_in[9],  (const float*)d_in[11],
                          (const float*)d_in[13]};
    const float* wfc1 = (const float*)d_in[14];
    const float* bfc1 = (const float*)d_in[15];
    const float* wl1  = (const float*)d_in[16];
    const float* bl1  = (const float*)d_in[17];
    const float* wr1  = (const float*)d_in[18];
    const float* br1  = (const float*)d_in[19];
    const float* wl2  = (const float*)d_in[20];
    const float* bl2  = (const float*)d_in[21];
    const float* wr2  = (const float*)d_in[22];
    const float* br2  = (const float*)d_in[23];
    float* out = (float*)d_out;

    static bool attr_done = false;
    if (!attr_done) {
        cudaFuncSetAttribute(convB64_k, cudaFuncAttributeMaxDynamicSharedMemorySize,
                             2 * STG_W * 4);
        cudaFuncSetAttribute(fc1T_k, cudaFuncAttributeMaxDynamicSharedMemorySize, 55296);
        attr_done = true;
    }

    const int INO[5]   = {448, 320, 192, 96, 32};
    const int OUTO[5]  = {320, 192, 96, 32, 0};
    const int OCL[5]   = {128, 128, 96, 64, 32};
    const int OCT64[5] = {2, 2, 2, 1, 1};
    const int CHK[5]   = {6, 14, 22, 28, 32};
    const int WBASE[5] = {0, 24, 80, 146, 202};

    wprep_all<<<234, 256>>>(w6[0], w6[1], w6[2], w6[3], w6[4]);
    corr_k<<<B_, 576>>>(left, right);

    for (int l = 0; l < 5; l++)
        convB64_k<<<dim3(B_, OCT64[l]), 256, 2 * STG_W * 4>>>(
            b6[l], CHK[l], WBASE[l], INO[l] >> 4, OUTO[l], OCL[l]);

    fc1T_k<<<dim3(8, KSPLIT), 256, 55296>>>(wfc1);
    fc1red_k<<<256, 256>>>(bfc1);
    l1r1_k<<<dim3(2, 2), 256>>>(wl1, bl1, wr1, br1);
    heads2_k<<<B_, 256>>>(wl2, bl2, wr2, br2, lt, rt);
    mean_k<<<1, 128>>>(out);
}

// round 8
// speedup vs baseline: 3.7273x; 1.0399x over previous
#include <cuda_runtime.h>
#include <cstdint>

#define B_   128
#define C_   512
#define PIX  238            // 7*34
#define NCH  529
#define KTOT (NCH*PIX)      // 125902
#define KPAD 126976         // padded dense row stride = 64*1984 (16B-aligned rows)
#define KSPLIT 64
#define KSP  1984
#define NCHUNK 62           // KSP/32
#define NPLANE 324          // padded 9*36 plane positions
#define NCHK 34             // global 16-channel chunks covering 529 (+15 zero)
#define XP2_CH (NPLANE * 8) // 2592 words per (b,chunk) plane
#define WCT 2304            // 9 taps * 32 oc * 8 kpair words per tile

#define XS_W   (NPLANE * 12)   // 3888 words
#define WS64_W (2 * 3456)      // 6912 words (2 oc-halves)
#define STG_W  (XS_W + WS64_W) // 10800 words / 43200 B per stage

// ---------------- scratch (device globals; no allocations allowed) ----------
__device__ uint32_t g_Xdt[B_ * KPAD];            // dense activations, tf32 bits (fc1)
__device__ uint32_t g_Xp2[B_ * NCHK * XP2_CH];   // padded bf16 pair-interleaved (convs)
__device__ uint32_t g_Wc2[234 * WCT];            // prepped conv weights, bf16 pairs
__device__ float g_part[KSPLIT * B_ * 512];
__device__ float g_fc1[B_ * 512];
__device__ float g_h[2 * B_ * 256];
__device__ float g_ang[2 * B_];

typedef unsigned long long ull;

__device__ __forceinline__ float leaky(float x) { return x >= 0.f ? x : 0.1f * x; }

__device__ __forceinline__ ull fpack(float lo, float hi) {
    ull r; asm("mov.b64 %0, {%1, %2};" : "=l"(r) : "f"(lo), "f"(hi)); return r;
}
__device__ __forceinline__ ull fdup(float v) { return fpack(v, v); }
__device__ __forceinline__ void funpack(ull p, float& lo, float& hi) {
    asm("mov.b64 {%0, %1}, %2;" : "=f"(lo), "=f"(hi) : "l"(p));
}
__device__ __forceinline__ void fma2(ull& d, ull a, ull b) {
    asm("fma.rn.f32x2 %0, %1, %2, %3;" : "=l"(d) : "l"(a), "l"(b), "l"(d));
}
__device__ __forceinline__ uint32_t to_tf32(float f) {
    uint32_t r; asm("cvt.rna.tf32.f32 %0, %1;" : "=r"(r) : "f"(f)); return r;
}
__device__ __forceinline__ uint16_t f2bf(float f) {
    uint32_t u = __float_as_uint(f);
    return (uint16_t)((u + 0x7fffu + ((u >> 16) & 1u)) >> 16);
}
__device__ __forceinline__ uint32_t f2bf2(float lo, float hi) {
    return (uint32_t)f2bf(lo) | ((uint32_t)f2bf(hi) << 16);
}
__device__ __forceinline__ void mma_tf32(float* c,
                                         uint32_t a0, uint32_t a1, uint32_t a2, uint32_t a3,
                                         uint32_t b0, uint32_t b1) {
    asm volatile("mma.sync.aligned.m16n8k8.row.col.f32.tf32.tf32.f32 "
                 "{%0,%1,%2,%3}, {%4,%5,%6,%7}, {%8,%9}, {%0,%1,%2,%3};"
                 : "+f"(c[0]), "+f"(c[1]), "+f"(c[2]), "+f"(c[3])
                 : "r"(a0), "r"(a1), "r"(a2), "r"(a3), "r"(b0), "r"(b1));
}
__device__ __forceinline__ void mma_bf16(float* c,
                                         uint32_t a0, uint32_t a1, uint32_t a2, uint32_t a3,
                                         uint32_t b0, uint32_t b1) {
    asm volatile("mma.sync.aligned.m16n8k16.row.col.f32.bf16.bf16.f32 "
                 "{%0,%1,%2,%3}, {%4,%5,%6,%7}, {%8,%9}, {%0,%1,%2,%3};"
                 : "+f"(c[0]), "+f"(c[1]), "+f"(c[2]), "+f"(c[3])
                 : "r"(a0), "r"(a1), "r"(a2), "r"(a3), "r"(b0), "r"(b1));
}
__device__ __forceinline__ uint32_t sptr(const void* p) {
    return (uint32_t)__cvta_generic_to_shared(p);
}
#define CPA16(dst, src)  asm volatile("cp.async.ca.shared.global [%0], [%1], 16;"    :: "r"(dst), "l"(src))
#define CPA8(dst, src)   asm volatile("cp.async.ca.shared.global [%0], [%1], 8;"     :: "r"(dst), "l"(src))
#define CPCOMMIT()       asm volatile("cp.async.commit_group;")
#define CPWAIT1()        asm volatile("cp.async.wait_group 1;" ::: "memory")

// ============================================================================
// weight prep: all 5 layers -> pair-packed bf16 tiles [tap][oc32][kpair]
// ============================================================================
__global__ void wprep_all(const float* __restrict__ w0, const float* __restrict__ w1,
                          const float* __restrict__ w2, const float* __restrict__ w3,
                          const float* __restrict__ w4) {
    int tile = blockIdx.x;
    const float* W; int IC, chunks, tbase;
    if      (tile <  24) { W = w0; IC =  81; chunks =  6; tbase =   0; }
    else if (tile <  80) { W = w1; IC = 209; chunks = 14; tbase =  24; }
    else if (tile < 146) { W = w2; IC = 337; chunks = 22; tbase =  80; }
    else if (tile < 202) { W = w3; IC = 433; chunks = 28; tbase = 146; }
    else                 { W = w4; IC = 497; chunks = 32; tbase = 202; }
    int rel = tile - tbase, ocb = rel / chunks, ch = rel % chunks;
    uint32_t* out = g_Wc2 + (size_t)tile * WCT;
    for (int i = threadIdx.x; i < WCT; i += 256) {
        int tap = i >> 8, rem = i & 255, oc = rem >> 3, kp = rem & 7;
        int ic0 = ch * 16 + kp * 2;
        float v0 = 0.f, v1 = 0.f;
        const float* wrow = W + ((size_t)(ocb * 32 + oc) * IC) * 9;
        if (ic0     < IC) v0 = wrow[(ic0    ) * 9 + tap];
        if (ic0 + 1 < IC) v1 = wrow[(ic0 + 1) * 9 + tap];
        out[i] = f2bf2(v0, v1);
    }
}

// ============================================================================
// corr81 + leaky -> channels [448,529): 16-channel chunks
// ============================================================================
__global__ __launch_bounds__(576) void corr_k(const float* __restrict__ L,
                                              const float* __restrict__ R) {
    int b = blockIdx.x;
    __shared__ __align__(16) float Ls[16][7][36];
    __shared__ __align__(16) float Rs[16][7][44];
    int t = threadIdx.x;
    int g  = t % 9;
    int dy = (t / 9) % 9;
    int y  = t / 81;
    int x0 = g * 4;

    for (int i = t; i < 16 * 7 * 44; i += 576) ((float*)Rs)[i] = 0.f;
    for (int i = t; i < 16 * 7 * 36; i += 576) ((float*)Ls)[i] = 0.f;
    __syncthreads();

    ull acc2[9][2] = {};

    int ry = y + dy - 4;
    bool valid = (y < 7) && (ry >= 0) && (ry < 7);
    const float* Lb = L + (size_t)b * C_ * PIX;
    const float* Rb = R + (size_t)b * C_ * PIX;

    for (int c0 = 0; c0 < C_; c0 += 16) {
        for (int i = t; i < 16 * PIX; i += 576) {
            int c = i / PIX, p = i % PIX;
            Ls[c][p / 34][p % 34]       = Lb[(size_t)(c0 + c) * PIX + p];
            Rs[c][p / 34][(p % 34) + 4] = Rb[(size_t)(c0 + c) * PIX + p];
        }
        __syncthreads();
        if (valid) {
#pragma unroll
            for (int c = 0; c < 16; c++) {
                float4 l4 = *(const float4*)&Ls[c][y][x0];
                float4 r0 = *(const float4*)&Rs[c][ry][x0];
                float4 r1 = *(const float4*)&Rs[c][ry][x0 + 4];
                float4 r2 = *(const float4*)&Rs[c][ry][x0 + 8];
                ull lp0 = fpack(l4.x, l4.y), lp1 = fpack(l4.z, l4.w);
                float rv[12] = {r0.x, r0.y, r0.z, r0.w,
                                r1.x, r1.y, r1.z, r1.w,
                                r2.x, r2.y, r2.z, r2.w};
#pragma unroll
                for (int dx = 0; dx < 9; dx++) {
                    fma2(acc2[dx][0], lp0, fpack(rv[dx],     rv[dx + 1]));
                    fma2(acc2[dx][1], lp1, fpack(rv[dx + 2], rv[dx + 3]));
                }
            }
        }
        __syncthreads();
    }

    if (y < 7) {
        uint16_t* Xp16 = (uint16_t*)g_Xp2;
#pragma unroll
        for (int dx = 0; dx < 9; dx++) {
            int ch = 448 + dy * 9 + dx;
            float av[4];
            funpack(acc2[dx][0], av[0], av[1]);
            funpack(acc2[dx][1], av[2], av[3]);
            uint32_t* opd = &g_Xdt[(size_t)b * KPAD + ch * PIX + y * 34];
            size_t pbase = ((size_t)(b * NCHK + (ch >> 4)) * NPLANE) * 8 + ((ch & 15) >> 1);
            int half = ch & 1;
#pragma unroll
            for (int i = 0; i < 4; i++) {
                int x = x0 + i;
                if (x < 34) {
                    float v = leaky(av[i] * (1.f / 512.f));
                    opd[x] = to_tf32(v);
                    int pos = (y + 1) * 36 + (x + 1);
                    Xp16[(pbase + (size_t)pos * 8) * 2 + half] = f2bf(v);
                }
            }
        }
    }
}

// ============================================================================
// 3x3 conv, bf16 mma.m16n8k16, 64-oc block tile (warp: 32oc x 64pos),
// cp.async double-buffered; 2 blocks/SM via launch bounds.
// ============================================================================
__device__ __forceinline__ void conv64_fill(const uint32_t* Xsrc,
                                            const uint32_t* W0, const uint32_t* W1,
                                            int nhalf, uint32_t* stage, int ch, int t) {
    const uint32_t* xs = Xsrc + (size_t)ch * XP2_CH;
    for (int i = t; i < 648; i += 256) {
        int pos = i >> 1, h = i & 1;
        CPA16(sptr(stage + pos * 12 + h * 4), xs + pos * 8 + h * 4);
    }
    uint32_t* Ws = stage + XS_W;
    for (int i = t; i < nhalf * 576; i += 256) {
        int h = (i >= 576), ii = i - h * 576;
        int to = ii >> 1, hw = ii & 1;
        const uint32_t* ws = (h ? W1 : W0) + (size_t)ch * WCT;
        CPA16(sptr(Ws + h * 3456 + to * 12 + hw * 4), ws + to * 8 + hw * 4);
    }
}

__global__ __launch_bounds__(256, 2) void convB64_k(const float* __restrict__ Bi,
                                                    int chunks, int wtile0,
                                                    int chunk0in, int OUT_OFF, int OC) {
    int b    = blockIdx.x;
    int ocb2 = blockIdx.y;
    bool partial = (ocb2 * 64 + 64 > OC);
    int nhalf = partial ? 1 : 2;
    extern __shared__ uint32_t dyn[];

    int t = threadIdx.x;
    int wid = t >> 5, lane = t & 31;
    int mw = wid & 1, nw = wid >> 1;
    int gid = lane >> 2, tig = lane & 3;

    float acc[2][8][4] = {};

    int offp[8];
#pragma unroll
    for (int j = 0; j < 8; j++) {
        int p = nw * 64 + j * 8 + gid;
        if (p > 237) p = 237;
        offp[j] = (p / 34) * 36 + (p % 34);
    }

    const uint32_t* Xsrc = g_Xp2 + (size_t)(b * NCHK + chunk0in) * XP2_CH;
    const uint32_t* W0 = g_Wc2 + (size_t)(wtile0 + (ocb2 * 2    ) * chunks) * WCT;
    const uint32_t* W1 = g_Wc2 + (size_t)(wtile0 + (ocb2 * 2 + nhalf - 1) * chunks) * WCT;

    int aBase0, aBase1;
    if (partial) {
        aBase0 = (mw * 16 + gid) * 12 + tig;
        aBase1 = aBase0;
    } else {
        aBase0 = mw * 3456 + (gid     ) * 12 + tig;
        aBase1 = mw * 3456 + (16 + gid) * 12 + tig;
    }

    conv64_fill(Xsrc, W0, W1, nhalf, dyn, 0, t);
    CPCOMMIT();

    int buf = 0;
    for (int ch = 0; ch < chunks; ch++) {
        if (ch + 1 < chunks)
            conv64_fill(Xsrc, W0, W1, nhalf, dyn + (buf ^ 1) * STG_W, ch + 1, t);
        CPCOMMIT();
        CPWAIT1();
        __syncthreads();

        const uint32_t* Xs = dyn + buf * STG_W;
        const uint32_t* Ws = Xs + XS_W;
        if (!partial) {
#pragma unroll
            for (int ky = 0; ky < 3; ky++)
#pragma unroll
                for (int kx = 0; kx < 3; kx++) {
                    int kk  = ky * 3 + kx;
                    int kof = ky * 36 + kx;
                    int a0b = aBase0 + kk * 384;
                    int a1b = aBase1 + kk * 384;
                    uint32_t p0 = Ws[a0b], p1 = Ws[a0b + 96];
                    uint32_t p2 = Ws[a0b + 4], p3 = Ws[a0b + 100];
                    uint32_t q0 = Ws[a1b], q1 = Ws[a1b + 96];
                    uint32_t q2 = Ws[a1b + 4], q3 = Ws[a1b + 100];
#pragma unroll
                    for (int j = 0; j < 8; j++) {
                        int xb = (offp[j] + kof) * 12 + tig;
                        uint32_t b0 = Xs[xb];
                        uint32_t b1 = Xs[xb + 4];
                        mma_bf16(acc[0][j], p0, p1, p2, p3, b0, b1);
                        mma_bf16(acc[1][j], q0, q1, q2, q3, b0, b1);
                    }
                }
        } else {
#pragma unroll
            for (int ky = 0; ky < 3; ky++)
#pragma unroll
                for (int kx = 0; kx < 3; kx++) {
                    int kk  = ky * 3 + kx;
                    int kof = ky * 36 + kx;
                    int a0b = aBase0 + kk * 384;
                    uint32_t p0 = Ws[a0b], p1 = Ws[a0b + 96];
                    uint32_t p2 = Ws[a0b + 4], p3 = Ws[a0b + 100];
#pragma unroll
                    for (int j = 0; j < 8; j++) {
                        int xb = (offp[j] + kof) * 12 + tig;
                        uint32_t b0 = Xs[xb];
                        uint32_t b1 = Xs[xb + 4];
                        mma_bf16(acc[0][j], p0, p1, p2, p3, b0, b1);
                    }
                }
        }
        __syncthreads();
        buf ^= 1;
    }

    // epilogue: bias + leaky; tf32 dense + bf16 pair-interleaved stores
    uint16_t* Xp16 = (uint16_t*)g_Xp2;
    int fmax = partial ? 1 : 2;
    int kp0 = gid >> 1, kp1 = kp0 + 4, half = gid & 1;
    for (int f = 0; f < fmax; f++) {
        int ocf = ocb2 * 64 + (partial ? mw * 16 : mw * 32 + f * 16);
        int oc0 = ocf + gid;
        int oc1 = oc0 + 8;
        float bi0 = Bi[oc0], bi1 = Bi[oc1];
        uint32_t* o0d = g_Xdt + (size_t)b * KPAD + (OUT_OFF + oc0) * PIX;
        uint32_t* o1d = g_Xdt + (size_t)b * KPAD + (OUT_OFF + oc1) * PIX;
        size_t pb = ((size_t)(b * NCHK + (OUT_OFF >> 4) + (ocf >> 4)) * NPLANE) * 8;
#pragma unroll
        for (int j = 0; j < 8; j++) {
            int p = nw * 64 + j * 8 + tig * 2;
            if (p < 238) {
                int p1 = p + 1;
                int pos0 = (p / 34 + 1) * 36 + (p % 34 + 1);
                int pos1 = (p1 / 34 + 1) * 36 + (p1 % 34 + 1);
                float v00 = leaky(acc[f][j][0] + bi0);
                float v01 = leaky(acc[f][j][1] + bi0);
                float v10 = leaky(acc[f][j][2] + bi1);
                float v11 = leaky(acc[f][j][3] + bi1);
                o0d[p] = to_tf32(v00);  o0d[p1] = to_tf32(v01);
                o1d[p] = to_tf32(v10);  o1d[p1] = to_tf32(v11);
                Xp16[(pb + (size_t)pos0 * 8 + kp0) * 2 + half] = f2bf(v00);
                Xp16[(pb + (size_t)pos1 * 8 + kp0) * 2 + half] = f2bf(v01);
                Xp16[(pb + (size_t)pos0 * 8 + kp1) * 2 + half] = f2bf(v10);
                Xp16[(pb + (size_t)pos1 * 8 + kp1) * 2 + half] = f2bf(v11);
            }
        }
    }
}

// ============================================================================
// fc1 via tf32 mma, cp.async double-buffered, 64-way K-split, 2 blocks/SM
// ============================================================================
__device__ __forceinline__ void fc1_fill(const float* __restrict__ Wf,
                                         uint32_t* Xs_s, uint32_t* Ws_s,
                                         int nb, int kk0, int t) {
    for (int i = t; i < 1024; i += 256) {
        int row = i >> 3, s = i & 7;
        CPA16(sptr(Xs_s + row * 36 + s * 4), g_Xdt + (size_t)row * KPAD + kk0 + s * 4);
    }
    for (int i = t; i < 1024; i += 256) {
        int row = i >> 4, s = i & 15;
        size_t off = (size_t)(nb + row) * KTOT + kk0 + s * 2;
        if (off + 2 > (size_t)512 * KTOT) off = 0;   // clamp: X pad region is zero
        CPA8(sptr(Ws_s + row * 36 + s * 2), Wf + off);
    }
}

__global__ __launch_bounds__(256, 2) void fc1T_k(const float* __restrict__ Wf) {
    int ntile = blockIdx.x, ks = blockIdx.y;
    int nb = ntile * 64;
    int k0 = ks * KSP;
    extern __shared__ uint32_t dyn[];
    uint32_t* Xsb = dyn;
    uint32_t* Wsb = dyn + 9216;

    int t = threadIdx.x;
    int wid = t >> 5, lane = t & 31;
    int gid = lane >> 2, tig = lane & 3;
    int mwarp = wid & 3, nwarp = wid >> 2;
    int m0 = mwarp * 32, n0 = nwarp * 32;

    float acc[2][4][4] = {};

    fc1_fill(Wf, Xsb, Wsb, nb, k0, t);
    CPCOMMIT();

    int buf = 0;
    for (int ch = 0; ch < NCHUNK; ch++) {
        if (ch + 1 < NCHUNK)
            fc1_fill(Wf, Xsb + (buf ^ 1) * 4608, Wsb + (buf ^ 1) * 2304,
                     nb, k0 + (ch + 1) * 32, t);
        CPCOMMIT();
        CPWAIT1();
        __syncthreads();

        const uint32_t* Xs = Xsb + buf * 4608;
        const uint32_t* Ws = Wsb + buf * 2304;
#pragma unroll
        for (int k8 = 0; k8 < 4; k8++) {
            int kb = k8 * 8;
            uint32_t a[2][4];
#pragma unroll
            for (int mi = 0; mi < 2; mi++) {
                int m = m0 + mi * 16;
                a[mi][0] = Xs[(m + gid    ) * 36 + kb + tig];
                a[mi][1] = Xs[(m + gid + 8) * 36 + kb + tig];
                a[mi][2] = Xs[(m + gid    ) * 36 + kb + tig + 4];
                a[mi][3] = Xs[(m + gid + 8) * 36 + kb + tig + 4];
            }
#pragma unroll
            for (int nj = 0; nj < 4; nj++) {
                int n = n0 + nj * 8;
                uint32_t b0 = Ws[(n + gid) * 36 + kb + tig];
                uint32_t b1 = Ws[(n + gid) * 36 + kb + tig + 4];
#pragma unroll
                for (int mi = 0; mi < 2; mi++)
                    mma_tf32(acc[mi][nj], a[mi][0], a[mi][1], a[mi][2], a[mi][3], b0, b1);
            }
        }
        __syncthreads();
        buf ^= 1;
    }

    float* pp = g_part + (size_t)ks * 65536;
#pragma unroll
    for (int mi = 0; mi < 2; mi++) {
        int m = m0 + mi * 16;
#pragma unroll
        for (int nj = 0; nj < 4; nj++) {
            int col = nb + n0 + nj * 8 + 2 * tig;
            *(float2*)&pp[(size_t)(m + gid    ) * 512 + col] =
                make_float2(acc[mi][nj][0], acc[mi][nj][1]);
            *(float2*)&pp[(size_t)(m + gid + 8) * 512 + col] =
                make_float2(acc[mi][nj][2], acc[mi][nj][3]);
        }
    }
}

__global__ void fc1red_k(const float* __restrict__ bias) {
    int i = blockIdx.x * 256 + threadIdx.x;
    float a = 0.f;
#pragma unroll 8
    for (int ks = 0; ks < KSPLIT; ks++) a += g_part[(size_t)ks * 65536 + i];
    g_fc1[i] = leaky(a + bias[i & 511]);
}

// ============================================================================
// l1 / r1 (FFMA2, small)
// ============================================================================
__global__ __launch_bounds__(256, 2) void l1r1_k(const float* __restrict__ wl1,
                                                 const float* __restrict__ bl1,
                                                 const float* __restrict__ wr1,
                                                 const float* __restrict__ br1) {
    int side = blockIdx.x, ntile = blockIdx.y;
    int nb = ntile * 128;
    const float* Wp = side ? wr1 : wl1;
    const float* Bp = side ? br1 : bl1;
    __shared__ __align__(16) float Xs[16][132];
    __shared__ __align__(16) float Ws[16][132];
    int t = threadIdx.x, tn = t & 15, tb = t >> 4, b0 = tb * 8, n0 = tn * 8;
    ull acc[8][4] = {};

    for (int kk0 = 0; kk0 < 512; kk0 += 16) {
        for (int i = t; i < 2048; i += 256) {
            int k = i & 15, row = i >> 4;
            Xs[k][row] = g_fc1[(size_t)row * 512 + kk0 + k];
            Ws[k][row] = Wp[(size_t)(nb + row) * 512 + kk0 + k];
        }
        __syncthreads();
#pragma unroll 4
        for (int kk = 0; kk < 16; kk++) {
            float4 xa = *(const float4*)&Xs[kk][b0];
            float4 xb = *(const float4*)&Xs[kk][b0 + 4];
            float4 wa = *(const float4*)&Ws[kk][n0];
            float4 wb = *(const float4*)&Ws[kk][n0 + 4];
            ull xd[8] = {fdup(xa.x), fdup(xa.y), fdup(xa.z), fdup(xa.w),
                         fdup(xb.x), fdup(xb.y), fdup(xb.z), fdup(xb.w)};
            ull w2[4] = {fpack(wa.x, wa.y), fpack(wa.z, wa.w),
                         fpack(wb.x, wb.y), fpack(wb.z, wb.w)};
#pragma unroll
            for (int i = 0; i < 8; i++)
#pragma unroll
                for (int j = 0; j < 4; j++)
                    fma2(acc[i][j], w2[j], xd[i]);
        }
        __syncthreads();
    }

#pragma unroll
    for (int i = 0; i < 8; i++)
#pragma unroll
        for (int j = 0; j < 4; j++) {
            float lo, hi; funpack(acc[i][j], lo, hi);
            int n = nb + n0 + 2 * j;
            float* p = &g_h[(size_t)side * (B_ * 256) + (size_t)(b0 + i) * 256 + n];
            p[0] = leaky(lo + Bp[n]);
            p[1] = leaky(hi + Bp[n + 1]);
        }
}

// ============================================================================
// heads + quat distance + mean
// ============================================================================
__global__ void heads2_k(const float* __restrict__ wl2, const float* __restrict__ bl2,
                         const float* __restrict__ wr2, const float* __restrict__ br2,
                         const float* __restrict__ lt,  const float* __restrict__ rt) {
    int b = blockIdx.x, t = threadIdx.x;
    __shared__ float hl[256], hr[256], q[8];
    hl[t] = g_h[(size_t)b * 256 + t];
    hr[t] = g_h[(size_t)(B_ * 256) + (size_t)b * 256 + t];
    __syncthreads();

    int wrp = t >> 5, lane = t & 31;
    const float* w   = (wrp < 4) ? wl2 : wr2;
    const float* src = (wrp < 4) ? hl : hr;
    int i = wrp & 3;
    float s = 0.f;
    for (int j = lane; j < 256; j += 32) s += w[i * 256 + j] * src[j];
#pragma unroll
    for (int off = 16; off > 0; off >>= 1) s += __shfl_down_sync(0xffffffffu, s, off);
    if (lane == 0) q[wrp] = s + ((wrp < 4) ? bl2[i] : br2[i]);
    __syncthreads();

    if (t == 0) {
#pragma unroll
        for (int side = 0; side < 2; side++) {
            float qw = q[side * 4 + 0], qx = q[side * 4 + 1];
            float qy = q[side * 4 + 2], qz = q[side * 4 + 3];
            float nn = sqrtf(qw * qw + qx * qx + qy * qy + qz * qz);
            nn = fmaxf(nn, 1e-12f);
            qw /= nn; qx /= nn; qy /= nn; qz /= nn;
            const float* tgt = (side == 0 ? lt : rt) + (size_t)b * 4;
            float rw = tgt[0], rx = -tgt[1], ry = -tgt[2], rz = -tgt[3];
            float tw = qw * rw - qx * rx - qy * ry - qz * rz;
            float tx = qw * rx + qx * rw + qy * rz - qz * ry;
            float ty = qw * ry - qx * rz + qy * rw + qz * rx;
            float tz = qw * rz + qx * ry - qy * rx + qz * rw;
            float ang = 2.f * atan2f(sqrtf(tx * tx + ty * ty + tz * tz + 1e-12f), fabsf(tw));
            g_ang[side * B_ + b] = ang;
        }
    }
}

__global__ void mean_k(float* __restrict__ out) {
    __shared__ float sl[128], sr[128];
    int t = threadIdx.x;
    sl[t] = g_ang[t];
    sr[t] = g_ang[128 + t];
    __syncthreads();
    for (int s = 64; s > 0; s >>= 1) {
        if (t < s) { sl[t] += sl[t + s]; sr[t] += sr[t + s]; }
        __syncthreads();
    }
    if (t == 0) { out[0] = sl[0] * (1.f / 128.f); out[1] = sr[0] * (1.f / 128.f); }
}

// ============================================================================
extern "C" void kernel_launch(void* const* d_in, const int* in_sizes, int n_in,
                              void* d_out, int out_size) {
    (void)in_sizes; (void)n_in; (void)out_size;
    const float* left  = (const float*)d_in[0];
    const float* right = (const float*)d_in[1];
    const float* lt    = (const float*)d_in[2];
    const float* rt    = (const float*)d_in[3];
    const float* w6[5] = {(const float*)d_in[4],  (const float*)d_in[6],
                          (const float*)d_in[8],  (const float*)d_in[10],
                          (const float*)d_in[12]};
    const float* b6[5] = {(const float*)d_in[5],  (const float*)d_in[7],
                          (const float*)d_in[9],  (const float*)d_in[11],
                          (const float*)d_in[13]};
    const float* wfc1 = (const float*)d_in[14];
    const float* bfc1 = (const float*)d_in[15];
    const float* wl1  = (const float*)d_in[16];
    const float* bl1  = (const float*)d_in[17];
    const float* wr1  = (const float*)d_in[18];
    const float* br1  = (const float*)d_in[19];
    const float* wl2  = (const float*)d_in[20];
    const float* bl2  = (const float*)d_in[21];
    const float* wr2  = (const float*)d_in[22];
    const float* br2  = (const float*)d_in[23];
    float* out = (float*)d_out;

    static bool attr_done = false;
    if (!attr_done) {
        cudaFuncSetAttribute(convB64_k, cudaFuncAttributeMaxDynamicSharedMemorySize,
                             2 * STG_W * 4);
        cudaFuncSetAttribute(fc1T_k, cudaFuncAttributeMaxDynamicSharedMemorySize, 55296);
        attr_done = true;
    }

    const int INO[5]   = {448, 320, 192, 96, 32};
    const int OUTO[5]  = {320, 192, 96, 32, 0};
    const int OCL[5]   = {128, 128, 96, 64, 32};
    const int OCT64[5] = {2, 2, 2, 1, 1};
    const int CHK[5]   = {6, 14, 22, 28, 32};
    const int WBASE[5] = {0, 24, 80, 146, 202};

    wprep_all<<<234, 256>>>(w6[0], w6[1], w6[2], w6[3], w6[4]);
    corr_k<<<B_, 576>>>(left, right);

    for (int l = 0; l < 5; l++)
        convB64_k<<<dim3(B_, OCT64[l]), 256, 2 * STG_W * 4>>>(
            b6[l], CHK[l], WBASE[l], INO[l] >> 4, OUTO[l], OCL[l]);

    fc1T_k<<<dim3(8, KSPLIT), 256, 55296>>>(wfc1);
    fc1red_k<<<256, 256>>>(bfc1);
    l1r1_k<<<dim3(2, 2), 256>>>(wl1, bl1, wr1, br1);
    heads2_k<<<B_, 256>>>(wl2, bl2, wr2, br2, lt, rt);
    mean_k<<<1, 128>>>(out);
}

// round 10
// speedup vs baseline: 3.9777x; 1.0672x over previous
#include <cuda_runtime.h>
#include <cstdint>

#define B_   128
#define C_   512
#define PIX  238            // 7*34
#define NCH  529
#define KTOT (NCH*PIX)      // 125902
#define KSPLIT 37
#define KSP  3424           // fp32 k per split (37*3424 = 126688 >= KTOT)
#define KSP2 1712           // words per split
#define KPAD 126688
#define KPAD2 63344         // pair-words per dense row (16B-aligned rows)
#define NCHUNK 107          // KSP/32
#define NPLANE 324          // padded 9*36 plane positions
#define NCHK 34             // global 16-channel chunks covering 529 (+15 zero)
#define XP2_CH (NPLANE * 8) // 2592 words per (b,chunk) plane
#define WCT 2304            // 9 taps * 32 oc * 8 kpair words per tile

#define XS_W   (NPLANE * 12)   // 3888 words
#define WS64_W (2 * 3456)      // 6912 words (2 oc-halves)
#define STG_W  (XS_W + WS64_W) // 10800 words / 43200 B per stage

// fc1 stage layout: Xs bf16 [128][20] = 2560 w, Ws fp32 [64][36] = 2304 w
#define F1_XSW 2560
#define F1_STW 4864            // words per stage; 3 stages = 58368 B

// ---------------- scratch (device globals; no allocations allowed) ----------
__device__ uint32_t g_Xdb[B_ * KPAD2];           // dense activations, bf16 pairs (fc1)
__device__ uint32_t g_Xp2[B_ * NCHK * XP2_CH];   // padded bf16 pair-interleaved (convs)
__device__ uint32_t g_Wc2[234 * WCT];            // prepped conv weights, bf16 pairs
__device__ float g_part[KSPLIT * B_ * 512];
__device__ float g_fc1[B_ * 512];
__device__ float g_h[2 * B_ * 256];
__device__ float g_ang[2 * B_];

typedef unsigned long long ull;

__device__ __forceinline__ float leaky(float x) { return x >= 0.f ? x : 0.1f * x; }

__device__ __forceinline__ ull fpack(float lo, float hi) {
    ull r; asm("mov.b64 %0, {%1, %2};" : "=l"(r) : "f"(lo), "f"(hi)); return r;
}
__device__ __forceinline__ void funpack(ull p, float& lo, float& hi) {
    asm("mov.b64 {%0, %1}, %2;" : "=f"(lo), "=f"(hi) : "l"(p));
}
__device__ __forceinline__ void fma2(ull& d, ull a, ull b) {
    asm("fma.rn.f32x2 %0, %1, %2, %3;" : "=l"(d) : "l"(a), "l"(b), "l"(d));
}
__device__ __forceinline__ uint16_t f2bf(float f) {
    uint32_t u = __float_as_uint(f);
    return (uint16_t)((u + 0x7fffu + ((u >> 16) & 1u)) >> 16);
}
__device__ __forceinline__ uint32_t f2bf2(float lo, float hi) {
    return (uint32_t)f2bf(lo) | ((uint32_t)f2bf(hi) << 16);
}
__device__ __forceinline__ uint32_t cvt_bf2(float lo, float hi) {  // pack {hi,lo}
    uint32_t r;
    asm("cvt.rn.bf16x2.f32 %0, %1, %2;" : "=r"(r) : "f"(hi), "f"(lo));
    return r;
}
__device__ __forceinline__ void mma_bf16(float* c,
                                         uint32_t a0, uint32_t a1, uint32_t a2, uint32_t a3,
                                         uint32_t b0, uint32_t b1) {
    asm volatile("mma.sync.aligned.m16n8k16.row.col.f32.bf16.bf16.f32 "
                 "{%0,%1,%2,%3}, {%4,%5,%6,%7}, {%8,%9}, {%0,%1,%2,%3};"
                 : "+f"(c[0]), "+f"(c[1]), "+f"(c[2]), "+f"(c[3])
                 : "r"(a0), "r"(a1), "r"(a2), "r"(a3), "r"(b0), "r"(b1));
}
__device__ __forceinline__ uint32_t sptr(const void* p) {
    return (uint32_t)__cvta_generic_to_shared(p);
}
#define CPA16(dst, src)  asm volatile("cp.async.ca.shared.global [%0], [%1], 16;"    :: "r"(dst), "l"(src))
#define CPA8(dst, src)   asm volatile("cp.async.ca.shared.global [%0], [%1], 8;"     :: "r"(dst), "l"(src))
#define CPCOMMIT()       asm volatile("cp.async.commit_group;")
#define CPWAIT1()        asm volatile("cp.async.wait_group 1;" ::: "memory")
#define CPWAIT2()        asm volatile("cp.async.wait_group 2;" ::: "memory")

// ============================================================================
// weight prep: all 5 layers -> pair-packed bf16 tiles [tap][oc32][kpair]
// ============================================================================
__global__ void wprep_all(const float* __restrict__ w0, const float* __restrict__ w1,
                          const float* __restrict__ w2, const float* __restrict__ w3,
                          const float* __restrict__ w4) {
    int tile = blockIdx.x;
    const float* W; int IC, chunks, tbase;
    if      (tile <  24) { W = w0; IC =  81; chunks =  6; tbase =   0; }
    else if (tile <  80) { W = w1; IC = 209; chunks = 14; tbase =  24; }
    else if (tile < 146) { W = w2; IC = 337; chunks = 22; tbase =  80; }
    else if (tile < 202) { W = w3; IC = 433; chunks = 28; tbase = 146; }
    else                 { W = w4; IC = 497; chunks = 32; tbase = 202; }
    int rel = tile - tbase, ocb = rel / chunks, ch = rel % chunks;
    uint32_t* out = g_Wc2 + (size_t)tile * WCT;
    for (int i = threadIdx.x; i < WCT; i += 256) {
        int tap = i >> 8, rem = i & 255, oc = rem >> 3, kp = rem & 7;
        int ic0 = ch * 16 + kp * 2;
        float v0 = 0.f, v1 = 0.f;
        const float* wrow = W + ((size_t)(ocb * 32 + oc) * IC) * 9;
        if (ic0     < IC) v0 = wrow[(ic0    ) * 9 + tap];
        if (ic0 + 1 < IC) v1 = wrow[(ic0 + 1) * 9 + tap];
        out[i] = f2bf2(v0, v1);
    }
}

// ============================================================================
// corr81 + leaky -> channels [448,529): bf16 dense pairs + bf16 padded
// ============================================================================
__global__ __launch_bounds__(576) void corr_k(const float* __restrict__ L,
                                              const float* __restrict__ R) {
    int b = blockIdx.x;
    __shared__ __align__(16) float Ls[16][7][36];
    __shared__ __align__(16) float Rs[16][7][44];
    int t = threadIdx.x;
    int g  = t % 9;
    int dy = (t / 9) % 9;
    int y  = t / 81;
    int x0 = g * 4;

    for (int i = t; i < 16 * 7 * 44; i += 576) ((float*)Rs)[i] = 0.f;
    for (int i = t; i < 16 * 7 * 36; i += 576) ((float*)Ls)[i] = 0.f;
    __syncthreads();

    ull acc2[9][2] = {};

    int ry = y + dy - 4;
    bool valid = (y < 7) && (ry >= 0) && (ry < 7);
    const float* Lb = L + (size_t)b * C_ * PIX;
    const float* Rb = R + (size_t)b * C_ * PIX;

    for (int c0 = 0; c0 < C_; c0 += 16) {
        for (int i = t; i < 16 * PIX; i += 576) {
            int c = i / PIX, p = i % PIX;
            Ls[c][p / 34][p % 34]       = Lb[(size_t)(c0 + c) * PIX + p];
            Rs[c][p / 34][(p % 34) + 4] = Rb[(size_t)(c0 + c) * PIX + p];
        }
        __syncthreads();
        if (valid) {
#pragma unroll
            for (int c = 0; c < 16; c++) {
                float4 l4 = *(const float4*)&Ls[c][y][x0];
                float4 r0 = *(const float4*)&Rs[c][ry][x0];
                float4 r1 = *(const float4*)&Rs[c][ry][x0 + 4];
                float4 r2 = *(const float4*)&Rs[c][ry][x0 + 8];
                ull lp0 = fpack(l4.x, l4.y), lp1 = fpack(l4.z, l4.w);
                float rv[12] = {r0.x, r0.y, r0.z, r0.w,
                                r1.x, r1.y, r1.z, r1.w,
                                r2.x, r2.y, r2.z, r2.w};
#pragma unroll
                for (int dx = 0; dx < 9; dx++) {
                    fma2(acc2[dx][0], lp0, fpack(rv[dx],     rv[dx + 1]));
                    fma2(acc2[dx][1], lp1, fpack(rv[dx + 2], rv[dx + 3]));
                }
            }
        }
        __syncthreads();
    }

    if (y < 7) {
        uint16_t* Xp16 = (uint16_t*)g_Xp2;
#pragma unroll
        for (int dx = 0; dx < 9; dx++) {
            int ch = 448 + dy * 9 + dx;
            float av[4];
            funpack(acc2[dx][0], av[0], av[1]);
            funpack(acc2[dx][1], av[2], av[3]);
            float v[4];
#pragma unroll
            for (int i = 0; i < 4; i++) v[i] = leaky(av[i] * (1.f / 512.f));

            // padded bf16 stores (per element, x<34 guard)
            size_t pbase = ((size_t)(b * NCHK + (ch >> 4)) * NPLANE) * 8 + ((ch & 15) >> 1);
            int half = ch & 1;
#pragma unroll
            for (int i = 0; i < 4; i++) {
                int x = x0 + i;
                if (x < 34) {
                    int pos = (y + 1) * 36 + (x + 1);
                    Xp16[(pbase + (size_t)pos * 8) * 2 + half] = f2bf(v[i]);
                }
            }
            // dense bf16 pair stores
            uint32_t* odb = g_Xdb + (size_t)b * KPAD2 + ch * 119 + y * 17;
            odb[x0 >> 1] = f2bf2(v[0], v[1]);
            if (x0 < 32) odb[(x0 >> 1) + 1] = f2bf2(v[2], v[3]);
        }
    }
}

// ============================================================================
// 3x3 conv, bf16 mma.m16n8k16, 64-oc block tile (warp: 32oc x 64pos),
// cp.async double-buffered; 2 blocks/SM.
// ============================================================================
__device__ __forceinline__ void conv64_fill(const uint32_t* Xsrc,
                                            const uint32_t* W0, const uint32_t* W1,
                                            int nhalf, uint32_t* stage, int ch, int t) {
    const uint32_t* xs = Xsrc + (size_t)ch * XP2_CH;
    for (int i = t; i < 648; i += 256) {
        int pos = i >> 1, h = i & 1;
        CPA16(sptr(stage + pos * 12 + h * 4), xs + pos * 8 + h * 4);
    }
    uint32_t* Ws = stage + XS_W;
    for (int i = t; i < nhalf * 576; i += 256) {
        int h = (i >= 576), ii = i - h * 576;
        int to = ii >> 1, hw = ii & 1;
        const uint32_t* ws = (h ? W1 : W0) + (size_t)ch * WCT;
        CPA16(sptr(Ws + h * 3456 + to * 12 + hw * 4), ws + to * 8 + hw * 4);
    }
}

__global__ __launch_bounds__(256, 2) void convB64_k(const float* __restrict__ Bi,
                                                    int chunks, int wtile0,
                                                    int chunk0in, int OUT_OFF, int OC) {
    int b    = blockIdx.x;
    int ocb2 = blockIdx.y;
    bool partial = (ocb2 * 64 + 64 > OC);
    int nhalf = partial ? 1 : 2;
    extern __shared__ uint32_t dyn[];

    int t = threadIdx.x;
    int wid = t >> 5, lane = t & 31;
    int mw = wid & 1, nw = wid >> 1;
    int gid = lane >> 2, tig = lane & 3;

    float acc[2][8][4] = {};

    int offp[8];
#pragma unroll
    for (int j = 0; j < 8; j++) {
        int p = nw * 64 + j * 8 + gid;
        if (p > 237) p = 237;
        offp[j] = (p / 34) * 36 + (p % 34);
    }

    const uint32_t* Xsrc = g_Xp2 + (size_t)(b * NCHK + chunk0in) * XP2_CH;
    const uint32_t* W0 = g_Wc2 + (size_t)(wtile0 + (ocb2 * 2    ) * chunks) * WCT;
    const uint32_t* W1 = g_Wc2 + (size_t)(wtile0 + (ocb2 * 2 + nhalf - 1) * chunks) * WCT;

    int aBase0, aBase1;
    if (partial) {
        aBase0 = (mw * 16 + gid) * 12 + tig;
        aBase1 = aBase0;
    } else {
        aBase0 = mw * 3456 + (gid     ) * 12 + tig;
        aBase1 = mw * 3456 + (16 + gid) * 12 + tig;
    }

    conv64_fill(Xsrc, W0, W1, nhalf, dyn, 0, t);
    CPCOMMIT();

    int buf = 0;
    for (int ch = 0; ch < chunks; ch++) {
        if (ch + 1 < chunks)
            conv64_fill(Xsrc, W0, W1, nhalf, dyn + (buf ^ 1) * STG_W, ch + 1, t);
        CPCOMMIT();
        CPWAIT1();
        __syncthreads();

        const uint32_t* Xs = dyn + buf * STG_W;
        const uint32_t* Ws = Xs + XS_W;
        if (!partial) {
#pragma unroll
            for (int ky = 0; ky < 3; ky++)
#pragma unroll
                for (int kx = 0; kx < 3; kx++) {
                    int kk  = ky * 3 + kx;
                    int kof = ky * 36 + kx;
                    int a0b = aBase0 + kk * 384;
                    int a1b = aBase1 + kk * 384;
                    uint32_t p0 = Ws[a0b], p1 = Ws[a0b + 96];
                    uint32_t p2 = Ws[a0b + 4], p3 = Ws[a0b + 100];
                    uint32_t q0 = Ws[a1b], q1 = Ws[a1b + 96];
                    uint32_t q2 = Ws[a1b + 4], q3 = Ws[a1b + 100];
#pragma unroll
                    for (int j = 0; j < 8; j++) {
                        int xb = (offp[j] + kof) * 12 + tig;
                        uint32_t b0 = Xs[xb];
                        uint32_t b1 = Xs[xb + 4];
                        mma_bf16(acc[0][j], p0, p1, p2, p3, b0, b1);
                        mma_bf16(acc[1][j], q0, q1, q2, q3, b0, b1);
                    }
                }
        } else {
#pragma unroll
            for (int ky = 0; ky < 3; ky++)
#pragma unroll
                for (int kx = 0; kx < 3; kx++) {
                    int kk  = ky * 3 + kx;
                    int kof = ky * 36 + kx;
                    int a0b = aBase0 + kk * 384;
                    uint32_t p0 = Ws[a0b], p1 = Ws[a0b + 96];
                    uint32_t p2 = Ws[a0b + 4], p3 = Ws[a0b + 100];
#pragma unroll
                    for (int j = 0; j < 8; j++) {
                        int xb = (offp[j] + kof) * 12 + tig;
                        uint32_t b0 = Xs[xb];
                        uint32_t b1 = Xs[xb + 4];
                        mma_bf16(acc[0][j], p0, p1, p2, p3, b0, b1);
                    }
                }
        }
        __syncthreads();
        buf ^= 1;
    }

    // epilogue: bias + leaky; bf16 dense pairs + bf16 padded stores
    uint16_t* Xp16 = (uint16_t*)g_Xp2;
    uint32_t* odb = g_Xdb + (size_t)b * KPAD2;
    int fmax = partial ? 1 : 2;
    int kp0 = gid >> 1, kp1 = kp0 + 4, half = gid & 1;
    for (int f = 0; f < fmax; f++) {
        int ocf = ocb2 * 64 + (partial ? mw * 16 : mw * 32 + f * 16);
        int oc0 = ocf + gid;
        int oc1 = oc0 + 8;
        float bi0 = Bi[oc0], bi1 = Bi[oc1];
        int cw0 = (OUT_OFF + oc0) * 119;
        int cw1 = (OUT_OFF + oc1) * 119;
        size_t pb = ((size_t)(b * NCHK + (OUT_OFF >> 4) + (ocf >> 4)) * NPLANE) * 8;
#pragma unroll
        for (int j = 0; j < 8; j++) {
            int p = nw * 64 + j * 8 + tig * 2;
            if (p < 238) {
                int p1 = p + 1;
                int pos0 = (p / 34 + 1) * 36 + (p % 34 + 1);
                int pos1 = (p1 / 34 + 1) * 36 + (p1 % 34 + 1);
                float v00 = leaky(acc[f][j][0] + bi0);
                float v01 = leaky(acc[f][j][1] + bi0);
                float v10 = leaky(acc[f][j][2] + bi1);
                float v11 = leaky(acc[f][j][3] + bi1);
                odb[cw0 + (p >> 1)] = f2bf2(v00, v01);
                odb[cw1 + (p >> 1)] = f2bf2(v10, v11);
                Xp16[(pb + (size_t)pos0 * 8 + kp0) * 2 + half] = f2bf(v00);
                Xp16[(pb + (size_t)pos1 * 8 + kp0) * 2 + half] = f2bf(v01);
                Xp16[(pb + (size_t)pos0 * 8 + kp1) * 2 + half] = f2bf(v10);
                Xp16[(pb + (size_t)pos1 * 8 + kp1) * 2 + half] = f2bf(v11);
            }
        }
    }
}

// ============================================================================
// fc1 via bf16 mma.m16n8k16: X bf16-pairs (A), W fp32 staged + cvt (B).
// 3-stage cp.async pipeline, grid (8, 37) = 296 blocks = one full wave.
// ============================================================================
__device__ __forceinline__ void fc1_fill(const float* __restrict__ Wf,
                                         uint32_t* stage, int nb,
                                         int kk0, int kk2, int t) {
    // X: 128 rows x 16 words (bf16 pairs)
    for (int i = t; i < 512; i += 256) {
        int row = i >> 2, w4 = (i & 3) * 4;
        CPA16(sptr(stage + row * 20 + w4),
              g_Xdb + (size_t)row * KPAD2 + kk2 + w4);
    }
    // W: 64 rows x 32 fp32 (rows only 8B-aligned)
    uint32_t* Ws = stage + F1_XSW;
    for (int i = t; i < 1024; i += 256) {
        int row = i >> 4, s8 = (i & 15) * 2;
        size_t off = (size_t)(nb + row) * KTOT + kk0 + s8;
        if (off + 2 > (size_t)512 * KTOT) off = 0;   // pad region: X=0 anyway
        CPA8(sptr(Ws + row * 36 + s8), Wf + off);
    }
}

__global__ __launch_bounds__(256, 2) void fc1B_k(const float* __restrict__ Wf) {
    int ntile = blockIdx.x, ks = blockIdx.y;
    int nb = ntile * 64;
    int k0 = ks * KSP, k20 = ks * KSP2;
    extern __shared__ uint32_t dyn[];

    int t = threadIdx.x;
    int wid = t >> 5, lane = t & 31;
    int gid = lane >> 2, tig = lane & 3;
    int mwarp = wid & 3, nwarp = wid >> 2;
    int m0 = mwarp * 32, n0 = nwarp * 32;

    float acc[2][4][4] = {};

    fc1_fill(Wf, dyn,            nb, k0,      k20,      t); CPCOMMIT();
    fc1_fill(Wf, dyn + F1_STW,   nb, k0 + 32, k20 + 16, t); CPCOMMIT();

    for (int ch = 0; ch < NCHUNK; ch++) {
        if (ch + 2 < NCHUNK)
            fc1_fill(Wf, dyn + ((ch + 2) % 3) * F1_STW, nb,
                     k0 + (ch + 2) * 32, k20 + (ch + 2) * 16, t);
        CPCOMMIT();
        CPWAIT2();
        __syncthreads();

        const uint32_t* Xs = dyn + (ch % 3) * F1_STW;
        const float*    Ws = (const float*)(Xs + F1_XSW);
#pragma unroll
        for (int g16 = 0; g16 < 2; g16++) {
            int wb = g16 * 8;
            uint32_t a[2][4];
#pragma unroll
            for (int mi = 0; mi < 2; mi++) {
                int rb = (m0 + mi * 16 + gid) * 20 + wb;
                a[mi][0] = Xs[rb + tig];
                a[mi][1] = Xs[rb + 160 + tig];
                a[mi][2] = Xs[rb + tig + 4];
                a[mi][3] = Xs[rb + 160 + tig + 4];
            }
#pragma unroll
            for (int nj = 0; nj < 4; nj++) {
                const float* wr = Ws + (n0 + nj * 8 + gid) * 36 + g16 * 16;
                float2 lo = *(const float2*)(wr + 2 * tig);
                float2 hi = *(const float2*)(wr + 2 * tig + 8);
                uint32_t b0 = cvt_bf2(lo.x, lo.y);
                uint32_t b1 = cvt_bf2(hi.x, hi.y);
#pragma unroll
                for (int mi = 0; mi < 2; mi++)
                    mma_bf16(acc[mi][nj], a[mi][0], a[mi][1], a[mi][2], a[mi][3], b0, b1);
            }
        }
        __syncthreads();
    }

    float* pp = g_part + (size_t)ks * 65536;
#pragma unroll
    for (int mi = 0; mi < 2; mi++) {
        int m = m0 + mi * 16;
#pragma unroll
        for (int nj = 0; nj < 4; nj++) {
            int col = nb + n0 + nj * 8 + 2 * tig;
            *(float2*)&pp[(size_t)(m + gid    ) * 512 + col] =
                make_float2(acc[mi][nj][0], acc[mi][nj][1]);
            *(float2*)&pp[(size_t)(m + gid + 8) * 512 + col] =
                make_float2(acc[mi][nj][2], acc[mi][nj][3]);
        }
    }
}

__global__ void fc1red_k(const float* __restrict__ bias) {
    int i = blockIdx.x * 256 + threadIdx.x;
    float a = 0.f;
#pragma unroll
    for (int ks = 0; ks < KSPLIT; ks++) a += g_part[(size_t)ks * 65536 + i];
    g_fc1[i] = leaky(a + bias[i & 511]);
}

// ============================================================================
// l1 / r1 (FFMA2, small)
// ============================================================================
__global__ __launch_bounds__(256, 2) void l1r1_k(const float* __restrict__ wl1,
                                                 const float* __restrict__ bl1,
                                                 const float* __restrict__ wr1,
                                                 const float* __restrict__ br1) {
    int side = blockIdx.x, ntile = blockIdx.y;
    int nb = ntile * 128;
    const float* Wp = side ? wr1 : wl1;
    const float* Bp = side ? br1 : bl1;
    __shared__ __align__(16) float Xs[16][132];
    __shared__ __align__(16) float Ws[16][132];
    int t = threadIdx.x, tn = t & 15, tb = t >> 4, b0 = tb * 8, n0 = tn * 8;
    ull acc[8][4] = {};

    for (int kk0 = 0; kk0 < 512; kk0 += 16) {
        for (int i = t; i < 2048; i += 256) {
            int k = i & 15, row = i >> 4;
            Xs[k][row] = g_fc1[(size_t)row * 512 + kk0 + k];
            Ws[k][row] = Wp[(size_t)(nb + row) * 512 + kk0 + k];
        }
        __syncthreads();
#pragma unroll 4
        for (int kk = 0; kk < 16; kk++) {
            float4 xa = *(const float4*)&Xs[kk][b0];
            float4 xb = *(const float4*)&Xs[kk][b0 + 4];
            float4 wa = *(const float4*)&Ws[kk][n0];
            float4 wb = *(const float4*)&Ws[kk][n0 + 4];
            ull xd[8] = {fpack(xa.x, xa.x), fpack(xa.y, xa.y),
                         fpack(xa.z, xa.z), fpack(xa.w, xa.w),
                         fpack(xb.x, xb.x), fpack(xb.y, xb.y),
                         fpack(xb.z, xb.z), fpack(xb.w, xb.w)};
            ull w2[4] = {fpack(wa.x, wa.y), fpack(wa.z, wa.w),
                         fpack(wb.x, wb.y), fpack(wb.z, wb.w)};
#pragma unroll
            for (int i = 0; i < 8; i++)
#pragma unroll
                for (int j = 0; j < 4; j++)
                    fma2(acc[i][j], w2[j], xd[i]);
        }
        __syncthreads();
    }

#pragma unroll
    for (int i = 0; i < 8; i++)
#pragma unroll
        for (int j = 0; j < 4; j++) {
            float lo, hi; funpack(acc[i][j], lo, hi);
            int n = nb + n0 + 2 * j;
            float* p = &g_h[(size_t)side * (B_ * 256) + (size_t)(b0 + i) * 256 + n];
            p[0] = leaky(lo + Bp[n]);
            p[1] = leaky(hi + Bp[n + 1]);
        }
}

// ============================================================================
// heads + quat distance + mean
// ============================================================================
__global__ void heads2_k(const float* __restrict__ wl2, const float* __restrict__ bl2,
                         const float* __restrict__ wr2, const float* __restrict__ br2,
                         const float* __restrict__ lt,  const float* __restrict__ rt) {
    int b = blockIdx.x, t = threadIdx.x;
    __shared__ float hl[256], hr[256], q[8];
    hl[t] = g_h[(size_t)b * 256 + t];
    hr[t] = g_h[(size_t)(B_ * 256) + (size_t)b * 256 + t];
    __syncthreads();

    int wrp = t >> 5, lane = t & 31;
    const float* w   = (wrp < 4) ? wl2 : wr2;
    const float* src = (wrp < 4) ? hl : hr;
    int i = wrp & 3;
    float s = 0.f;
    for (int j = lane; j < 256; j += 32) s += w[i * 256 + j] * src[j];
#pragma unroll
    for (int off = 16; off > 0; off >>= 1) s += __shfl_down_sync(0xffffffffu, s, off);
    if (lane == 0) q[wrp] = s + ((wrp < 4) ? bl2[i] : br2[i]);
    __syncthreads();

    if (t == 0) {
#pragma unroll
        for (int side = 0; side < 2; side++) {
            float qw = q[side * 4 + 0], qx = q[side * 4 + 1];
            float qy = q[side * 4 + 2], qz = q[side * 4 + 3];
            float nn = sqrtf(qw * qw + qx * qx + qy * qy + qz * qz);
            nn = fmaxf(nn, 1e-12f);
            qw /= nn; qx /= nn; qy /= nn; qz /= nn;
            const float* tgt = (side == 0 ? lt : rt) + (size_t)b * 4;
            float rw = tgt[0], rx = -tgt[1], ry = -tgt[2], rz = -tgt[3];
            float tw = qw * rw - qx * rx - qy * ry - qz * rz;
            float tx = qw * rx + qx * rw + qy * rz - qz * ry;
            float ty = qw * ry - qx * rz + qy * rw + qz * rx;
            float tz = qw * rz + qx * ry - qy * rx + qz * rw;
            float ang = 2.f * atan2f(sqrtf(tx * tx + ty * ty + tz * tz + 1e-12f), fabsf(tw));
            g_ang[side * B_ + b] = ang;
        }
    }
}

__global__ void mean_k(float* __restrict__ out) {
    __shared__ float sl[128], sr[128];
    int t = threadIdx.x;
    sl[t] = g_ang[t];
    sr[t] = g_ang[128 + t];
    __syncthreads();
    for (int s = 64; s > 0; s >>= 1) {
        if (t < s) { sl[t] += sl[t + s]; sr[t] += sr[t + s]; }
        __syncthreads();
    }
    if (t == 0) { out[0] = sl[0] * (1.f / 128.f); out[1] = sr[0] * (1.f / 128.f); }
}

// ============================================================================
extern "C" void kernel_launch(void* const* d_in, const int* in_sizes, int n_in,
                              void* d_out, int out_size) {
    (void)in_sizes; (void)n_in; (void)out_size;
    const float* left  = (const float*)d_in[0];
    const float* right = (const float*)d_in[1];
    const float* lt    = (const float*)d_in[2];
    const float* rt    = (const float*)d_in[3];
    const float* w6[5] = {(const float*)d_in[4],  (const float*)d_in[6],
                          (const float*)d_in[8],  (const float*)d_in[10],
                          (const float*)d_in[12]};
    const float* b6[5] = {(const float*)d_in[5],  (const float*)d_in[7],
                          (const float*)d_in[9],  (const float*)d_in[11],
                          (const float*)d_in[13]};
    const float* wfc1 = (const float*)d_in[14];
    const float* bfc1 = (const float*)d_in[15];
    const float* wl1  = (const float*)d_in[16];
    const float* bl1  = (const float*)d_in[17];
    const float* wr1  = (const float*)d_in[18];
    const float* br1  = (const float*)d_in[19];
    const float* wl2  = (const float*)d_in[20];
    const float* bl2  = (const float*)d_in[21];
    const float* wr2  = (const float*)d_in[22];
    const float* br2  = (const float*)d_in[23];
    float* out = (float*)d_out;

    static bool attr_done = false;
    if (!attr_done) {
        cudaFuncSetAttribute(convB64_k, cudaFuncAttributeMaxDynamicSharedMemorySize,
                             2 * STG_W * 4);
        cudaFuncSetAttribute(fc1B_k, cudaFuncAttributeMaxDynamicSharedMemorySize,
                             3 * F1_STW * 4);
        attr_done = true;
    }

    const int INO[5]   = {448, 320, 192, 96, 32};
    const int OUTO[5]  = {320, 192, 96, 32, 0};
    const int OCL[5]   = {128, 128, 96, 64, 32};
    const int OCT64[5] = {2, 2, 2, 1, 1};
    const int CHK[5]   = {6, 14, 22, 28, 32};
    const int WBASE[5] = {0, 24, 80, 146, 202};

    wprep_all<<<234, 256>>>(w6[0], w6[1], w6[2], w6[3], w6[4]);
    corr_k<<<B_, 576>>>(left, right);

    for (int l = 0; l < 5; l++)
        convB64_k<<<dim3(B_, OCT64[l]), 256, 2 * STG_W * 4>>>(
            b6[l], CHK[l], WBASE[l], INO[l] >> 4, OUTO[l], OCL[l]);

    fc1B_k<<<dim3(8, KSPLIT), 256, 3 * F1_STW * 4>>>(wfc1);
    fc1red_k<<<256, 256>>>(bfc1);
    l1r1_k<<<dim3(2, 2), 256>>>(wl1, bl1, wr1, br1);
    heads2_k<<<B_, 256>>>(wl2, bl2, wr2, br2, lt, rt);
    mean_k<<<1, 128>>>(out);
}